// round 2
// baseline (speedup 1.0000x reference)
#include <cuda_runtime.h>
#include <cuda_bf16.h>
#include <math.h>

// Problem constants
#define BB    2
#define NN    1024
#define DD    512
#define HH    8
#define DH    64
#define KKB   4
#define VV    32000
#define INNER 1536
#define CKW   3
#define MROWS (BB*NN)     // 2048
#define BHN   (BB*HH)     // 16
#define TOTAL_PASSES 8    // H_CYCLES*L_CYCLES*K = 2*1*4

// ---------------- scratch (static device memory; no allocs allowed) -------
__device__ float g_X   [MROWS*DD];
__device__ float g_Q   [MROWS*DD];
__device__ float g_Hc  [MROWS*DD];
__device__ float g_PhiQ[MROWS*DD];
__device__ float g_PhiK[MROWS*DD];
__device__ float g_Vp  [MROWS*DD];
__device__ float g_Wm  [(size_t)BHN*NN*NN];   // 64 MB attention weights
__device__ float g_wsum[BHN*NN];
__device__ float g_mbuf[MROWS*DD];
__device__ float g_Qi  [MROWS*DD];
__device__ float g_Qn2 [MROWS*DD];
__device__ float g_GU  [(size_t)MROWS*2*INNER];
__device__ float g_Hf  [(size_t)MROWS*INNER];
__device__ float g_Hcv [(size_t)MROWS*INNER];
__device__ float g_Qn  [MROWS*DD];

// ---------------- helpers -------------------------------------------------
__device__ __forceinline__ float siluf(float x) { return x / (1.0f + expf(-x)); }

// Robust read of a "bool" array whose storage dtype is unknown
// (uint8 vs int32 vs float32). For an int32/float32 element holding 0/1,
// byte 1 of the buffer is always 0; for uint8 storage of [1,1] it is 1.
__device__ __forceinline__ bool read_halted(const void* p, int b)
{
    const unsigned char* u8 = (const unsigned char*)p;
    if (u8[1] != 0) {                  // must be 1-byte storage
        return u8[b] != 0;
    }
    // 4-byte storage (int32, or float32 whose bit pattern is nonzero iff != 0)
    return ((const int*)p)[b] != 0;
}

// ---------------- init: Q reset + embed + input LN ------------------------
__global__ void init_kernel(const int* __restrict__ inputs,
                            const int* __restrict__ carry_inputs,
                            const void* __restrict__ halted,
                            const float* __restrict__ carry_hidden,
                            const float* __restrict__ init_hidden,
                            const float* __restrict__ emb,
                            const float* __restrict__ pos,
                            const float* __restrict__ in_s,
                            const float* __restrict__ in_b)
{
    int r = blockIdx.x;           // b*NN + n
    int b = r / NN, n = r % NN;
    int t = threadIdx.x;          // 256 threads, 2 elems each
    bool h = read_halted(halted, b);
    int idx = h ? inputs[r] : carry_inputs[r];
    const float* e = emb + (size_t)idx * DD;
    const float* p = pos + (size_t)n * DD;

    float x0 = e[t]       + p[t];
    float x1 = e[t + 256] + p[t + 256];

    size_t base = (size_t)r * DD;
    float q0 = h ? init_hidden[t]       : carry_hidden[base + t];
    float q1 = h ? init_hidden[t + 256] : carry_hidden[base + t + 256];
    g_Q[base + t]       = q0;
    g_Q[base + t + 256] = q1;

    __shared__ float s_sum[256], s_sq[256];
    s_sum[t] = x0 + x1;
    s_sq[t]  = x0 * x0 + x1 * x1;
    __syncthreads();
    for (int o = 128; o > 0; o >>= 1) {
        if (t < o) { s_sum[t] += s_sum[t + o]; s_sq[t] += s_sq[t + o]; }
        __syncthreads();
    }
    float mu   = s_sum[0] * (1.0f / DD);
    float var  = s_sq[0] * (1.0f / DD) - mu * mu;
    float rstd = rsqrtf(var + 1e-5f);
    g_X[base + t]       = (x0 - mu) * rstd * in_s[t]       + in_b[t];
    g_X[base + t + 256] = (x1 - mu) * rstd * in_s[t + 256] + in_b[t + 256];
}

// ---------------- generic per-row LayerNorm (D=512) -----------------------
// out = LN(in)*s + b  (+ add if add != nullptr)
__global__ void ln_kernel(const float* __restrict__ in, float* __restrict__ out,
                          const float* __restrict__ s, const float* __restrict__ bia,
                          const float* __restrict__ add)
{
    int r = blockIdx.x;
    int t = threadIdx.x;
    size_t base = (size_t)r * DD;
    float x0 = in[base + t];
    float x1 = in[base + t + 256];

    __shared__ float s_sum[256], s_sq[256];
    s_sum[t] = x0 + x1;
    s_sq[t]  = x0 * x0 + x1 * x1;
    __syncthreads();
    for (int o = 128; o > 0; o >>= 1) {
        if (t < o) { s_sum[t] += s_sum[t + o]; s_sq[t] += s_sq[t + o]; }
        __syncthreads();
    }
    float mu   = s_sum[0] * (1.0f / DD);
    float var  = s_sq[0] * (1.0f / DD) - mu * mu;
    float rstd = rsqrtf(var + 1e-5f);
    float v0 = (x0 - mu) * rstd * s[t]       + bia[t];
    float v1 = (x1 - mu) * rstd * s[t + 256] + bia[t + 256];
    if (add) { v0 += add[base + t]; v1 += add[base + t + 256]; }
    out[base + t]       = v0;
    out[base + t + 256] = v1;
}

// ---------------- generic tiled SGEMM (row-major NN) ----------------------
// C[M,Nc] = A[M,Kd] @ B[Kd,Nc]; epilogues:
//   EPI 0: none
//   EPI 1: elu(x)+1
//   EPI 2: C = addP + softplus(dtP[kIdx]) * acc
//   EPI 3: C = addP + acc
template <int EPI>
__global__ void gemm_nn(const float* __restrict__ A, const float* __restrict__ Bm,
                        float* __restrict__ C, int M, int Nc, int Kd,
                        const float* __restrict__ addP,
                        const float* __restrict__ dtP, int kIdx)
{
    __shared__ __align__(16) float As[16][68];
    __shared__ __align__(16) float Bs[16][64];
    int m0 = blockIdx.y * 64;
    int n0 = blockIdx.x * 64;
    int tid = threadIdx.x;
    int tx = tid & 15, ty = tid >> 4;
    float acc[4][4] = {};

    for (int k0 = 0; k0 < Kd; k0 += 16) {
        #pragma unroll
        for (int tt = 0; tt < 4; tt++) {
            int e = tid + 256 * tt;
            int rr = e >> 4, kk = e & 15;
            As[kk][rr] = A[(size_t)(m0 + rr) * Kd + k0 + kk];
        }
        #pragma unroll
        for (int tt = 0; tt < 4; tt++) {
            int e = tid + 256 * tt;
            int kk = e >> 6, cc = e & 63;
            Bs[kk][cc] = Bm[(size_t)(k0 + kk) * Nc + n0 + cc];
        }
        __syncthreads();
        #pragma unroll
        for (int kk = 0; kk < 16; kk++) {
            float4 av = *(const float4*)&As[kk][ty * 4];
            float4 bv = *(const float4*)&Bs[kk][tx * 4];
            float a[4] = {av.x, av.y, av.z, av.w};
            float bb[4] = {bv.x, bv.y, bv.z, bv.w};
            #pragma unroll
            for (int i = 0; i < 4; i++)
                #pragma unroll
                for (int j = 0; j < 4; j++)
                    acc[i][j] += a[i] * bb[j];
        }
        __syncthreads();
    }

    float alpha = 1.0f;
    if (EPI == 2) {
        float d = dtP[kIdx];
        alpha = (d > 20.0f) ? d : log1pf(expf(d));
    }
    #pragma unroll
    for (int i = 0; i < 4; i++) {
        int m = m0 + ty * 4 + i;
        #pragma unroll
        for (int j = 0; j < 4; j++) {
            int n = n0 + tx * 4 + j;
            size_t idx = (size_t)m * Nc + n;
            float v = acc[i][j];
            if (EPI == 1)      v = (v > 0.0f) ? (v + 1.0f) : expf(v);
            else if (EPI == 2) v = addP[idx] + alpha * v;
            else if (EPI == 3) v = addP[idx] + v;
            C[idx] = v;
        }
    }
}

// ---------------- LM head: C[M,Nc] = A[M,Kd] @ Bt[Nc,Kd]^T -----------------
__global__ void gemm_nt(const float* __restrict__ A, const float* __restrict__ Bt,
                        float* __restrict__ C, int M, int Nc, int Kd)
{
    __shared__ __align__(16) float As[16][68];
    __shared__ __align__(16) float Bs[16][68];
    int m0 = blockIdx.y * 64;
    int n0 = blockIdx.x * 64;
    int tid = threadIdx.x;
    int tx = tid & 15, ty = tid >> 4;
    float acc[4][4] = {};

    for (int k0 = 0; k0 < Kd; k0 += 16) {
        #pragma unroll
        for (int tt = 0; tt < 4; tt++) {
            int e = tid + 256 * tt;
            int rr = e >> 4, kk = e & 15;
            As[kk][rr] = A[(size_t)(m0 + rr) * Kd + k0 + kk];
        }
        #pragma unroll
        for (int tt = 0; tt < 4; tt++) {
            int e = tid + 256 * tt;
            int cc = e >> 4, kk = e & 15;
            Bs[kk][cc] = Bt[(size_t)(n0 + cc) * Kd + k0 + kk];
        }
        __syncthreads();
        #pragma unroll
        for (int kk = 0; kk < 16; kk++) {
            float4 av = *(const float4*)&As[kk][ty * 4];
            float4 bv = *(const float4*)&Bs[kk][tx * 4];
            float a[4] = {av.x, av.y, av.z, av.w};
            float bb[4] = {bv.x, bv.y, bv.z, bv.w};
            #pragma unroll
            for (int i = 0; i < 4; i++)
                #pragma unroll
                for (int j = 0; j < 4; j++)
                    acc[i][j] += a[i] * bb[j];
        }
        __syncthreads();
    }
    #pragma unroll
    for (int i = 0; i < 4; i++) {
        int m = m0 + ty * 4 + i;
        #pragma unroll
        for (int j = 0; j < 4; j++) {
            int n = n0 + tx * 4 + j;
            C[(size_t)m * Nc + n] = acc[i][j];
        }
    }
}

// ---------------- attention W = (PhiQ . PhiK)^2 (relu^2, K=64) ------------
__global__ void attn_qk(const float* __restrict__ PhiQ, const float* __restrict__ PhiK,
                        float* __restrict__ Wm)
{
    __shared__ __align__(16) float Qs[64][68];  // [d][row]
    __shared__ __align__(16) float Ks[64][68];  // [d][col]
    int bh = blockIdx.z;
    int b = bh / HH, h = bh % HH;
    int n0 = blockIdx.y * 64;
    int m0 = blockIdx.x * 64;
    int tid = threadIdx.x;
    int tx = tid & 15, ty = tid >> 4;

    #pragma unroll
    for (int tt = 0; tt < 16; tt++) {
        int e = tid + 256 * tt;
        int row = e >> 6, d = e & 63;
        Qs[d][row] = PhiQ[((size_t)(b * NN + n0 + row)) * DD + h * DH + d];
        Ks[d][row] = PhiK[((size_t)(b * NN + m0 + row)) * DD + h * DH + d];
    }
    __syncthreads();

    float acc[4][4] = {};
    #pragma unroll 8
    for (int kk = 0; kk < 64; kk++) {
        float4 av = *(const float4*)&Qs[kk][ty * 4];
        float4 bv = *(const float4*)&Ks[kk][tx * 4];
        float a[4] = {av.x, av.y, av.z, av.w};
        float bb[4] = {bv.x, bv.y, bv.z, bv.w};
        #pragma unroll
        for (int i = 0; i < 4; i++)
            #pragma unroll
            for (int j = 0; j < 4; j++)
                acc[i][j] += a[i] * bb[j];
    }
    #pragma unroll
    for (int i = 0; i < 4; i++) {
        int n = n0 + ty * 4 + i;
        #pragma unroll
        for (int j = 0; j < 4; j++) {
            int m = m0 + tx * 4 + j;
            float s = fmaxf(acc[i][j], 0.0f);
            Wm[((size_t)bh * NN + n) * NN + m] = s * s;
        }
    }
}

// ---------------- row sums of W -------------------------------------------
__global__ void rowsum_kernel(const float* __restrict__ Wm, float* __restrict__ ws)
{
    int r = blockIdx.x;             // bh*NN + n
    int t = threadIdx.x;
    const float* row = Wm + (size_t)r * NN;
    float s = 0.0f;
    for (int i = t; i < NN; i += 256) s += row[i];
    __shared__ float sh[256];
    sh[t] = s; __syncthreads();
    for (int o = 128; o > 0; o >>= 1) {
        if (t < o) sh[t] += sh[t + o];
        __syncthreads();
    }
    if (t == 0) ws[r] = sh[0];
}

// ---------------- Attr = W @ V; m = Attr/(wsum+1) - V ---------------------
__global__ void attn_wv(const float* __restrict__ Wm, const float* __restrict__ Vp,
                        const float* __restrict__ ws, float* __restrict__ mout)
{
    __shared__ __align__(16) float As[16][68];  // [k(m)][row(n)]
    __shared__ __align__(16) float Bs[16][64];  // [k(m)][d]
    int bh = blockIdx.y;
    int b = bh / HH, h = bh % HH;
    int n0 = blockIdx.x * 64;
    int tid = threadIdx.x;
    int tx = tid & 15, ty = tid >> 4;
    float acc[4][4] = {};

    for (int k0 = 0; k0 < NN; k0 += 16) {
        #pragma unroll
        for (int tt = 0; tt < 4; tt++) {
            int e = tid + 256 * tt;
            int rr = e >> 4, kk = e & 15;
            As[kk][rr] = Wm[((size_t)bh * NN + n0 + rr) * NN + k0 + kk];
        }
        {
            int kk = tid >> 6, cc = tid & 63;   // 256 threads cover 4 k rows
            #pragma unroll
            for (int tt = 0; tt < 4; tt++) {
                Bs[kk + 4 * tt][cc] =
                    Vp[((size_t)(b * NN + k0 + kk + 4 * tt)) * DD + h * DH + cc];
            }
        }
        __syncthreads();
        #pragma unroll
        for (int kk = 0; kk < 16; kk++) {
            float4 av = *(const float4*)&As[kk][ty * 4];
            float4 bv = *(const float4*)&Bs[kk][tx * 4];
            float a[4] = {av.x, av.y, av.z, av.w};
            float bb[4] = {bv.x, bv.y, bv.z, bv.w};
            #pragma unroll
            for (int i = 0; i < 4; i++)
                #pragma unroll
                for (int j = 0; j < 4; j++)
                    acc[i][j] += a[i] * bb[j];
        }
        __syncthreads();
    }

    #pragma unroll
    for (int i = 0; i < 4; i++) {
        int n = n0 + ty * 4 + i;
        float denom = ws[bh * NN + n] + 1.0f;
        float rden = 1.0f / denom;
        #pragma unroll
        for (int j = 0; j < 4; j++) {
            int d = tx * 4 + j;
            size_t idx = ((size_t)(b * NN + n)) * DD + h * DH + d;
            mout[idx] = acc[i][j] * rden - Vp[idx];
        }
    }
}

// ---------------- SwiGLU: Hf = silu(G)*U ----------------------------------
__global__ void swiglu_kernel(const float* __restrict__ GU, float* __restrict__ Hf)
{
    size_t i = (size_t)blockIdx.x * 256 + threadIdx.x;
    if (i >= (size_t)MROWS * INNER) return;
    size_t row = i / INNER;
    int c = (int)(i % INNER);
    float g = GU[row * (2 * INNER) + c];
    float u = GU[row * (2 * INNER) + INNER + c];
    Hf[i] = siluf(g) * u;
}

// ---------------- depthwise conv (k=3, pad 1, over n) + bias + silu -------
__global__ void conv_kernel(const float* __restrict__ Hf, const float* __restrict__ w,
                            const float* __restrict__ bias, float* __restrict__ out)
{
    size_t i = (size_t)blockIdx.x * 256 + threadIdx.x;
    if (i >= (size_t)MROWS * INNER) return;
    size_t row = i / INNER;
    int c = (int)(i % INNER);
    int n = (int)(row % NN);
    const float* wc = w + (size_t)c * CKW;   // [CK] taps (correlation, no flip)
    float acc = bias[c];
    if (n > 0)      acc += wc[0] * Hf[(row - 1) * INNER + c];
    acc += wc[1] * Hf[row * INNER + c];
    if (n < NN - 1) acc += wc[2] * Hf[(row + 1) * INNER + c];
    out[i] = siluf(acc);
}

// ---------------- halt head: q_logits = mean_n(Qn) @ halt_w^T + halt_b ----
__global__ void halt_kernel(const float* __restrict__ Qn, const float* __restrict__ hw,
                            const float* __restrict__ hb, float* __restrict__ out)
{
    int b = blockIdx.x;
    int t = threadIdx.x;   // 256
    __shared__ float md[DD];
    for (int d = t; d < DD; d += 256) {
        float s = 0.0f;
        for (int n = 0; n < NN; n++)
            s += Qn[((size_t)(b * NN + n)) * DD + d];
        md[d] = s * (1.0f / NN);
    }
    __syncthreads();
    __shared__ float r0[256], r1[256];
    float p0 = 0.0f, p1 = 0.0f;
    for (int d = t; d < DD; d += 256) {
        p0 += md[d] * hw[d];
        p1 += md[d] * hw[DD + d];
    }
    r0[t] = p0; r1[t] = p1;
    __syncthreads();
    for (int o = 128; o > 0; o >>= 1) {
        if (t < o) { r0[t] += r0[t + o]; r1[t] += r1[t + o]; }
        __syncthreads();
    }
    if (t == 0) {
        out[b * 2 + 0] = r0[0] + hb[0];
        out[b * 2 + 1] = r1[0] + hb[1];
    }
}

// ---------------- host orchestration --------------------------------------
extern "C" void kernel_launch(void* const* d_in, const int* in_sizes, int n_in,
                              void* d_out, int out_size)
{
    const int*   inputs       = (const int*)d_in[0];
    // d_in[1] labels: unused
    const float* carry_hidden = (const float*)d_in[2];
    // d_in[3] carry_steps: unused
    const void*  halted       = d_in[4];   // bool; storage dtype unknown
    const int*   carry_inputs = (const int*)d_in[5];
    // d_in[6] carry_labels: unused
    const float* init_hidden  = (const float*)d_in[7];
    const float* emb          = (const float*)d_in[8];
    const float* pos          = (const float*)d_in[9];
    const float* in_s         = (const float*)d_in[10];
    const float* in_b         = (const float*)d_in[11];
    const float* fin_s        = (const float*)d_in[12];
    const float* fin_b        = (const float*)d_in[13];
    const float* lm_w         = (const float*)d_in[14];
    const float* halt_w       = (const float*)d_in[15];
    const float* halt_b       = (const float*)d_in[16];
    const float* dt           = (const float*)d_in[17];
    const float* W_Q          = (const float*)d_in[18];
    const float* W_K          = (const float*)d_in[19];
    const float* W_V          = (const float*)d_in[20];
    const float* W_O          = (const float*)d_in[21];
    const float* W_up         = (const float*)d_in[22];
    const float* dw_w         = (const float*)d_in[23];
    const float* dw_b         = (const float*)d_in[24];
    const float* W_down       = (const float*)d_in[25];
    const float* n1_s         = (const float*)d_in[26];
    const float* n1_b         = (const float*)d_in[27];
    const float* n2_s         = (const float*)d_in[28];
    const float* n2_b         = (const float*)d_in[29];

    float *X, *Q, *Hc, *PhiQ, *PhiK, *Vp, *Wm, *ws, *mb, *Qi, *Qn2, *GU, *Hf, *Hcv, *Qn;
    cudaGetSymbolAddress((void**)&X,    g_X);
    cudaGetSymbolAddress((void**)&Q,    g_Q);
    cudaGetSymbolAddress((void**)&Hc,   g_Hc);
    cudaGetSymbolAddress((void**)&PhiQ, g_PhiQ);
    cudaGetSymbolAddress((void**)&PhiK, g_PhiK);
    cudaGetSymbolAddress((void**)&Vp,   g_Vp);
    cudaGetSymbolAddress((void**)&Wm,   g_Wm);
    cudaGetSymbolAddress((void**)&ws,   g_wsum);
    cudaGetSymbolAddress((void**)&mb,   g_mbuf);
    cudaGetSymbolAddress((void**)&Qi,   g_Qi);
    cudaGetSymbolAddress((void**)&Qn2,  g_Qn2);
    cudaGetSymbolAddress((void**)&GU,   g_GU);
    cudaGetSymbolAddress((void**)&Hf,   g_Hf);
    cudaGetSymbolAddress((void**)&Hcv,  g_Hcv);
    cudaGetSymbolAddress((void**)&Qn,   g_Qn);

    float* out = (float*)d_out;

    init_kernel<<<MROWS, 256>>>(inputs, carry_inputs, halted, carry_hidden,
                                init_hidden, emb, pos, in_s, in_b);

    dim3 gD(DD / 64, MROWS / 64);             // (8, 32)
    dim3 gUP(2 * INNER / 64, MROWS / 64);     // (48, 32)
    dim3 gQK(NN / 64, NN / 64, BHN);          // (16, 16, 16)
    dim3 gWV(NN / 64, BHN);                   // (16, 16)

    for (int it = 0; it < TOTAL_PASSES; it++) {
        int k = it % KKB;
        size_t woff = (size_t)k * DD * DD;

        // Hc = LN(Q; n1) + X
        ln_kernel<<<MROWS, 256>>>(Q, Hc, n1_s + k * DD, n1_b + k * DD, X);

        // head projections
        gemm_nn<1><<<gD, 256>>>(Hc, W_Q + woff, PhiQ, MROWS, DD, DD, nullptr, nullptr, 0);
        gemm_nn<1><<<gD, 256>>>(Hc, W_K + woff, PhiK, MROWS, DD, DD, nullptr, nullptr, 0);
        gemm_nn<0><<<gD, 256>>>(Hc, W_V + woff, Vp,   MROWS, DD, DD, nullptr, nullptr, 0);

        // attention
        attn_qk<<<gQK, 256>>>(PhiQ, PhiK, Wm);
        rowsum_kernel<<<BHN * NN, 256>>>(Wm, ws);
        attn_wv<<<gWV, 256>>>(Wm, Vp, ws, mb);

        // Qi = Q + softplus(dt[k]) * (m @ Wo)
        gemm_nn<2><<<gD, 256>>>(mb, W_O + woff, Qi, MROWS, DD, DD, Q, dt, k);

        // FFN
        ln_kernel<<<MROWS, 256>>>(Qi, Qn2, n2_s + k * DD, n2_b + k * DD, nullptr);
        gemm_nn<0><<<gUP, 256>>>(Qn2, W_up + (size_t)k * DD * 2 * INNER, GU,
                                 MROWS, 2 * INNER, DD, nullptr, nullptr, 0);
        int tot = MROWS * INNER;
        swiglu_kernel<<<(tot + 255) / 256, 256>>>(GU, Hf);
        conv_kernel<<<(tot + 255) / 256, 256>>>(Hf, dw_w + (size_t)k * INNER * CKW,
                                                dw_b + (size_t)k * INNER, Hcv);
        // Q = Qi + Hcv @ W_down
        gemm_nn<3><<<gD, 256>>>(Hcv, W_down + (size_t)k * INNER * DD, Q,
                                MROWS, DD, INNER, Qi, nullptr, 0);
    }

    // final LN + LM head + halt head
    ln_kernel<<<MROWS, 256>>>(Q, Qn, fin_s, fin_b, nullptr);
    dim3 gLM(VV / 64, MROWS / 64);            // (500, 32)
    gemm_nt<<<gLM, 256>>>(Qn, lm_w, out, MROWS, VV, DD);
    halt_kernel<<<BB, 256>>>(Qn, halt_w, halt_b, out + (size_t)MROWS * VV);
}

// round 5
// speedup vs baseline: 1.1158x; 1.1158x over previous
#include <cuda_runtime.h>
#include <cuda_bf16.h>
#include <math.h>
#include <stdint.h>

// Problem constants
#define BB    2
#define NN    1024
#define DD    512
#define HH    8
#define DH    64
#define KKB   4
#define VV    32000
#define INNER 1536
#define CKW   3
#define MROWS (BB*NN)     // 2048
#define BHN   (BB*HH)     // 16
#define TOTAL_PASSES 8    // H_CYCLES*L_CYCLES*K

// ---------------- scratch (static device memory; no allocs allowed) -------
__device__ float g_X   [MROWS*DD];
__device__ float g_Q   [MROWS*DD];
__device__ float g_Hc  [MROWS*DD];
__device__ float g_PhiQ[MROWS*DD];
__device__ float g_PhiK[MROWS*DD];
__device__ float g_Vp  [MROWS*DD];
__device__ float g_Wm  [(size_t)BHN*NN*NN];   // 64 MB attention weights
__device__ float g_wsum[BHN*NN];
__device__ float g_mbuf[MROWS*DD];
__device__ float g_Qi  [MROWS*DD];
__device__ float g_Qn2 [MROWS*DD];
__device__ float g_GU  [(size_t)MROWS*2*INNER];
__device__ float g_Hf  [(size_t)MROWS*INNER];
__device__ float g_Hcv [(size_t)MROWS*INNER];
__device__ float g_Qn  [MROWS*DD];

// ---------------- helpers -------------------------------------------------
__device__ __forceinline__ float siluf(float x) { return x / (1.0f + expf(-x)); }

__device__ __forceinline__ bool read_halted(const void* p, int b)
{
    const unsigned char* u8 = (const unsigned char*)p;
    if (u8[1] != 0) return u8[b] != 0;           // 1-byte storage
    return ((const int*)p)[b] != 0;              // 4-byte storage
}

__device__ __forceinline__ uint32_t smem_u32(const void* p) {
    uint32_t a;
    asm("{ .reg .u64 t; cvta.to.shared.u64 t, %1; cvt.u32.u64 %0, t; }"
        : "=r"(a) : "l"(p));
    return a;
}

// ---------------- mma.sync helpers (family-portable tensor core path) -----
__device__ __forceinline__ void ldm4(uint32_t* r, uint32_t a) {
    asm volatile("ldmatrix.sync.aligned.m8n8.x4.shared.b16 {%0,%1,%2,%3}, [%4];"
                 : "=r"(r[0]), "=r"(r[1]), "=r"(r[2]), "=r"(r[3]) : "r"(a));
}
__device__ __forceinline__ void mma_bf16(float* c, const uint32_t* a, const uint32_t* b) {
    asm volatile("mma.sync.aligned.m16n8k16.row.col.f32.bf16.bf16.f32 "
                 "{%0,%1,%2,%3}, {%4,%5,%6,%7}, {%8,%9}, {%0,%1,%2,%3};"
                 : "+f"(c[0]), "+f"(c[1]), "+f"(c[2]), "+f"(c[3])
                 : "r"(a[0]), "r"(a[1]), "r"(a[2]), "r"(a[3]),
                   "r"(b[0]), "r"(b[1]));
}
// split 8 fp32 into hi/lo bf16 packs (error-compensated bf16x3 scheme)
__device__ __forceinline__ void split8(float4 v0, float4 v1, uint4& h, uint4& l) {
    float f[8] = {v0.x, v0.y, v0.z, v0.w, v1.x, v1.y, v1.z, v1.w};
    uint32_t hh[8], ll[8];
    #pragma unroll
    for (int q = 0; q < 8; q++) {
        __nv_bfloat16 bh = __float2bfloat16(f[q]);
        __nv_bfloat16 bl = __float2bfloat16(f[q] - __bfloat162float(bh));
        hh[q] = __bfloat16_as_ushort(bh);
        ll[q] = __bfloat16_as_ushort(bl);
    }
    h = make_uint4(hh[0] | (hh[1] << 16), hh[2] | (hh[3] << 16),
                   hh[4] | (hh[5] << 16), hh[6] | (hh[7] << 16));
    l = make_uint4(ll[0] | (ll[1] << 16), ll[2] | (ll[3] << 16),
                   ll[4] | (ll[5] << 16), ll[6] | (ll[7] << 16));
}

// ---------------- LM head: mma.sync bf16x3, C = A @ Bw^T -------------------
// A: [MROWS, DD] fp32, Bw: [VV, DD] fp32 (both K-major), C: [MROWS, VV]
#define LMS 40   // smem row stride in bf16 (32 data + 8 pad)
__global__ void __launch_bounds__(256)
lm_head_mma(const float* __restrict__ A, const float* __restrict__ Bw,
            float* __restrict__ C)
{
    __shared__ __align__(16) __nv_bfloat16 sAh[128 * LMS];
    __shared__ __align__(16) __nv_bfloat16 sAl[128 * LMS];
    __shared__ __align__(16) __nv_bfloat16 sBh[128 * LMS];
    __shared__ __align__(16) __nv_bfloat16 sBl[128 * LMS];

    const int tid  = threadIdx.x;
    const int lane = tid & 31, wid = tid >> 5;
    const int warp_m = wid >> 1, warp_n = wid & 1;   // 4x2 warps, 32x64 tiles
    const int m0 = blockIdx.y * 128, n0 = blockIdx.x * 128;

    const uint32_t uAh = smem_u32(sAh), uAl = smem_u32(sAl);
    const uint32_t uBh = smem_u32(sBh), uBl = smem_u32(sBl);

    float acc[2][8][4];
    #pragma unroll
    for (int i = 0; i < 2; i++)
        #pragma unroll
        for (int j = 0; j < 8; j++)
            #pragma unroll
            for (int q = 0; q < 4; q++) acc[i][j][q] = 0.0f;

    for (int kc = 0; kc < 16; kc++) {          // 16 chunks of K=32
        // ---- stage: gmem fp32 -> smem bf16 hi/lo ----
        #pragma unroll
        for (int it = 0; it < 2; it++) {
            int g = tid + 256 * it;            // 0..511 groups of 8 floats
            int row = g >> 2;
            int c8  = (g & 3) * 8;
            const float* pa = A  + (size_t)(m0 + row) * DD + kc * 32 + c8;
            const float* pb = Bw + (size_t)(n0 + row) * DD + kc * 32 + c8;
            uint4 h, l;
            split8(*(const float4*)pa, *(const float4*)(pa + 4), h, l);
            *(uint4*)(sAh + row * LMS + c8) = h;
            *(uint4*)(sAl + row * LMS + c8) = l;
            split8(*(const float4*)pb, *(const float4*)(pb + 4), h, l);
            *(uint4*)(sBh + row * LMS + c8) = h;
            *(uint4*)(sBl + row * LMS + c8) = l;
        }
        __syncthreads();

        // ---- 2 k-steps of 16 ----
        #pragma unroll
        for (int s = 0; s < 2; s++) {
            uint32_t ah[2][4], al[2][4], bh[8][2], bl[8][2];
            // A fragments (m16k16 each)
            #pragma unroll
            for (int i = 0; i < 2; i++) {
                int r  = warp_m * 32 + i * 16 + (lane & 15);
                int kb = s * 16 + ((lane >> 4) << 3);
                uint32_t off = (uint32_t)(r * LMS + kb) * 2;
                ldm4(ah[i], uAh + off);
                ldm4(al[i], uAl + off);
            }
            // B fragments (n8k16 pairs via x4)
            #pragma unroll
            for (int j = 0; j < 4; j++) {
                int r  = warp_n * 64 + j * 16 + (lane & 7) + ((lane >> 4) << 3);
                int kb = s * 16 + (((lane >> 3) & 1) << 3);
                uint32_t off = (uint32_t)(r * LMS + kb) * 2;
                uint32_t q[4];
                ldm4(q, uBh + off);
                bh[2*j][0] = q[0]; bh[2*j][1] = q[1];
                bh[2*j+1][0] = q[2]; bh[2*j+1][1] = q[3];
                ldm4(q, uBl + off);
                bl[2*j][0] = q[0]; bl[2*j][1] = q[1];
                bl[2*j+1][0] = q[2]; bl[2*j+1][1] = q[3];
            }
            #pragma unroll
            for (int i = 0; i < 2; i++)
                #pragma unroll
                for (int j = 0; j < 8; j++) {
                    mma_bf16(acc[i][j], ah[i], bh[j]);
                    mma_bf16(acc[i][j], al[i], bh[j]);
                    mma_bf16(acc[i][j], ah[i], bl[j]);
                }
        }
        __syncthreads();
    }

    // ---- epilogue: fragment -> gmem ----
    #pragma unroll
    for (int i = 0; i < 2; i++) {
        int m = m0 + warp_m * 32 + i * 16 + (lane >> 2);
        #pragma unroll
        for (int j = 0; j < 8; j++) {
            int n = n0 + warp_n * 64 + j * 8 + (lane & 3) * 2;
            *(float2*)(C + (size_t)m * VV + n) =
                make_float2(acc[i][j][0], acc[i][j][1]);
            *(float2*)(C + (size_t)(m + 8) * VV + n) =
                make_float2(acc[i][j][2], acc[i][j][3]);
        }
    }
}

// ---------------- init: Q reset + embed + input LN ------------------------
__global__ void init_kernel(const int* __restrict__ inputs,
                            const int* __restrict__ carry_inputs,
                            const void* __restrict__ halted,
                            const float* __restrict__ carry_hidden,
                            const float* __restrict__ init_hidden,
                            const float* __restrict__ emb,
                            const float* __restrict__ pos,
                            const float* __restrict__ in_s,
                            const float* __restrict__ in_b)
{
    int r = blockIdx.x;
    int b = r / NN, n = r % NN;
    int t = threadIdx.x;
    bool h = read_halted(halted, b);
    int idx = h ? inputs[r] : carry_inputs[r];
    const float* e = emb + (size_t)idx * DD;
    const float* p = pos + (size_t)n * DD;

    float x0 = e[t]       + p[t];
    float x1 = e[t + 256] + p[t + 256];

    size_t base = (size_t)r * DD;
    g_Q[base + t]       = h ? init_hidden[t]       : carry_hidden[base + t];
    g_Q[base + t + 256] = h ? init_hidden[t + 256] : carry_hidden[base + t + 256];

    __shared__ float s_sum[256], s_sq[256];
    s_sum[t] = x0 + x1;
    s_sq[t]  = x0 * x0 + x1 * x1;
    __syncthreads();
    for (int o = 128; o > 0; o >>= 1) {
        if (t < o) { s_sum[t] += s_sum[t + o]; s_sq[t] += s_sq[t + o]; }
        __syncthreads();
    }
    float mu   = s_sum[0] * (1.0f / DD);
    float var  = s_sq[0] * (1.0f / DD) - mu * mu;
    float rstd = rsqrtf(var + 1e-5f);
    g_X[base + t]       = (x0 - mu) * rstd * in_s[t]       + in_b[t];
    g_X[base + t + 256] = (x1 - mu) * rstd * in_s[t + 256] + in_b[t + 256];
}

// ---------------- per-row LayerNorm ---------------------------------------
__global__ void ln_kernel(const float* __restrict__ in, float* __restrict__ out,
                          const float* __restrict__ s, const float* __restrict__ bia,
                          const float* __restrict__ add)
{
    int r = blockIdx.x;
    int t = threadIdx.x;
    size_t base = (size_t)r * DD;
    float x0 = in[base + t];
    float x1 = in[base + t + 256];

    __shared__ float s_sum[256], s_sq[256];
    s_sum[t] = x0 + x1;
    s_sq[t]  = x0 * x0 + x1 * x1;
    __syncthreads();
    for (int o = 128; o > 0; o >>= 1) {
        if (t < o) { s_sum[t] += s_sum[t + o]; s_sq[t] += s_sq[t + o]; }
        __syncthreads();
    }
    float mu   = s_sum[0] * (1.0f / DD);
    float var  = s_sq[0] * (1.0f / DD) - mu * mu;
    float rstd = rsqrtf(var + 1e-5f);
    float v0 = (x0 - mu) * rstd * s[t]       + bia[t];
    float v1 = (x1 - mu) * rstd * s[t + 256] + bia[t + 256];
    if (add) { v0 += add[base + t]; v1 += add[base + t + 256]; }
    out[base + t]       = v0;
    out[base + t + 256] = v1;
}

// ---------------- generic tiled SGEMM (row-major NN) ----------------------
template <int EPI>
__global__ void gemm_nn(const float* __restrict__ A, const float* __restrict__ Bm,
                        float* __restrict__ C, int M, int Nc, int Kd,
                        const float* __restrict__ addP,
                        const float* __restrict__ dtP, int kIdx)
{
    __shared__ __align__(16) float As[16][68];
    __shared__ __align__(16) float Bs[16][64];
    int m0 = blockIdx.y * 64;
    int n0 = blockIdx.x * 64;
    int tid = threadIdx.x;
    int tx = tid & 15, ty = tid >> 4;
    float acc[4][4] = {};

    for (int k0 = 0; k0 < Kd; k0 += 16) {
        #pragma unroll
        for (int tt = 0; tt < 4; tt++) {
            int e = tid + 256 * tt;
            int rr = e >> 4, kk = e & 15;
            As[kk][rr] = A[(size_t)(m0 + rr) * Kd + k0 + kk];
        }
        #pragma unroll
        for (int tt = 0; tt < 4; tt++) {
            int e = tid + 256 * tt;
            int kk = e >> 6, cc = e & 63;
            Bs[kk][cc] = Bm[(size_t)(k0 + kk) * Nc + n0 + cc];
        }
        __syncthreads();
        #pragma unroll
        for (int kk = 0; kk < 16; kk++) {
            float4 av = *(const float4*)&As[kk][ty * 4];
            float4 bv = *(const float4*)&Bs[kk][tx * 4];
            float a[4] = {av.x, av.y, av.z, av.w};
            float bb[4] = {bv.x, bv.y, bv.z, bv.w};
            #pragma unroll
            for (int i = 0; i < 4; i++)
                #pragma unroll
                for (int j = 0; j < 4; j++)
                    acc[i][j] += a[i] * bb[j];
        }
        __syncthreads();
    }

    float alpha = 1.0f;
    if (EPI == 2) {
        float d = dtP[kIdx];
        alpha = (d > 20.0f) ? d : log1pf(expf(d));
    }
    #pragma unroll
    for (int i = 0; i < 4; i++) {
        int m = m0 + ty * 4 + i;
        #pragma unroll
        for (int j = 0; j < 4; j++) {
            int n = n0 + tx * 4 + j;
            size_t idx = (size_t)m * Nc + n;
            float v = acc[i][j];
            if (EPI == 1)      v = (v > 0.0f) ? (v + 1.0f) : expf(v);
            else if (EPI == 2) v = addP[idx] + alpha * v;
            else if (EPI == 3) v = addP[idx] + v;
            C[idx] = v;
        }
    }
}

// ---------------- fused Q/K/V projection (grid.z selects) -----------------
__global__ void gemm_proj(const float* __restrict__ A,
                          const float* __restrict__ WQ, const float* __restrict__ WK,
                          const float* __restrict__ WV,
                          float* __restrict__ OQ, float* __restrict__ OK2,
                          float* __restrict__ OV)
{
    __shared__ __align__(16) float As[16][68];
    __shared__ __align__(16) float Bs[16][64];
    int z = blockIdx.z;
    const float* Bm = (z == 0) ? WQ : (z == 1) ? WK : WV;
    float* C = (z == 0) ? OQ : (z == 1) ? OK2 : OV;
    int m0 = blockIdx.y * 64;
    int n0 = blockIdx.x * 64;
    int tid = threadIdx.x;
    int tx = tid & 15, ty = tid >> 4;
    float acc[4][4] = {};

    for (int k0 = 0; k0 < DD; k0 += 16) {
        #pragma unroll
        for (int tt = 0; tt < 4; tt++) {
            int e = tid + 256 * tt;
            int rr = e >> 4, kk = e & 15;
            As[kk][rr] = A[(size_t)(m0 + rr) * DD + k0 + kk];
        }
        #pragma unroll
        for (int tt = 0; tt < 4; tt++) {
            int e = tid + 256 * tt;
            int kk = e >> 6, cc = e & 63;
            Bs[kk][cc] = Bm[(size_t)(k0 + kk) * DD + n0 + cc];
        }
        __syncthreads();
        #pragma unroll
        for (int kk = 0; kk < 16; kk++) {
            float4 av = *(const float4*)&As[kk][ty * 4];
            float4 bv = *(const float4*)&Bs[kk][tx * 4];
            float a[4] = {av.x, av.y, av.z, av.w};
            float bb[4] = {bv.x, bv.y, bv.z, bv.w};
            #pragma unroll
            for (int i = 0; i < 4; i++)
                #pragma unroll
                for (int j = 0; j < 4; j++)
                    acc[i][j] += a[i] * bb[j];
        }
        __syncthreads();
    }
    bool elu = (z < 2);
    #pragma unroll
    for (int i = 0; i < 4; i++) {
        int m = m0 + ty * 4 + i;
        #pragma unroll
        for (int j = 0; j < 4; j++) {
            int n = n0 + tx * 4 + j;
            float v = acc[i][j];
            if (elu) v = (v > 0.0f) ? (v + 1.0f) : expf(v);
            C[(size_t)m * DD + n] = v;
        }
    }
}

// ---------------- attention W = relu(PhiQ . PhiK)^2 -----------------------
__global__ void attn_qk(const float* __restrict__ PhiQ, const float* __restrict__ PhiK,
                        float* __restrict__ Wm)
{
    __shared__ __align__(16) float Qs[64][68];
    __shared__ __align__(16) float Ks[64][68];
    int bh = blockIdx.z;
    int b = bh / HH, h = bh % HH;
    int n0 = blockIdx.y * 64;
    int m0 = blockIdx.x * 64;
    int tid = threadIdx.x;
    int tx = tid & 15, ty = tid >> 4;

    #pragma unroll
    for (int tt = 0; tt < 16; tt++) {
        int e = tid + 256 * tt;
        int row = e >> 6, d = e & 63;
        Qs[d][row] = PhiQ[((size_t)(b * NN + n0 + row)) * DD + h * DH + d];
        Ks[d][row] = PhiK[((size_t)(b * NN + m0 + row)) * DD + h * DH + d];
    }
    __syncthreads();

    float acc[4][4] = {};
    #pragma unroll 8
    for (int kk = 0; kk < 64; kk++) {
        float4 av = *(const float4*)&Qs[kk][ty * 4];
        float4 bv = *(const float4*)&Ks[kk][tx * 4];
        float a[4] = {av.x, av.y, av.z, av.w};
        float bb[4] = {bv.x, bv.y, bv.z, bv.w};
        #pragma unroll
        for (int i = 0; i < 4; i++)
            #pragma unroll
            for (int j = 0; j < 4; j++)
                acc[i][j] += a[i] * bb[j];
    }
    #pragma unroll
    for (int i = 0; i < 4; i++) {
        int n = n0 + ty * 4 + i;
        #pragma unroll
        for (int j = 0; j < 4; j++) {
            int m = m0 + tx * 4 + j;
            float s = fmaxf(acc[i][j], 0.0f);
            Wm[((size_t)bh * NN + n) * NN + m] = s * s;
        }
    }
}

// ---------------- row sums of W -------------------------------------------
__global__ void rowsum_kernel(const float* __restrict__ Wm, float* __restrict__ ws)
{
    int r = blockIdx.x;
    int t = threadIdx.x;
    const float* row = Wm + (size_t)r * NN;
    float s = 0.0f;
    for (int i = t; i < NN; i += 256) s += row[i];
    __shared__ float sh[256];
    sh[t] = s; __syncthreads();
    for (int o = 128; o > 0; o >>= 1) {
        if (t < o) sh[t] += sh[t + o];
        __syncthreads();
    }
    if (t == 0) ws[r] = sh[0];
}

// ---------------- Attr = W @ V; m = Attr/(wsum+1) - V ---------------------
__global__ void attn_wv(const float* __restrict__ Wm, const float* __restrict__ Vp,
                        const float* __restrict__ ws, float* __restrict__ mout)
{
    __shared__ __align__(16) float As[16][68];
    __shared__ __align__(16) float Bs[16][64];
    int bh = blockIdx.y;
    int b = bh / HH, h = bh % HH;
    int n0 = blockIdx.x * 64;
    int tid = threadIdx.x;
    int tx = tid & 15, ty = tid >> 4;
    float acc[4][4] = {};

    for (int k0 = 0; k0 < NN; k0 += 16) {
        #pragma unroll
        for (int tt = 0; tt < 4; tt++) {
            int e = tid + 256 * tt;
            int rr = e >> 4, kk = e & 15;
            As[kk][rr] = Wm[((size_t)bh * NN + n0 + rr) * NN + k0 + kk];
        }
        {
            int kk = tid >> 6, cc = tid & 63;
            #pragma unroll
            for (int tt = 0; tt < 4; tt++) {
                Bs[kk + 4 * tt][cc] =
                    Vp[((size_t)(b * NN + k0 + kk + 4 * tt)) * DD + h * DH + cc];
            }
        }
        __syncthreads();
        #pragma unroll
        for (int kk = 0; kk < 16; kk++) {
            float4 av = *(const float4*)&As[kk][ty * 4];
            float4 bv = *(const float4*)&Bs[kk][tx * 4];
            float a[4] = {av.x, av.y, av.z, av.w};
            float bb[4] = {bv.x, bv.y, bv.z, bv.w};
            #pragma unroll
            for (int i = 0; i < 4; i++)
                #pragma unroll
                for (int j = 0; j < 4; j++)
                    acc[i][j] += a[i] * bb[j];
        }
        __syncthreads();
    }

    #pragma unroll
    for (int i = 0; i < 4; i++) {
        int n = n0 + ty * 4 + i;
        float rden = 1.0f / (ws[bh * NN + n] + 1.0f);
        #pragma unroll
        for (int j = 0; j < 4; j++) {
            int d = tx * 4 + j;
            size_t idx = ((size_t)(b * NN + n)) * DD + h * DH + d;
            mout[idx] = acc[i][j] * rden - Vp[idx];
        }
    }
}

// ---------------- SwiGLU ---------------------------------------------------
__global__ void swiglu_kernel(const float* __restrict__ GU, float* __restrict__ Hf)
{
    size_t i = (size_t)blockIdx.x * 256 + threadIdx.x;
    if (i >= (size_t)MROWS * INNER) return;
    size_t row = i / INNER;
    int c = (int)(i % INNER);
    float g = GU[row * (2 * INNER) + c];
    float u = GU[row * (2 * INNER) + INNER + c];
    Hf[i] = siluf(g) * u;
}

// ---------------- depthwise conv k=3 + bias + silu ------------------------
__global__ void conv_kernel(const float* __restrict__ Hf, const float* __restrict__ w,
                            const float* __restrict__ bias, float* __restrict__ out)
{
    size_t i = (size_t)blockIdx.x * 256 + threadIdx.x;
    if (i >= (size_t)MROWS * INNER) return;
    size_t row = i / INNER;
    int c = (int)(i % INNER);
    int n = (int)(row % NN);
    const float* wc = w + (size_t)c * CKW;
    float acc = bias[c];
    if (n > 0)      acc += wc[0] * Hf[(row - 1) * INNER + c];
    acc += wc[1] * Hf[row * INNER + c];
    if (n < NN - 1) acc += wc[2] * Hf[(row + 1) * INNER + c];
    out[i] = siluf(acc);
}

// ---------------- halt head ------------------------------------------------
__global__ void halt_kernel(const float* __restrict__ Qn, const float* __restrict__ hw,
                            const float* __restrict__ hb, float* __restrict__ out)
{
    int b = blockIdx.x;
    int t = threadIdx.x;
    __shared__ float md[DD];
    for (int d = t; d < DD; d += 256) {
        float s = 0.0f;
        for (int n = 0; n < NN; n++)
            s += Qn[((size_t)(b * NN + n)) * DD + d];
        md[d] = s * (1.0f / NN);
    }
    __syncthreads();
    __shared__ float r0[256], r1[256];
    float p0 = 0.0f, p1 = 0.0f;
    for (int d = t; d < DD; d += 256) {
        p0 += md[d] * hw[d];
        p1 += md[d] * hw[DD + d];
    }
    r0[t] = p0; r1[t] = p1;
    __syncthreads();
    for (int o = 128; o > 0; o >>= 1) {
        if (t < o) { r0[t] += r0[t + o]; r1[t] += r1[t + o]; }
        __syncthreads();
    }
    if (t == 0) {
        out[b * 2 + 0] = r0[0] + hb[0];
        out[b * 2 + 1] = r1[0] + hb[1];
    }
}

// ---------------- host orchestration --------------------------------------
extern "C" void kernel_launch(void* const* d_in, const int* in_sizes, int n_in,
                              void* d_out, int out_size)
{
    const int*   inputs       = (const int*)d_in[0];
    const float* carry_hidden = (const float*)d_in[2];
    const void*  halted       = d_in[4];
    const int*   carry_inputs = (const int*)d_in[5];
    const float* init_hidden  = (const float*)d_in[7];
    const float* emb          = (const float*)d_in[8];
    const float* pos          = (const float*)d_in[9];
    const float* in_s         = (const float*)d_in[10];
    const float* in_b         = (const float*)d_in[11];
    const float* fin_s        = (const float*)d_in[12];
    const float* fin_b        = (const float*)d_in[13];
    const float* lm_w         = (const float*)d_in[14];
    const float* halt_w       = (const float*)d_in[15];
    const float* halt_b       = (const float*)d_in[16];
    const float* dt           = (const float*)d_in[17];
    const float* W_Q          = (const float*)d_in[18];
    const float* W_K          = (const float*)d_in[19];
    const float* W_V          = (const float*)d_in[20];
    const float* W_O          = (const float*)d_in[21];
    const float* W_up         = (const float*)d_in[22];
    const float* dw_w         = (const float*)d_in[23];
    const float* dw_b         = (const float*)d_in[24];
    const float* W_down       = (const float*)d_in[25];
    const float* n1_s         = (const float*)d_in[26];
    const float* n1_b         = (const float*)d_in[27];
    const float* n2_s         = (const float*)d_in[28];
    const float* n2_b         = (const float*)d_in[29];

    float *X, *Q, *Hc, *PhiQ, *PhiK, *Vp, *Wm, *ws, *mb, *Qi, *Qn2, *GU, *Hf, *Hcv, *Qn;
    cudaGetSymbolAddress((void**)&X,    g_X);
    cudaGetSymbolAddress((void**)&Q,    g_Q);
    cudaGetSymbolAddress((void**)&Hc,   g_Hc);
    cudaGetSymbolAddress((void**)&PhiQ, g_PhiQ);
    cudaGetSymbolAddress((void**)&PhiK, g_PhiK);
    cudaGetSymbolAddress((void**)&Vp,   g_Vp);
    cudaGetSymbolAddress((void**)&Wm,   g_Wm);
    cudaGetSymbolAddress((void**)&ws,   g_wsum);
    cudaGetSymbolAddress((void**)&mb,   g_mbuf);
    cudaGetSymbolAddress((void**)&Qi,   g_Qi);
    cudaGetSymbolAddress((void**)&Qn2,  g_Qn2);
    cudaGetSymbolAddress((void**)&GU,   g_GU);
    cudaGetSymbolAddress((void**)&Hf,   g_Hf);
    cudaGetSymbolAddress((void**)&Hcv,  g_Hcv);
    cudaGetSymbolAddress((void**)&Qn,   g_Qn);

    float* out = (float*)d_out;

    init_kernel<<<MROWS, 256>>>(inputs, carry_inputs, halted, carry_hidden,
                                init_hidden, emb, pos, in_s, in_b);

    dim3 gD(DD / 64, MROWS / 64);             // (8, 32)
    dim3 gP(DD / 64, MROWS / 64, 3);          // fused QKV
    dim3 gUP(2 * INNER / 64, MROWS / 64);     // (48, 32)
    dim3 gQK(NN / 64, NN / 64, BHN);          // (16, 16, 16)
    dim3 gWV(NN / 64, BHN);                   // (16, 16)

    for (int it = 0; it < TOTAL_PASSES; it++) {
        int k = it % KKB;
        size_t woff = (size_t)k * DD * DD;

        ln_kernel<<<MROWS, 256>>>(Q, Hc, n1_s + k * DD, n1_b + k * DD, X);

        gemm_proj<<<gP, 256>>>(Hc, W_Q + woff, W_K + woff, W_V + woff,
                               PhiQ, PhiK, Vp);

        attn_qk<<<gQK, 256>>>(PhiQ, PhiK, Wm);
        rowsum_kernel<<<BHN * NN, 256>>>(Wm, ws);
        attn_wv<<<gWV, 256>>>(Wm, Vp, ws, mb);

        gemm_nn<2><<<gD, 256>>>(mb, W_O + woff, Qi, MROWS, DD, DD, Q, dt, k);

        ln_kernel<<<MROWS, 256>>>(Qi, Qn2, n2_s + k * DD, n2_b + k * DD, nullptr);
        gemm_nn<0><<<gUP, 256>>>(Qn2, W_up + (size_t)k * DD * 2 * INNER, GU,
                                 MROWS, 2 * INNER, DD, nullptr, nullptr, 0);
        int tot = MROWS * INNER;
        swiglu_kernel<<<(tot + 255) / 256, 256>>>(GU, Hf);
        conv_kernel<<<(tot + 255) / 256, 256>>>(Hf, dw_w + (size_t)k * INNER * CKW,
                                                dw_b + (size_t)k * INNER, Hcv);
        gemm_nn<3><<<gD, 256>>>(Hcv, W_down + (size_t)k * INNER * DD, Q,
                                MROWS, DD, INNER, Qi, nullptr, 0);
    }

    ln_kernel<<<MROWS, 256>>>(Q, Qn, fin_s, fin_b, nullptr);
    dim3 gLM(VV / 128, MROWS / 128);          // (250, 16)
    lm_head_mma<<<gLM, 256>>>(Qn, lm_w, out);
    halt_kernel<<<BB, 256>>>(Qn, halt_w, halt_b, out + (size_t)MROWS * VV);
}

// round 6
// speedup vs baseline: 1.6437x; 1.4731x over previous
#include <cuda_runtime.h>
#include <cuda_bf16.h>
#include <math.h>
#include <stdint.h>

// Problem constants
#define BB    2
#define NN    1024
#define DD    512
#define HH    8
#define DH    64
#define KKB   4
#define VV    32000
#define INNER 1536
#define CKW   3
#define MROWS (BB*NN)     // 2048
#define BHN   (BB*HH)     // 16
#define TOTAL_PASSES 8

#define AMS  40    // A smem stride (bf16): 32 data + 8 pad
#define BNS  136   // B smem stride for 128-wide B tile
#define BNS2 72    // B smem stride for 64-wide B tile

// ---------------- scratch ---------------------------------------------------
__device__ float        g_X   [MROWS*DD];
__device__ float        g_Q   [MROWS*DD];
__device__ float        g_Hc  [MROWS*DD];
__device__ float        g_PhiQ[MROWS*DD];
__device__ float        g_PhiK[MROWS*DD];
__device__ float        g_Vp  [MROWS*DD];
__device__ unsigned int g_Wm  [(size_t)BHN*NN*NN];   // packed bf16 hi|lo<<16
__device__ float        g_mbuf[MROWS*DD];
__device__ float        g_Qi  [MROWS*DD];
__device__ float        g_Qn2 [MROWS*DD];
__device__ float        g_GU  [(size_t)MROWS*2*INNER];
__device__ float        g_Hf  [(size_t)MROWS*INNER];
__device__ float        g_Hcv [(size_t)MROWS*INNER];
__device__ float        g_Qn  [MROWS*DD];

// ---------------- helpers ---------------------------------------------------
__device__ __forceinline__ float siluf(float x) { return x / (1.0f + expf(-x)); }

__device__ __forceinline__ bool read_halted(const void* p, int b)
{
    const unsigned char* u8 = (const unsigned char*)p;
    if (u8[1] != 0) return u8[b] != 0;
    return ((const int*)p)[b] != 0;
}

__device__ __forceinline__ uint32_t smem_u32(const void* p) {
    uint32_t a;
    asm("{ .reg .u64 t; cvta.to.shared.u64 t, %1; cvt.u32.u64 %0, t; }"
        : "=r"(a) : "l"(p));
    return a;
}

// ---------------- mma.sync helpers -----------------------------------------
__device__ __forceinline__ void ldm4(uint32_t* r, uint32_t a) {
    asm volatile("ldmatrix.sync.aligned.m8n8.x4.shared.b16 {%0,%1,%2,%3}, [%4];"
                 : "=r"(r[0]), "=r"(r[1]), "=r"(r[2]), "=r"(r[3]) : "r"(a));
}
__device__ __forceinline__ void ldm4t(uint32_t* r, uint32_t a) {
    asm volatile("ldmatrix.sync.aligned.m8n8.x4.trans.shared.b16 {%0,%1,%2,%3}, [%4];"
                 : "=r"(r[0]), "=r"(r[1]), "=r"(r[2]), "=r"(r[3]) : "r"(a));
}
__device__ __forceinline__ void mma_bf16(float* c, const uint32_t* a, const uint32_t* b) {
    asm volatile("mma.sync.aligned.m16n8k16.row.col.f32.bf16.bf16.f32 "
                 "{%0,%1,%2,%3}, {%4,%5,%6,%7}, {%8,%9}, {%0,%1,%2,%3};"
                 : "+f"(c[0]), "+f"(c[1]), "+f"(c[2]), "+f"(c[3])
                 : "r"(a[0]), "r"(a[1]), "r"(a[2]), "r"(a[3]),
                   "r"(b[0]), "r"(b[1]));
}
__device__ __forceinline__ void split8(float4 v0, float4 v1, uint4& h, uint4& l) {
    float f[8] = {v0.x, v0.y, v0.z, v0.w, v1.x, v1.y, v1.z, v1.w};
    uint32_t hh[8], ll[8];
    #pragma unroll
    for (int q = 0; q < 8; q++) {
        __nv_bfloat16 bh = __float2bfloat16(f[q]);
        __nv_bfloat16 bl = __float2bfloat16(f[q] - __bfloat162float(bh));
        hh[q] = __bfloat16_as_ushort(bh);
        ll[q] = __bfloat16_as_ushort(bl);
    }
    h = make_uint4(hh[0] | (hh[1] << 16), hh[2] | (hh[3] << 16),
                   hh[4] | (hh[5] << 16), hh[6] | (hh[7] << 16));
    l = make_uint4(ll[0] | (ll[1] << 16), ll[2] | (ll[3] << 16),
                   ll[4] | (ll[5] << 16), ll[6] | (ll[7] << 16));
}

// ---------------- generic bf16x3 GEMM body: C = A[M,K] @ B[K,N] -------------
// trans-B via ldmatrix.trans (B stored row-major [K,N]).
// epi: 0 none, 1 elu+1, 2 addP + alpha*acc, 3 addP + acc
__device__ __forceinline__ void gemm_mma_body(
    __nv_bfloat16* sAh, __nv_bfloat16* sAl,
    __nv_bfloat16* sBh, __nv_bfloat16* sBl,
    const float* __restrict__ A, int lda,
    const float* __restrict__ B, int ldb,
    float* __restrict__ C, int ldc,
    int m0, int n0, int kch,
    int epi, const float* __restrict__ addP, float alpha)
{
    const int tid = threadIdx.x, lane = tid & 31, wid = tid >> 5;
    const int warp_m = wid >> 1, warp_n = wid & 1;
    const uint32_t uAh = smem_u32(sAh), uAl = smem_u32(sAl);
    const uint32_t uBh = smem_u32(sBh), uBl = smem_u32(sBl);

    float acc[2][8][4];
    #pragma unroll
    for (int i = 0; i < 2; i++)
        #pragma unroll
        for (int j = 0; j < 8; j++)
            #pragma unroll
            for (int q = 0; q < 4; q++) acc[i][j][q] = 0.0f;

    for (int kc = 0; kc < kch; kc++) {
        // stage A 128x32
        #pragma unroll
        for (int it = 0; it < 2; it++) {
            int g = tid + 256 * it;
            int row = g >> 2, c8 = (g & 3) * 8;
            const float* pa = A + (size_t)(m0 + row) * lda + kc * 32 + c8;
            uint4 h, l;
            split8(*(const float4*)pa, *(const float4*)(pa + 4), h, l);
            *(uint4*)(sAh + row * AMS + c8) = h;
            *(uint4*)(sAl + row * AMS + c8) = l;
        }
        // stage B 32x128 (natural [K,N] layout)
        #pragma unroll
        for (int it = 0; it < 2; it++) {
            int g = tid + 256 * it;
            int row = g >> 4, c8 = (g & 15) * 8;
            const float* pb = B + (size_t)(kc * 32 + row) * ldb + n0 + c8;
            uint4 h, l;
            split8(*(const float4*)pb, *(const float4*)(pb + 4), h, l);
            *(uint4*)(sBh + row * BNS + c8) = h;
            *(uint4*)(sBl + row * BNS + c8) = l;
        }
        __syncthreads();

        #pragma unroll
        for (int s = 0; s < 2; s++) {
            uint32_t ah[2][4], al[2][4], bh[8][2], bl[8][2];
            #pragma unroll
            for (int i = 0; i < 2; i++) {
                int r  = warp_m * 32 + i * 16 + (lane & 15);
                int kb = s * 16 + ((lane >> 4) << 3);
                uint32_t off = (uint32_t)(r * AMS + kb) * 2;
                ldm4(ah[i], uAh + off);
                ldm4(al[i], uAl + off);
            }
            #pragma unroll
            for (int j = 0; j < 4; j++) {
                int kk = s * 16 + (lane & 7) + ((lane >> 3) & 1) * 8;
                int nn = warp_n * 64 + j * 16 + (lane >> 4) * 8;
                uint32_t off = (uint32_t)(kk * BNS + nn) * 2;
                uint32_t q[4];
                ldm4t(q, uBh + off);
                bh[2*j][0] = q[0]; bh[2*j][1] = q[1];
                bh[2*j+1][0] = q[2]; bh[2*j+1][1] = q[3];
                ldm4t(q, uBl + off);
                bl[2*j][0] = q[0]; bl[2*j][1] = q[1];
                bl[2*j+1][0] = q[2]; bl[2*j+1][1] = q[3];
            }
            #pragma unroll
            for (int i = 0; i < 2; i++)
                #pragma unroll
                for (int j = 0; j < 8; j++) {
                    mma_bf16(acc[i][j], ah[i], bh[j]);
                    mma_bf16(acc[i][j], al[i], bh[j]);
                    mma_bf16(acc[i][j], ah[i], bl[j]);
                }
        }
        __syncthreads();
    }

    #pragma unroll
    for (int i = 0; i < 2; i++) {
        int m = m0 + warp_m * 32 + i * 16 + (lane >> 2);
        #pragma unroll
        for (int j = 0; j < 8; j++) {
            int n = n0 + warp_n * 64 + j * 8 + (lane & 3) * 2;
            float v0 = acc[i][j][0], v1 = acc[i][j][1];
            float v2 = acc[i][j][2], v3 = acc[i][j][3];
            size_t i0 = (size_t)m * ldc + n;
            size_t i1 = (size_t)(m + 8) * ldc + n;
            if (epi == 1) {
                v0 = (v0 > 0.f) ? v0 + 1.f : expf(v0);
                v1 = (v1 > 0.f) ? v1 + 1.f : expf(v1);
                v2 = (v2 > 0.f) ? v2 + 1.f : expf(v2);
                v3 = (v3 > 0.f) ? v3 + 1.f : expf(v3);
            } else if (epi == 2) {
                v0 = addP[i0] + alpha * v0; v1 = addP[i0+1] + alpha * v1;
                v2 = addP[i1] + alpha * v2; v3 = addP[i1+1] + alpha * v3;
            } else if (epi == 3) {
                v0 += addP[i0]; v1 += addP[i0+1];
                v2 += addP[i1]; v3 += addP[i1+1];
            }
            *(float2*)(C + i0) = make_float2(v0, v1);
            *(float2*)(C + i1) = make_float2(v2, v3);
        }
    }
}

// ---------------- wrappers --------------------------------------------------
__global__ void __launch_bounds__(256) mma_proj(
    const float* __restrict__ A, const float* __restrict__ WQ,
    const float* __restrict__ WK, const float* __restrict__ WV,
    float* __restrict__ OQ, float* __restrict__ OK2, float* __restrict__ OV)
{
    __shared__ __align__(16) __nv_bfloat16 sAh[128*AMS], sAl[128*AMS];
    __shared__ __align__(16) __nv_bfloat16 sBh[32*BNS],  sBl[32*BNS];
    int z = blockIdx.z;
    const float* B = (z == 0) ? WQ : (z == 1) ? WK : WV;
    float* C = (z == 0) ? OQ : (z == 1) ? OK2 : OV;
    gemm_mma_body(sAh, sAl, sBh, sBl, A, DD, B, DD, C, DD,
                  blockIdx.y * 128, blockIdx.x * 128, DD / 32,
                  (z < 2) ? 1 : 0, nullptr, 0.f);
}

__global__ void __launch_bounds__(256) mma_wo(
    const float* __restrict__ A, const float* __restrict__ W,
    float* __restrict__ C, const float* __restrict__ addP,
    const float* __restrict__ dt, int kIdx)
{
    __shared__ __align__(16) __nv_bfloat16 sAh[128*AMS], sAl[128*AMS];
    __shared__ __align__(16) __nv_bfloat16 sBh[32*BNS],  sBl[32*BNS];
    float d = dt[kIdx];
    float alpha = (d > 20.0f) ? d : log1pf(expf(d));
    gemm_mma_body(sAh, sAl, sBh, sBl, A, DD, W, DD, C, DD,
                  blockIdx.y * 128, blockIdx.x * 128, DD / 32, 2, addP, alpha);
}

__global__ void __launch_bounds__(256) mma_up(
    const float* __restrict__ A, const float* __restrict__ W,
    float* __restrict__ C)
{
    __shared__ __align__(16) __nv_bfloat16 sAh[128*AMS], sAl[128*AMS];
    __shared__ __align__(16) __nv_bfloat16 sBh[32*BNS],  sBl[32*BNS];
    gemm_mma_body(sAh, sAl, sBh, sBl, A, DD, W, 2 * INNER, C, 2 * INNER,
                  blockIdx.y * 128, blockIdx.x * 128, DD / 32, 0, nullptr, 0.f);
}

__global__ void __launch_bounds__(256) mma_down(
    const float* __restrict__ A, const float* __restrict__ W,
    float* __restrict__ C, const float* __restrict__ addP)
{
    __shared__ __align__(16) __nv_bfloat16 sAh[128*AMS], sAl[128*AMS];
    __shared__ __align__(16) __nv_bfloat16 sBh[32*BNS],  sBl[32*BNS];
    gemm_mma_body(sAh, sAl, sBh, sBl, A, INNER, W, DD, C, DD,
                  blockIdx.y * 128, blockIdx.x * 128, INNER / 32, 3, addP, 0.f);
}

// ---------------- attention QK: W = relu(PhiQ.PhiK)^2, packed bf16 ----------
__global__ void __launch_bounds__(256) attn_qk_mma(
    const float* __restrict__ PhiQ, const float* __restrict__ PhiK,
    unsigned int* __restrict__ Wp)
{
    __shared__ __align__(16) __nv_bfloat16 sAh[128*AMS], sAl[128*AMS];
    __shared__ __align__(16) __nv_bfloat16 sBh[128*AMS], sBl[128*AMS];
    const int tid = threadIdx.x, lane = tid & 31, wid = tid >> 5;
    const int warp_m = wid >> 1, warp_n = wid & 1;
    const int bh = blockIdx.z, b = bh >> 3, h = bh & 7;
    const int q0 = blockIdx.y * 128, k0 = blockIdx.x * 128;
    const float* Abase = PhiQ + (size_t)(b * NN + q0) * DD + h * DH;
    const float* Bbase = PhiK + (size_t)(b * NN + k0) * DD + h * DH;
    const uint32_t uAh = smem_u32(sAh), uAl = smem_u32(sAl);
    const uint32_t uBh = smem_u32(sBh), uBl = smem_u32(sBl);

    float acc[2][8][4];
    #pragma unroll
    for (int i = 0; i < 2; i++)
        #pragma unroll
        for (int j = 0; j < 8; j++)
            #pragma unroll
            for (int q = 0; q < 4; q++) acc[i][j][q] = 0.0f;

    for (int kc = 0; kc < 2; kc++) {
        #pragma unroll
        for (int it = 0; it < 2; it++) {
            int g = tid + 256 * it;
            int row = g >> 2, c8 = (g & 3) * 8;
            const float* pa = Abase + (size_t)row * DD + kc * 32 + c8;
            const float* pb = Bbase + (size_t)row * DD + kc * 32 + c8;
            uint4 h4, l4;
            split8(*(const float4*)pa, *(const float4*)(pa + 4), h4, l4);
            *(uint4*)(sAh + row * AMS + c8) = h4;
            *(uint4*)(sAl + row * AMS + c8) = l4;
            split8(*(const float4*)pb, *(const float4*)(pb + 4), h4, l4);
            *(uint4*)(sBh + row * AMS + c8) = h4;
            *(uint4*)(sBl + row * AMS + c8) = l4;
        }
        __syncthreads();
        #pragma unroll
        for (int s = 0; s < 2; s++) {
            uint32_t ah[2][4], al[2][4], bh2[8][2], bl2[8][2];
            #pragma unroll
            for (int i = 0; i < 2; i++) {
                int r  = warp_m * 32 + i * 16 + (lane & 15);
                int kb = s * 16 + ((lane >> 4) << 3);
                uint32_t off = (uint32_t)(r * AMS + kb) * 2;
                ldm4(ah[i], uAh + off);
                ldm4(al[i], uAl + off);
            }
            #pragma unroll
            for (int j = 0; j < 4; j++) {
                int r  = warp_n * 64 + j * 16 + (lane & 7) + ((lane >> 4) << 3);
                int kb = s * 16 + (((lane >> 3) & 1) << 3);
                uint32_t off = (uint32_t)(r * AMS + kb) * 2;
                uint32_t q[4];
                ldm4(q, uBh + off);
                bh2[2*j][0] = q[0]; bh2[2*j][1] = q[1];
                bh2[2*j+1][0] = q[2]; bh2[2*j+1][1] = q[3];
                ldm4(q, uBl + off);
                bl2[2*j][0] = q[0]; bl2[2*j][1] = q[1];
                bl2[2*j+1][0] = q[2]; bl2[2*j+1][1] = q[3];
            }
            #pragma unroll
            for (int i = 0; i < 2; i++)
                #pragma unroll
                for (int j = 0; j < 8; j++) {
                    mma_bf16(acc[i][j], ah[i], bh2[j]);
                    mma_bf16(acc[i][j], al[i], bh2[j]);
                    mma_bf16(acc[i][j], ah[i], bl2[j]);
                }
        }
        __syncthreads();
    }

    #pragma unroll
    for (int i = 0; i < 2; i++) {
        int qr = q0 + warp_m * 32 + i * 16 + (lane >> 2);
        #pragma unroll
        for (int j = 0; j < 8; j++) {
            int kc2 = k0 + warp_n * 64 + j * 8 + (lane & 3) * 2;
            uint32_t u[4];
            #pragma unroll
            for (int q = 0; q < 4; q++) {
                float w = fmaxf(acc[i][j][q], 0.0f);
                float w2 = w * w;
                __nv_bfloat16 hi = __float2bfloat16(w2);
                __nv_bfloat16 lo = __float2bfloat16(w2 - __bfloat162float(hi));
                u[q] = (uint32_t)__bfloat16_as_ushort(hi) |
                       ((uint32_t)__bfloat16_as_ushort(lo) << 16);
            }
            *(uint2*)(Wp + (size_t)(bh * NN + qr) * NN + kc2)       = make_uint2(u[0], u[1]);
            *(uint2*)(Wp + (size_t)(bh * NN + qr + 8) * NN + kc2)   = make_uint2(u[2], u[3]);
        }
    }
}

// ---------------- attention WV: m = (W@V)/(rowsum+1) - V --------------------
__global__ void __launch_bounds__(256) attn_wv_mma(
    const unsigned int* __restrict__ Wp, const float* __restrict__ Vp,
    float* __restrict__ mout)
{
    __shared__ __align__(16) __nv_bfloat16 sAh[128*AMS], sAl[128*AMS];
    __shared__ __align__(16) __nv_bfloat16 sBh[32*BNS2], sBl[32*BNS2];
    __shared__ float sWs[128];
    const int tid = threadIdx.x, lane = tid & 31, wid = tid >> 5;
    const int warp_m = wid >> 1, warp_n = wid & 1;
    const int bh = blockIdx.y, b = bh >> 3, h = bh & 7;
    const int m0 = blockIdx.x * 128;
    const uint32_t uAh = smem_u32(sAh), uAl = smem_u32(sAl);
    const uint32_t uBh = smem_u32(sBh), uBl = smem_u32(sBl);

    float acc[2][4][4];
    #pragma unroll
    for (int i = 0; i < 2; i++)
        #pragma unroll
        for (int j = 0; j < 4; j++)
            #pragma unroll
            for (int q = 0; q < 4; q++) acc[i][j][q] = 0.0f;
    float rsum = 0.0f;

    for (int kc = 0; kc < 32; kc++) {
        // stage A: 128x32 packed W
        #pragma unroll
        for (int it = 0; it < 4; it++) {
            int g = tid + 256 * it;
            int row = g >> 3, c4 = (g & 7) * 4;
            uint4 w4 = *(const uint4*)(Wp + (size_t)(bh * NN + m0 + row) * NN + kc * 32 + c4);
            uint32_t h01 = (w4.x & 0xFFFFu) | (w4.y << 16);
            uint32_t l01 = (w4.x >> 16)     | (w4.y & 0xFFFF0000u);
            uint32_t h23 = (w4.z & 0xFFFFu) | (w4.w << 16);
            uint32_t l23 = (w4.z >> 16)     | (w4.w & 0xFFFF0000u);
            *(uint32_t*)(sAh + row * AMS + c4)     = h01;
            *(uint32_t*)(sAh + row * AMS + c4 + 2) = h23;
            *(uint32_t*)(sAl + row * AMS + c4)     = l01;
            *(uint32_t*)(sAl + row * AMS + c4 + 2) = l23;
        }
        // stage B: 32x64 Vp
        {
            int row = tid >> 3, c8 = (tid & 7) * 8;
            const float* pb = Vp + (size_t)(b * NN + kc * 32 + row) * DD + h * DH + c8;
            uint4 h4, l4;
            split8(*(const float4*)pb, *(const float4*)(pb + 4), h4, l4);
            *(uint4*)(sBh + row * BNS2 + c8) = h4;
            *(uint4*)(sBl + row * BNS2 + c8) = l4;
        }
        __syncthreads();

        // deterministic row sums of W (hi+lo) from staged tile
        if (tid < 128) {
            float s = 0.0f;
            #pragma unroll
            for (int kk = 0; kk < 32; kk++)
                s += __bfloat162float(sAh[tid * AMS + kk]) +
                     __bfloat162float(sAl[tid * AMS + kk]);
            rsum += s;
        }

        #pragma unroll
        for (int s = 0; s < 2; s++) {
            uint32_t ah[2][4], al[2][4], bh2[4][2], bl2[4][2];
            #pragma unroll
            for (int i = 0; i < 2; i++) {
                int r  = warp_m * 32 + i * 16 + (lane & 15);
                int kb = s * 16 + ((lane >> 4) << 3);
                uint32_t off = (uint32_t)(r * AMS + kb) * 2;
                ldm4(ah[i], uAh + off);
                ldm4(al[i], uAl + off);
            }
            #pragma unroll
            for (int j2 = 0; j2 < 2; j2++) {
                int kk = s * 16 + (lane & 7) + ((lane >> 3) & 1) * 8;
                int nn = warp_n * 32 + j2 * 16 + (lane >> 4) * 8;
                uint32_t off = (uint32_t)(kk * BNS2 + nn) * 2;
                uint32_t q[4];
                ldm4t(q, uBh + off);
                bh2[2*j2][0] = q[0]; bh2[2*j2][1] = q[1];
                bh2[2*j2+1][0] = q[2]; bh2[2*j2+1][1] = q[3];
                ldm4t(q, uBl + off);
                bl2[2*j2][0] = q[0]; bl2[2*j2][1] = q[1];
                bl2[2*j2+1][0] = q[2]; bl2[2*j2+1][1] = q[3];
            }
            #pragma unroll
            for (int i = 0; i < 2; i++)
                #pragma unroll
                for (int j = 0; j < 4; j++) {
                    mma_bf16(acc[i][j], ah[i], bh2[j]);
                    mma_bf16(acc[i][j], al[i], bh2[j]);
                    mma_bf16(acc[i][j], ah[i], bl2[j]);
                }
        }
        __syncthreads();
    }

    if (tid < 128) sWs[tid] = rsum;
    __syncthreads();

    #pragma unroll
    for (int i = 0; i < 2; i++) {
        int mr = warp_m * 32 + i * 16 + (lane >> 2);   // local row
        float rd0 = 1.0f / (sWs[mr] + 1.0f);
        float rd1 = 1.0f / (sWs[mr + 8] + 1.0f);
        #pragma unroll
        for (int j = 0; j < 4; j++) {
            int d = warp_n * 32 + j * 8 + (lane & 3) * 2;
            size_t i0 = (size_t)(b * NN + m0 + mr) * DD + h * DH + d;
            size_t i1 = (size_t)(b * NN + m0 + mr + 8) * DD + h * DH + d;
            *(float2*)(mout + i0) = make_float2(
                acc[i][j][0] * rd0 - Vp[i0], acc[i][j][1] * rd0 - Vp[i0 + 1]);
            *(float2*)(mout + i1) = make_float2(
                acc[i][j][2] * rd1 - Vp[i1], acc[i][j][3] * rd1 - Vp[i1 + 1]);
        }
    }
}

// ---------------- LM head (unchanged from R5 — validated) -------------------
#define LMS 40
__global__ void __launch_bounds__(256)
lm_head_mma(const float* __restrict__ A, const float* __restrict__ Bw,
            float* __restrict__ C)
{
    __shared__ __align__(16) __nv_bfloat16 sAh[128 * LMS];
    __shared__ __align__(16) __nv_bfloat16 sAl[128 * LMS];
    __shared__ __align__(16) __nv_bfloat16 sBh[128 * LMS];
    __shared__ __align__(16) __nv_bfloat16 sBl[128 * LMS];

    const int tid  = threadIdx.x;
    const int lane = tid & 31, wid = tid >> 5;
    const int warp_m = wid >> 1, warp_n = wid & 1;
    const int m0 = blockIdx.y * 128, n0 = blockIdx.x * 128;

    const uint32_t uAh = smem_u32(sAh), uAl = smem_u32(sAl);
    const uint32_t uBh = smem_u32(sBh), uBl = smem_u32(sBl);

    float acc[2][8][4];
    #pragma unroll
    for (int i = 0; i < 2; i++)
        #pragma unroll
        for (int j = 0; j < 8; j++)
            #pragma unroll
            for (int q = 0; q < 4; q++) acc[i][j][q] = 0.0f;

    for (int kc = 0; kc < 16; kc++) {
        #pragma unroll
        for (int it = 0; it < 2; it++) {
            int g = tid + 256 * it;
            int row = g >> 2;
            int c8  = (g & 3) * 8;
            const float* pa = A  + (size_t)(m0 + row) * DD + kc * 32 + c8;
            const float* pb = Bw + (size_t)(n0 + row) * DD + kc * 32 + c8;
            uint4 h, l;
            split8(*(const float4*)pa, *(const float4*)(pa + 4), h, l);
            *(uint4*)(sAh + row * LMS + c8) = h;
            *(uint4*)(sAl + row * LMS + c8) = l;
            split8(*(const float4*)pb, *(const float4*)(pb + 4), h, l);
            *(uint4*)(sBh + row * LMS + c8) = h;
            *(uint4*)(sBl + row * LMS + c8) = l;
        }
        __syncthreads();

        #pragma unroll
        for (int s = 0; s < 2; s++) {
            uint32_t ah[2][4], al[2][4], bh[8][2], bl[8][2];
            #pragma unroll
            for (int i = 0; i < 2; i++) {
                int r  = warp_m * 32 + i * 16 + (lane & 15);
                int kb = s * 16 + ((lane >> 4) << 3);
                uint32_t off = (uint32_t)(r * LMS + kb) * 2;
                ldm4(ah[i], uAh + off);
                ldm4(al[i], uAl + off);
            }
            #pragma unroll
            for (int j = 0; j < 4; j++) {
                int r  = warp_n * 64 + j * 16 + (lane & 7) + ((lane >> 4) << 3);
                int kb = s * 16 + (((lane >> 3) & 1) << 3);
                uint32_t off = (uint32_t)(r * LMS + kb) * 2;
                uint32_t q[4];
                ldm4(q, uBh + off);
                bh[2*j][0] = q[0]; bh[2*j][1] = q[1];
                bh[2*j+1][0] = q[2]; bh[2*j+1][1] = q[3];
                ldm4(q, uBl + off);
                bl[2*j][0] = q[0]; bl[2*j][1] = q[1];
                bl[2*j+1][0] = q[2]; bl[2*j+1][1] = q[3];
            }
            #pragma unroll
            for (int i = 0; i < 2; i++)
                #pragma unroll
                for (int j = 0; j < 8; j++) {
                    mma_bf16(acc[i][j], ah[i], bh[j]);
                    mma_bf16(acc[i][j], al[i], bh[j]);
                    mma_bf16(acc[i][j], ah[i], bl[j]);
                }
        }
        __syncthreads();
    }

    #pragma unroll
    for (int i = 0; i < 2; i++) {
        int m = m0 + warp_m * 32 + i * 16 + (lane >> 2);
        #pragma unroll
        for (int j = 0; j < 8; j++) {
            int n = n0 + warp_n * 64 + j * 8 + (lane & 3) * 2;
            *(float2*)(C + (size_t)m * VV + n) =
                make_float2(acc[i][j][0], acc[i][j][1]);
            *(float2*)(C + (size_t)(m + 8) * VV + n) =
                make_float2(acc[i][j][2], acc[i][j][3]);
        }
    }
}

// ---------------- init ------------------------------------------------------
__global__ void init_kernel(const int* __restrict__ inputs,
                            const int* __restrict__ carry_inputs,
                            const void* __restrict__ halted,
                            const float* __restrict__ carry_hidden,
                            const float* __restrict__ init_hidden,
                            const float* __restrict__ emb,
                            const float* __restrict__ pos,
                            const float* __restrict__ in_s,
                            const float* __restrict__ in_b)
{
    int r = blockIdx.x;
    int b = r / NN, n = r % NN;
    int t = threadIdx.x;
    bool h = read_halted(halted, b);
    int idx = h ? inputs[r] : carry_inputs[r];
    const float* e = emb + (size_t)idx * DD;
    const float* p = pos + (size_t)n * DD;

    float x0 = e[t]       + p[t];
    float x1 = e[t + 256] + p[t + 256];

    size_t base = (size_t)r * DD;
    g_Q[base + t]       = h ? init_hidden[t]       : carry_hidden[base + t];
    g_Q[base + t + 256] = h ? init_hidden[t + 256] : carry_hidden[base + t + 256];

    __shared__ float s_sum[256], s_sq[256];
    s_sum[t] = x0 + x1;
    s_sq[t]  = x0 * x0 + x1 * x1;
    __syncthreads();
    for (int o = 128; o > 0; o >>= 1) {
        if (t < o) { s_sum[t] += s_sum[t + o]; s_sq[t] += s_sq[t + o]; }
        __syncthreads();
    }
    float mu   = s_sum[0] * (1.0f / DD);
    float var  = s_sq[0] * (1.0f / DD) - mu * mu;
    float rstd = rsqrtf(var + 1e-5f);
    g_X[base + t]       = (x0 - mu) * rstd * in_s[t]       + in_b[t];
    g_X[base + t + 256] = (x1 - mu) * rstd * in_s[t + 256] + in_b[t + 256];
}

// ---------------- LayerNorm -------------------------------------------------
__global__ void ln_kernel(const float* __restrict__ in, float* __restrict__ out,
                          const float* __restrict__ s, const float* __restrict__ bia,
                          const float* __restrict__ add)
{
    int r = blockIdx.x;
    int t = threadIdx.x;
    size_t base = (size_t)r * DD;
    float x0 = in[base + t];
    float x1 = in[base + t + 256];

    __shared__ float s_sum[256], s_sq[256];
    s_sum[t] = x0 + x1;
    s_sq[t]  = x0 * x0 + x1 * x1;
    __syncthreads();
    for (int o = 128; o > 0; o >>= 1) {
        if (t < o) { s_sum[t] += s_sum[t + o]; s_sq[t] += s_sq[t + o]; }
        __syncthreads();
    }
    float mu   = s_sum[0] * (1.0f / DD);
    float var  = s_sq[0] * (1.0f / DD) - mu * mu;
    float rstd = rsqrtf(var + 1e-5f);
    float v0 = (x0 - mu) * rstd * s[t]       + bia[t];
    float v1 = (x1 - mu) * rstd * s[t + 256] + bia[t + 256];
    if (add) { v0 += add[base + t]; v1 += add[base + t + 256]; }
    out[base + t]       = v0;
    out[base + t + 256] = v1;
}

// ---------------- SwiGLU ----------------------------------------------------
__global__ void swiglu_kernel(const float* __restrict__ GU, float* __restrict__ Hf)
{
    size_t i = (size_t)blockIdx.x * 256 + threadIdx.x;
    if (i >= (size_t)MROWS * INNER) return;
    size_t row = i / INNER;
    int c = (int)(i % INNER);
    float g = GU[row * (2 * INNER) + c];
    float u = GU[row * (2 * INNER) + INNER + c];
    Hf[i] = siluf(g) * u;
}

// ---------------- depthwise conv k=3 + bias + silu --------------------------
__global__ void conv_kernel(const float* __restrict__ Hf, const float* __restrict__ w,
                            const float* __restrict__ bias, float* __restrict__ out)
{
    size_t i = (size_t)blockIdx.x * 256 + threadIdx.x;
    if (i >= (size_t)MROWS * INNER) return;
    size_t row = i / INNER;
    int c = (int)(i % INNER);
    int n = (int)(row % NN);
    const float* wc = w + (size_t)c * CKW;
    float acc = bias[c];
    if (n > 0)      acc += wc[0] * Hf[(row - 1) * INNER + c];
    acc += wc[1] * Hf[row * INNER + c];
    if (n < NN - 1) acc += wc[2] * Hf[(row + 1) * INNER + c];
    out[i] = siluf(acc);
}

// ---------------- halt head -------------------------------------------------
__global__ void halt_kernel(const float* __restrict__ Qn, const float* __restrict__ hw,
                            const float* __restrict__ hb, float* __restrict__ out)
{
    int b = blockIdx.x;
    int t = threadIdx.x;
    __shared__ float md[DD];
    for (int d = t; d < DD; d += 256) {
        float s = 0.0f;
        for (int n = 0; n < NN; n++)
            s += Qn[((size_t)(b * NN + n)) * DD + d];
        md[d] = s * (1.0f / NN);
    }
    __syncthreads();
    __shared__ float r0[256], r1[256];
    float p0 = 0.0f, p1 = 0.0f;
    for (int d = t; d < DD; d += 256) {
        p0 += md[d] * hw[d];
        p1 += md[d] * hw[DD + d];
    }
    r0[t] = p0; r1[t] = p1;
    __syncthreads();
    for (int o = 128; o > 0; o >>= 1) {
        if (t < o) { r0[t] += r0[t + o]; r1[t] += r1[t + o]; }
        __syncthreads();
    }
    if (t == 0) {
        out[b * 2 + 0] = r0[0] + hb[0];
        out[b * 2 + 1] = r1[0] + hb[1];
    }
}

// ---------------- host orchestration ----------------------------------------
extern "C" void kernel_launch(void* const* d_in, const int* in_sizes, int n_in,
                              void* d_out, int out_size)
{
    const int*   inputs       = (const int*)d_in[0];
    const float* carry_hidden = (const float*)d_in[2];
    const void*  halted       = d_in[4];
    const int*   carry_inputs = (const int*)d_in[5];
    const float* init_hidden  = (const float*)d_in[7];
    const float* emb          = (const float*)d_in[8];
    const float* pos          = (const float*)d_in[9];
    const float* in_s         = (const float*)d_in[10];
    const float* in_b         = (const float*)d_in[11];
    const float* fin_s        = (const float*)d_in[12];
    const float* fin_b        = (const float*)d_in[13];
    const float* lm_w         = (const float*)d_in[14];
    const float* halt_w       = (const float*)d_in[15];
    const float* halt_b       = (const float*)d_in[16];
    const float* dt           = (const float*)d_in[17];
    const float* W_Q          = (const float*)d_in[18];
    const float* W_K          = (const float*)d_in[19];
    const float* W_V          = (const float*)d_in[20];
    const float* W_O          = (const float*)d_in[21];
    const float* W_up         = (const float*)d_in[22];
    const float* dw_w         = (const float*)d_in[23];
    const float* dw_b         = (const float*)d_in[24];
    const float* W_down       = (const float*)d_in[25];
    const float* n1_s         = (const float*)d_in[26];
    const float* n1_b         = (const float*)d_in[27];
    const float* n2_s         = (const float*)d_in[28];
    const float* n2_b         = (const float*)d_in[29];

    float *X, *Q, *Hc, *PhiQ, *PhiK, *Vp, *mb, *Qi, *Qn2, *GU, *Hf, *Hcv, *Qn;
    unsigned int* Wp;
    cudaGetSymbolAddress((void**)&X,    g_X);
    cudaGetSymbolAddress((void**)&Q,    g_Q);
    cudaGetSymbolAddress((void**)&Hc,   g_Hc);
    cudaGetSymbolAddress((void**)&PhiQ, g_PhiQ);
    cudaGetSymbolAddress((void**)&PhiK, g_PhiK);
    cudaGetSymbolAddress((void**)&Vp,   g_Vp);
    cudaGetSymbolAddress((void**)&Wp,   g_Wm);
    cudaGetSymbolAddress((void**)&mb,   g_mbuf);
    cudaGetSymbolAddress((void**)&Qi,   g_Qi);
    cudaGetSymbolAddress((void**)&Qn2,  g_Qn2);
    cudaGetSymbolAddress((void**)&GU,   g_GU);
    cudaGetSymbolAddress((void**)&Hf,   g_Hf);
    cudaGetSymbolAddress((void**)&Hcv,  g_Hcv);
    cudaGetSymbolAddress((void**)&Qn,   g_Qn);

    float* out = (float*)d_out;

    init_kernel<<<MROWS, 256>>>(inputs, carry_inputs, halted, carry_hidden,
                                init_hidden, emb, pos, in_s, in_b);

    dim3 gP(DD / 128, MROWS / 128, 3);        // (4, 16, 3)
    dim3 gO(DD / 128, MROWS / 128);           // (4, 16)
    dim3 gUP(2 * INNER / 128, MROWS / 128);   // (24, 16)
    dim3 gQK(NN / 128, NN / 128, BHN);        // (8, 8, 16)
    dim3 gWV(NN / 128, BHN);                  // (8, 16)

    for (int it = 0; it < TOTAL_PASSES; it++) {
        int k = it % KKB;
        size_t woff = (size_t)k * DD * DD;

        ln_kernel<<<MROWS, 256>>>(Q, Hc, n1_s + k * DD, n1_b + k * DD, X);

        mma_proj<<<gP, 256>>>(Hc, W_Q + woff, W_K + woff, W_V + woff,
                              PhiQ, PhiK, Vp);

        attn_qk_mma<<<gQK, 256>>>(PhiQ, PhiK, Wp);
        attn_wv_mma<<<gWV, 256>>>(Wp, Vp, mb);

        mma_wo<<<gO, 256>>>(mb, W_O + woff, Qi, Q, dt, k);

        ln_kernel<<<MROWS, 256>>>(Qi, Qn2, n2_s + k * DD, n2_b + k * DD, nullptr);
        mma_up<<<gUP, 256>>>(Qn2, W_up + (size_t)k * DD * 2 * INNER, GU);
        int tot = MROWS * INNER;
        swiglu_kernel<<<(tot + 255) / 256, 256>>>(GU, Hf);
        conv_kernel<<<(tot + 255) / 256, 256>>>(Hf, dw_w + (size_t)k * INNER * CKW,
                                                dw_b + (size_t)k * INNER, Hcv);
        mma_down<<<gO, 256>>>(Hcv, W_down + (size_t)k * INNER * DD, Q, Qi);
    }

    ln_kernel<<<MROWS, 256>>>(Q, Qn, fin_s, fin_b, nullptr);
    dim3 gLM(VV / 128, MROWS / 128);          // (250, 16)
    lm_head_mma<<<gLM, 256>>>(Qn, lm_w, out);
    halt_kernel<<<BB, 256>>>(Qn, halt_w, halt_b, out + (size_t)MROWS * VV);
}

// round 7
// speedup vs baseline: 2.1174x; 1.2882x over previous
#include <cuda_runtime.h>
#include <cuda_bf16.h>
#include <math.h>
#include <stdint.h>

// Problem constants
#define BB    2
#define NN    1024
#define DD    512
#define HH    8
#define DH    64
#define KKB   4
#define VV    32000
#define INNER 1536
#define CKW   3
#define MROWS (BB*NN)     // 2048
#define BHN   (BB*HH)     // 16
#define TOTAL_PASSES 8

#define AMS  40    // A smem stride (bf16)
#define BNS  136   // B smem stride (128-wide tile)
#define QS   72    // attention smem stride (64 + 8)

typedef __nv_bfloat16 bf16;

// ---------------- fp32 scratch ----------------------------------------------
__device__ __align__(16) float g_X  [MROWS*DD];
__device__ __align__(16) float g_Q  [MROWS*DD];
__device__ __align__(16) float g_Qi [MROWS*DD];
__device__ __align__(16) float g_Qn [MROWS*DD];
__device__ __align__(16) float g_GU [(size_t)MROWS*2*INNER];
__device__ __align__(16) float g_Hf [(size_t)MROWS*INNER];

// ---------------- bf16 hi/lo activation scratch ------------------------------
__device__ __align__(16) bf16 g_Hch [MROWS*DD], g_Hcl [MROWS*DD];
__device__ __align__(16) bf16 g_PQh [MROWS*DD], g_PQl [MROWS*DD];
__device__ __align__(16) bf16 g_PKh [MROWS*DD], g_PKl [MROWS*DD];
__device__ __align__(16) bf16 g_Vh  [MROWS*DD], g_Vl  [MROWS*DD];
__device__ __align__(16) bf16 g_mbh [MROWS*DD], g_mbl [MROWS*DD];
__device__ __align__(16) bf16 g_Q2h [MROWS*DD], g_Q2l [MROWS*DD];
__device__ __align__(16) bf16 g_Hvh [(size_t)MROWS*INNER], g_Hvl [(size_t)MROWS*INNER];
__device__ __align__(16) bf16 g_Qnh [MROWS*DD], g_Qnl [MROWS*DD];

// ---------------- bf16 hi/lo weight scratch ----------------------------------
__device__ __align__(16) bf16 g_WQh [KKB*DD*DD],   g_WQl [KKB*DD*DD];
__device__ __align__(16) bf16 g_WKh [KKB*DD*DD],   g_WKl [KKB*DD*DD];
__device__ __align__(16) bf16 g_WVh [KKB*DD*DD],   g_WVl [KKB*DD*DD];
__device__ __align__(16) bf16 g_WOh [KKB*DD*DD],   g_WOl [KKB*DD*DD];
__device__ __align__(16) bf16 g_WUh [(size_t)KKB*DD*2*INNER], g_WUl [(size_t)KKB*DD*2*INNER];
__device__ __align__(16) bf16 g_WDh [(size_t)KKB*INNER*DD],   g_WDl [(size_t)KKB*INNER*DD];
__device__ __align__(16) bf16 g_LMh [(size_t)VV*DD], g_LMl [(size_t)VV*DD];

// ---------------- helpers ----------------------------------------------------
__device__ __forceinline__ float siluf(float x) { return x / (1.0f + expf(-x)); }

__device__ __forceinline__ bool read_halted(const void* p, int b)
{
    const unsigned char* u8 = (const unsigned char*)p;
    if (u8[1] != 0) return u8[b] != 0;
    return ((const int*)p)[b] != 0;
}
__device__ __forceinline__ uint32_t smem_u32(const void* p) {
    uint32_t a;
    asm("{ .reg .u64 t; cvta.to.shared.u64 t, %1; cvt.u32.u64 %0, t; }"
        : "=r"(a) : "l"(p));
    return a;
}
__device__ __forceinline__ void ldm4(uint32_t* r, uint32_t a) {
    asm volatile("ldmatrix.sync.aligned.m8n8.x4.shared.b16 {%0,%1,%2,%3}, [%4];"
                 : "=r"(r[0]), "=r"(r[1]), "=r"(r[2]), "=r"(r[3]) : "r"(a));
}
__device__ __forceinline__ void ldm4t(uint32_t* r, uint32_t a) {
    asm volatile("ldmatrix.sync.aligned.m8n8.x4.trans.shared.b16 {%0,%1,%2,%3}, [%4];"
                 : "=r"(r[0]), "=r"(r[1]), "=r"(r[2]), "=r"(r[3]) : "r"(a));
}
__device__ __forceinline__ void mma_bf16(float* c, const uint32_t* a, const uint32_t* b) {
    asm volatile("mma.sync.aligned.m16n8k16.row.col.f32.bf16.bf16.f32 "
                 "{%0,%1,%2,%3}, {%4,%5,%6,%7}, {%8,%9}, {%0,%1,%2,%3};"
                 : "+f"(c[0]), "+f"(c[1]), "+f"(c[2]), "+f"(c[3])
                 : "r"(a[0]), "r"(a[1]), "r"(a[2]), "r"(a[3]),
                   "r"(b[0]), "r"(b[1]));
}
__device__ __forceinline__ uint32_t pack2(bf16 a, bf16 b) {
    return (uint32_t)__bfloat16_as_ushort(a) |
           ((uint32_t)__bfloat16_as_ushort(b) << 16);
}
__device__ __forceinline__ void split1(float v, bf16& h, bf16& l) {
    h = __float2bfloat16(v);
    l = __float2bfloat16(v - __bfloat162float(h));
}

// ---------------- weight/activation converter --------------------------------
__global__ void cvt_kernel(const float* __restrict__ src, bf16* __restrict__ h,
                           bf16* __restrict__ l, int n4)
{
    int i = blockIdx.x * 256 + threadIdx.x;
    if (i >= n4) return;
    float4 v = *(const float4*)(src + (size_t)i * 4);
    bf16 h0, h1, h2, h3, l0, l1, l2, l3;
    split1(v.x, h0, l0); split1(v.y, h1, l1);
    split1(v.z, h2, l2); split1(v.w, h3, l3);
    *(uint2*)(h + (size_t)i * 4) = make_uint2(pack2(h0, h1), pack2(h2, h3));
    *(uint2*)(l + (size_t)i * 4) = make_uint2(pack2(l0, l1), pack2(l2, l3));
}

// ---------------- generic pre-split bf16x3 GEMM body -------------------------
// A: hi/lo [M,K] row-major; B: hi/lo [K,N] row-major (trans-B via ldmatrix.trans)
// epi: 0 fp32 plain, 1 hi/lo elu+1, 2 fp32 addP+alpha*acc, 3 fp32 addP+acc, 4 hi/lo plain
__device__ __forceinline__ void gemm_body(
    bf16* sAh, bf16* sAl, bf16* sBh, bf16* sBl,
    const bf16* __restrict__ Ah, const bf16* __restrict__ Al, int lda,
    const bf16* __restrict__ Bh, const bf16* __restrict__ Bl, int ldb,
    float* __restrict__ Cf, bf16* __restrict__ Ch, bf16* __restrict__ Cl, int ldc,
    int m0, int n0, int kch, int epi, const float* __restrict__ addP, float alpha)
{
    const int tid = threadIdx.x, lane = tid & 31, wid = tid >> 5;
    const int warp_m = wid >> 1, warp_n = wid & 1;
    const uint32_t uAh = smem_u32(sAh), uAl = smem_u32(sAl);
    const uint32_t uBh = smem_u32(sBh), uBl = smem_u32(sBl);

    float acc[2][8][4];
    #pragma unroll
    for (int i = 0; i < 2; i++)
        #pragma unroll
        for (int j = 0; j < 8; j++)
            #pragma unroll
            for (int q = 0; q < 4; q++) acc[i][j][q] = 0.0f;

    for (int kc = 0; kc < kch; kc++) {
        #pragma unroll
        for (int it = 0; it < 2; it++) {
            int g = tid + 256 * it;
            int row = g >> 2, c8 = (g & 3) * 8;
            size_t go = (size_t)(m0 + row) * lda + kc * 32 + c8;
            *(uint4*)(sAh + row * AMS + c8) = *(const uint4*)(Ah + go);
            *(uint4*)(sAl + row * AMS + c8) = *(const uint4*)(Al + go);
        }
        #pragma unroll
        for (int it = 0; it < 2; it++) {
            int g = tid + 256 * it;
            int row = g >> 4, c8 = (g & 15) * 8;
            size_t go = (size_t)(kc * 32 + row) * ldb + n0 + c8;
            *(uint4*)(sBh + row * BNS + c8) = *(const uint4*)(Bh + go);
            *(uint4*)(sBl + row * BNS + c8) = *(const uint4*)(Bl + go);
        }
        __syncthreads();

        #pragma unroll
        for (int s = 0; s < 2; s++) {
            uint32_t ah[2][4], al[2][4], bh[8][2], bl[8][2];
            #pragma unroll
            for (int i = 0; i < 2; i++) {
                int r  = warp_m * 32 + i * 16 + (lane & 15);
                int kb = s * 16 + ((lane >> 4) << 3);
                uint32_t off = (uint32_t)(r * AMS + kb) * 2;
                ldm4(ah[i], uAh + off);
                ldm4(al[i], uAl + off);
            }
            #pragma unroll
            for (int j = 0; j < 4; j++) {
                int kk = s * 16 + (lane & 7) + ((lane >> 3) & 1) * 8;
                int nn = warp_n * 64 + j * 16 + (lane >> 4) * 8;
                uint32_t off = (uint32_t)(kk * BNS + nn) * 2;
                uint32_t q[4];
                ldm4t(q, uBh + off);
                bh[2*j][0] = q[0]; bh[2*j][1] = q[1];
                bh[2*j+1][0] = q[2]; bh[2*j+1][1] = q[3];
                ldm4t(q, uBl + off);
                bl[2*j][0] = q[0]; bl[2*j][1] = q[1];
                bl[2*j+1][0] = q[2]; bl[2*j+1][1] = q[3];
            }
            #pragma unroll
            for (int i = 0; i < 2; i++)
                #pragma unroll
                for (int j = 0; j < 8; j++) {
                    mma_bf16(acc[i][j], ah[i], bh[j]);
                    mma_bf16(acc[i][j], al[i], bh[j]);
                    mma_bf16(acc[i][j], ah[i], bl[j]);
                }
        }
        __syncthreads();
    }

    #pragma unroll
    for (int i = 0; i < 2; i++) {
        int m = m0 + warp_m * 32 + i * 16 + (lane >> 2);
        #pragma unroll
        for (int j = 0; j < 8; j++) {
            int n = n0 + warp_n * 64 + j * 8 + (lane & 3) * 2;
            float v0 = acc[i][j][0], v1 = acc[i][j][1];
            float v2 = acc[i][j][2], v3 = acc[i][j][3];
            size_t i0 = (size_t)m * ldc + n;
            size_t i1 = (size_t)(m + 8) * ldc + n;
            if (epi == 1 || epi == 4) {
                if (epi == 1) {
                    v0 = (v0 > 0.f) ? v0 + 1.f : expf(v0);
                    v1 = (v1 > 0.f) ? v1 + 1.f : expf(v1);
                    v2 = (v2 > 0.f) ? v2 + 1.f : expf(v2);
                    v3 = (v3 > 0.f) ? v3 + 1.f : expf(v3);
                }
                bf16 h0, h1, h2, h3, l0, l1, l2, l3;
                split1(v0, h0, l0); split1(v1, h1, l1);
                split1(v2, h2, l2); split1(v3, h3, l3);
                *(uint32_t*)(Ch + i0) = pack2(h0, h1);
                *(uint32_t*)(Cl + i0) = pack2(l0, l1);
                *(uint32_t*)(Ch + i1) = pack2(h2, h3);
                *(uint32_t*)(Cl + i1) = pack2(l2, l3);
            } else {
                if (epi == 2) {
                    v0 = addP[i0] + alpha * v0; v1 = addP[i0+1] + alpha * v1;
                    v2 = addP[i1] + alpha * v2; v3 = addP[i1+1] + alpha * v3;
                } else if (epi == 3) {
                    v0 += addP[i0]; v1 += addP[i0+1];
                    v2 += addP[i1]; v3 += addP[i1+1];
                }
                *(float2*)(Cf + i0) = make_float2(v0, v1);
                *(float2*)(Cf + i1) = make_float2(v2, v3);
            }
        }
    }
}

// ---------------- GEMM wrappers ----------------------------------------------
__global__ void __launch_bounds__(256) mma_proj(
    const bf16* __restrict__ Ah, const bf16* __restrict__ Al, int kIdx)
{
    __shared__ __align__(16) bf16 sAh[128*AMS], sAl[128*AMS];
    __shared__ __align__(16) bf16 sBh[32*BNS],  sBl[32*BNS];
    int z = blockIdx.z;
    size_t wo = (size_t)kIdx * DD * DD;
    const bf16* Bh = (z == 0) ? g_WQh + wo : (z == 1) ? g_WKh + wo : g_WVh + wo;
    const bf16* Bl = (z == 0) ? g_WQl + wo : (z == 1) ? g_WKl + wo : g_WVl + wo;
    bf16* Ch = (z == 0) ? g_PQh : (z == 1) ? g_PKh : g_Vh;
    bf16* Cl = (z == 0) ? g_PQl : (z == 1) ? g_PKl : g_Vl;
    gemm_body(sAh, sAl, sBh, sBl, Ah, Al, DD, Bh, Bl, DD,
              nullptr, Ch, Cl, DD, blockIdx.y * 128, blockIdx.x * 128,
              DD / 32, (z < 2) ? 1 : 4, nullptr, 0.f);
}

__global__ void __launch_bounds__(256) mma_wo(
    const bf16* __restrict__ Ah, const bf16* __restrict__ Al, int kIdx,
    float* __restrict__ C, const float* __restrict__ addP,
    const float* __restrict__ dt)
{
    __shared__ __align__(16) bf16 sAh[128*AMS], sAl[128*AMS];
    __shared__ __align__(16) bf16 sBh[32*BNS],  sBl[32*BNS];
    size_t wo = (size_t)kIdx * DD * DD;
    float d = dt[kIdx];
    float alpha = (d > 20.0f) ? d : log1pf(expf(d));
    gemm_body(sAh, sAl, sBh, sBl, Ah, Al, DD, g_WOh + wo, g_WOl + wo, DD,
              C, nullptr, nullptr, DD, blockIdx.y * 128, blockIdx.x * 128,
              DD / 32, 2, addP, alpha);
}

__global__ void __launch_bounds__(256) mma_up(
    const bf16* __restrict__ Ah, const bf16* __restrict__ Al, int kIdx,
    float* __restrict__ C)
{
    __shared__ __align__(16) bf16 sAh[128*AMS], sAl[128*AMS];
    __shared__ __align__(16) bf16 sBh[32*BNS],  sBl[32*BNS];
    size_t wo = (size_t)kIdx * DD * 2 * INNER;
    gemm_body(sAh, sAl, sBh, sBl, Ah, Al, DD, g_WUh + wo, g_WUl + wo, 2 * INNER,
              C, nullptr, nullptr, 2 * INNER, blockIdx.y * 128, blockIdx.x * 128,
              DD / 32, 0, nullptr, 0.f);
}

__global__ void __launch_bounds__(256) mma_down(
    const bf16* __restrict__ Ah, const bf16* __restrict__ Al, int kIdx,
    float* __restrict__ C, const float* __restrict__ addP)
{
    __shared__ __align__(16) bf16 sAh[128*AMS], sAl[128*AMS];
    __shared__ __align__(16) bf16 sBh[32*BNS],  sBl[32*BNS];
    size_t wo = (size_t)kIdx * INNER * DD;
    gemm_body(sAh, sAl, sBh, sBl, Ah, Al, INNER, g_WDh + wo, g_WDl + wo, DD,
              C, nullptr, nullptr, DD, blockIdx.y * 128, blockIdx.x * 128,
              INNER / 32, 3, addP, 0.f);
}

// ---------------- fused flash attention --------------------------------------
// grid (NN/128, BHN). Per CTA: q-tile 128 rows of one (b,h).
// m = (W@V)/(rowsum+1) - V  with W = relu(PhiQ.PhiK)^2, never materialized.
#define ATT_SMEM (6 * 128 * QS * 2)
__global__ void __launch_bounds__(256) attn_fused(
    const bf16* __restrict__ PQh, const bf16* __restrict__ PQl,
    const bf16* __restrict__ PKh, const bf16* __restrict__ PKl,
    const bf16* __restrict__ Vh,  const bf16* __restrict__ Vl,
    bf16* __restrict__ Mh, bf16* __restrict__ Ml)
{
    extern __shared__ __align__(16) bf16 smem[];
    bf16* sQh = smem;
    bf16* sQl = sQh + 128 * QS;
    bf16* sKh = sQl + 128 * QS;
    bf16* sKl = sKh + 128 * QS;
    bf16* sVh = sKl + 128 * QS;
    bf16* sVl = sVh + 128 * QS;

    const int tid = threadIdx.x, lane = tid & 31, w = tid >> 5;
    const int bh = blockIdx.y, b = bh >> 3, h = bh & 7;
    const int q0 = blockIdx.x * 128;
    const size_t rowbase = (size_t)(b * NN) * DD + h * DH;
    const uint32_t uQh = smem_u32(sQh), uQl = smem_u32(sQl);
    const uint32_t uKh = smem_u32(sKh), uKl = smem_u32(sKl);
    const uint32_t uVh = smem_u32(sVh), uVl = smem_u32(sVl);

    // stage Q tile
    #pragma unroll
    for (int it = 0; it < 4; it++) {
        int g = tid + 256 * it;
        int row = g >> 3, c8 = (g & 7) * 8;
        size_t go = rowbase + (size_t)(q0 + row) * DD + c8;
        *(uint4*)(sQh + row * QS + c8) = *(const uint4*)(PQh + go);
        *(uint4*)(sQl + row * QS + c8) = *(const uint4*)(PQl + go);
    }
    __syncthreads();

    // Q fragments to registers (per warp: rows w*16..+15)
    uint32_t qh[4][4], ql[4][4];
    #pragma unroll
    for (int s = 0; s < 4; s++) {
        int r  = w * 16 + (lane & 15);
        int kb = s * 16 + ((lane >> 4) << 3);
        uint32_t off = (uint32_t)(r * QS + kb) * 2;
        ldm4(qh[s], uQh + off);
        ldm4(ql[s], uQl + off);
    }

    float oacc[8][4];
    #pragma unroll
    for (int j = 0; j < 8; j++)
        #pragma unroll
        for (int q = 0; q < 4; q++) oacc[j][q] = 0.0f;
    float p0 = 0.0f, p1 = 0.0f;

    for (int kt = 0; kt < NN / 128; kt++) {
        __syncthreads();
        #pragma unroll
        for (int it = 0; it < 4; it++) {
            int g = tid + 256 * it;
            int row = g >> 3, c8 = (g & 7) * 8;
            size_t go = rowbase + (size_t)(kt * 128 + row) * DD + c8;
            *(uint4*)(sKh + row * QS + c8) = *(const uint4*)(PKh + go);
            *(uint4*)(sKl + row * QS + c8) = *(const uint4*)(PKl + go);
            *(uint4*)(sVh + row * QS + c8) = *(const uint4*)(Vh + go);
            *(uint4*)(sVl + row * QS + c8) = *(const uint4*)(Vl + go);
        }
        __syncthreads();

        #pragma unroll
        for (int t = 0; t < 8; t++) {
            // S tile: m16 x n16 (keys t*16..t*16+15)
            float sacc[2][4] = {};
            #pragma unroll
            for (int s = 0; s < 4; s++) {
                int r  = t * 16 + (lane & 7) + ((lane >> 4) << 3);
                int kb = s * 16 + (((lane >> 3) & 1) << 3);
                uint32_t off = (uint32_t)(r * QS + kb) * 2;
                uint32_t kh[4], kl[4];
                ldm4(kh, uKh + off);
                ldm4(kl, uKl + off);
                mma_bf16(sacc[0], qh[s], kh + 0);
                mma_bf16(sacc[0], ql[s], kh + 0);
                mma_bf16(sacc[0], qh[s], kl + 0);
                mma_bf16(sacc[1], qh[s], kh + 2);
                mma_bf16(sacc[1], ql[s], kh + 2);
                mma_bf16(sacc[1], qh[s], kl + 2);
            }
            // relu^2 + rowsum + split into A-fragments for W@V
            float w2[2][4];
            #pragma unroll
            for (int f = 0; f < 2; f++)
                #pragma unroll
                for (int q = 0; q < 4; q++) {
                    float x = fmaxf(sacc[f][q], 0.0f);
                    w2[f][q] = x * x;
                }
            p0 += w2[0][0] + w2[0][1] + w2[1][0] + w2[1][1];
            p1 += w2[0][2] + w2[0][3] + w2[1][2] + w2[1][3];
            uint32_t wh[4], wl[4];
            {
                bf16 h0, h1, l0, l1;
                split1(w2[0][0], h0, l0); split1(w2[0][1], h1, l1);
                wh[0] = pack2(h0, h1); wl[0] = pack2(l0, l1);
                split1(w2[0][2], h0, l0); split1(w2[0][3], h1, l1);
                wh[1] = pack2(h0, h1); wl[1] = pack2(l0, l1);
                split1(w2[1][0], h0, l0); split1(w2[1][1], h1, l1);
                wh[2] = pack2(h0, h1); wl[2] = pack2(l0, l1);
                split1(w2[1][2], h0, l0); split1(w2[1][3], h1, l1);
                wh[3] = pack2(h0, h1); wl[3] = pack2(l0, l1);
            }
            // O += W @ V for this k16 slab
            #pragma unroll
            for (int n = 0; n < 4; n++) {
                int kk = t * 16 + (lane & 7) + ((lane >> 3) & 1) * 8;
                int nn = n * 16 + (lane >> 4) * 8;
                uint32_t off = (uint32_t)(kk * QS + nn) * 2;
                uint32_t vh[4], vl[4];
                ldm4t(vh, uVh + off);
                ldm4t(vl, uVl + off);
                mma_bf16(oacc[2*n],   wh, vh + 0);
                mma_bf16(oacc[2*n],   wl, vh + 0);
                mma_bf16(oacc[2*n],   wh, vl + 0);
                mma_bf16(oacc[2*n+1], wh, vh + 2);
                mma_bf16(oacc[2*n+1], wl, vh + 2);
                mma_bf16(oacc[2*n+1], wh, vl + 2);
            }
        }
    }

    // rowsum reduce across the quad (cols live on lane&3)
    p0 += __shfl_xor_sync(0xFFFFFFFFu, p0, 1);
    p0 += __shfl_xor_sync(0xFFFFFFFFu, p0, 2);
    p1 += __shfl_xor_sync(0xFFFFFFFFu, p1, 1);
    p1 += __shfl_xor_sync(0xFFFFFFFFu, p1, 2);
    float rd0 = 1.0f / (p0 + 1.0f);
    float rd1 = 1.0f / (p1 + 1.0f);

    int r0 = q0 + w * 16 + (lane >> 2);
    int r1 = r0 + 8;
    #pragma unroll
    for (int j = 0; j < 8; j++) {
        int d = j * 8 + (lane & 3) * 2;
        size_t i0 = rowbase + (size_t)r0 * DD + d;
        size_t i1 = rowbase + (size_t)r1 * DD + d;
        uint32_t vh0 = *(const uint32_t*)(Vh + i0), vl0 = *(const uint32_t*)(Vl + i0);
        uint32_t vh1 = *(const uint32_t*)(Vh + i1), vl1 = *(const uint32_t*)(Vl + i1);
        float vp00 = __bfloat162float(__ushort_as_bfloat16((unsigned short)(vh0 & 0xFFFF))) +
                     __bfloat162float(__ushort_as_bfloat16((unsigned short)(vl0 & 0xFFFF)));
        float vp01 = __bfloat162float(__ushort_as_bfloat16((unsigned short)(vh0 >> 16))) +
                     __bfloat162float(__ushort_as_bfloat16((unsigned short)(vl0 >> 16)));
        float vp10 = __bfloat162float(__ushort_as_bfloat16((unsigned short)(vh1 & 0xFFFF))) +
                     __bfloat162float(__ushort_as_bfloat16((unsigned short)(vl1 & 0xFFFF)));
        float vp11 = __bfloat162float(__ushort_as_bfloat16((unsigned short)(vh1 >> 16))) +
                     __bfloat162float(__ushort_as_bfloat16((unsigned short)(vl1 >> 16)));
        float m00 = oacc[j][0] * rd0 - vp00;
        float m01 = oacc[j][1] * rd0 - vp01;
        float m10 = oacc[j][2] * rd1 - vp10;
        float m11 = oacc[j][3] * rd1 - vp11;
        bf16 h0, h1, l0, l1;
        split1(m00, h0, l0); split1(m01, h1, l1);
        *(uint32_t*)(Mh + i0) = pack2(h0, h1);
        *(uint32_t*)(Ml + i0) = pack2(l0, l1);
        split1(m10, h0, l0); split1(m11, h1, l1);
        *(uint32_t*)(Mh + i1) = pack2(h0, h1);
        *(uint32_t*)(Ml + i1) = pack2(l0, l1);
    }
}

// ---------------- LM head (pre-split NT GEMM) --------------------------------
__global__ void __launch_bounds__(256)
lm_head_mma(const bf16* __restrict__ Ah, const bf16* __restrict__ Al,
            float* __restrict__ C)
{
    __shared__ __align__(16) bf16 sAh[128*AMS], sAl[128*AMS];
    __shared__ __align__(16) bf16 sBh[128*AMS], sBl[128*AMS];
    const int tid = threadIdx.x, lane = tid & 31, wid = tid >> 5;
    const int warp_m = wid >> 1, warp_n = wid & 1;
    const int m0 = blockIdx.y * 128, n0 = blockIdx.x * 128;
    const uint32_t uAh = smem_u32(sAh), uAl = smem_u32(sAl);
    const uint32_t uBh = smem_u32(sBh), uBl = smem_u32(sBl);

    float acc[2][8][4];
    #pragma unroll
    for (int i = 0; i < 2; i++)
        #pragma unroll
        for (int j = 0; j < 8; j++)
            #pragma unroll
            for (int q = 0; q < 4; q++) acc[i][j][q] = 0.0f;

    for (int kc = 0; kc < 16; kc++) {
        #pragma unroll
        for (int it = 0; it < 2; it++) {
            int g = tid + 256 * it;
            int row = g >> 2, c8 = (g & 3) * 8;
            size_t ga = (size_t)(m0 + row) * DD + kc * 32 + c8;
            size_t gb = (size_t)(n0 + row) * DD + kc * 32 + c8;
            *(uint4*)(sAh + row * AMS + c8) = *(const uint4*)(Ah + ga);
            *(uint4*)(sAl + row * AMS + c8) = *(const uint4*)(Al + ga);
            *(uint4*)(sBh + row * AMS + c8) = *(const uint4*)(g_LMh + gb);
            *(uint4*)(sBl + row * AMS + c8) = *(const uint4*)(g_LMl + gb);
        }
        __syncthreads();

        #pragma unroll
        for (int s = 0; s < 2; s++) {
            uint32_t ah[2][4], al[2][4], bh[8][2], bl[8][2];
            #pragma unroll
            for (int i = 0; i < 2; i++) {
                int r  = warp_m * 32 + i * 16 + (lane & 15);
                int kb = s * 16 + ((lane >> 4) << 3);
                uint32_t off = (uint32_t)(r * AMS + kb) * 2;
                ldm4(ah[i], uAh + off);
                ldm4(al[i], uAl + off);
            }
            #pragma unroll
            for (int j = 0; j < 4; j++) {
                int r  = warp_n * 64 + j * 16 + (lane & 7) + ((lane >> 4) << 3);
                int kb = s * 16 + (((lane >> 3) & 1) << 3);
                uint32_t off = (uint32_t)(r * AMS + kb) * 2;
                uint32_t q[4];
                ldm4(q, uBh + off);
                bh[2*j][0] = q[0]; bh[2*j][1] = q[1];
                bh[2*j+1][0] = q[2]; bh[2*j+1][1] = q[3];
                ldm4(q, uBl + off);
                bl[2*j][0] = q[0]; bl[2*j][1] = q[1];
                bl[2*j+1][0] = q[2]; bl[2*j+1][1] = q[3];
            }
            #pragma unroll
            for (int i = 0; i < 2; i++)
                #pragma unroll
                for (int j = 0; j < 8; j++) {
                    mma_bf16(acc[i][j], ah[i], bh[j]);
                    mma_bf16(acc[i][j], al[i], bh[j]);
                    mma_bf16(acc[i][j], ah[i], bl[j]);
                }
        }
        __syncthreads();
    }

    #pragma unroll
    for (int i = 0; i < 2; i++) {
        int m = m0 + warp_m * 32 + i * 16 + (lane >> 2);
        #pragma unroll
        for (int j = 0; j < 8; j++) {
            int n = n0 + warp_n * 64 + j * 8 + (lane & 3) * 2;
            *(float2*)(C + (size_t)m * VV + n) =
                make_float2(acc[i][j][0], acc[i][j][1]);
            *(float2*)(C + (size_t)(m + 8) * VV + n) =
                make_float2(acc[i][j][2], acc[i][j][3]);
        }
    }
}

// ---------------- init -------------------------------------------------------
__global__ void init_kernel(const int* __restrict__ inputs,
                            const int* __restrict__ carry_inputs,
                            const void* __restrict__ halted,
                            const float* __restrict__ carry_hidden,
                            const float* __restrict__ init_hidden,
                            const float* __restrict__ emb,
                            const float* __restrict__ pos,
                            const float* __restrict__ in_s,
                            const float* __restrict__ in_b)
{
    int r = blockIdx.x;
    int b = r / NN, n = r % NN;
    int t = threadIdx.x;
    bool h = read_halted(halted, b);
    int idx = h ? inputs[r] : carry_inputs[r];
    const float* e = emb + (size_t)idx * DD;
    const float* p = pos + (size_t)n * DD;

    float x0 = e[t]       + p[t];
    float x1 = e[t + 256] + p[t + 256];

    size_t base = (size_t)r * DD;
    g_Q[base + t]       = h ? init_hidden[t]       : carry_hidden[base + t];
    g_Q[base + t + 256] = h ? init_hidden[t + 256] : carry_hidden[base + t + 256];

    __shared__ float s_sum[256], s_sq[256];
    s_sum[t] = x0 + x1;
    s_sq[t]  = x0 * x0 + x1 * x1;
    __syncthreads();
    for (int o = 128; o > 0; o >>= 1) {
        if (t < o) { s_sum[t] += s_sum[t + o]; s_sq[t] += s_sq[t + o]; }
        __syncthreads();
    }
    float mu   = s_sum[0] * (1.0f / DD);
    float var  = s_sq[0] * (1.0f / DD) - mu * mu;
    float rstd = rsqrtf(var + 1e-5f);
    g_X[base + t]       = (x0 - mu) * rstd * in_s[t]       + in_b[t];
    g_X[base + t + 256] = (x1 - mu) * rstd * in_s[t + 256] + in_b[t + 256];
}

// ---------------- LayerNorm (fp32 in; optional fp32 out; optional hi/lo) -----
__global__ void ln_kernel(const float* __restrict__ in, float* __restrict__ outf,
                          bf16* __restrict__ outh, bf16* __restrict__ outl,
                          const float* __restrict__ s, const float* __restrict__ bia,
                          const float* __restrict__ add)
{
    int r = blockIdx.x;
    int t = threadIdx.x;
    size_t base = (size_t)r * DD;
    float x0 = in[base + t];
    float x1 = in[base + t + 256];

    __shared__ float s_sum[256], s_sq[256];
    s_sum[t] = x0 + x1;
    s_sq[t]  = x0 * x0 + x1 * x1;
    __syncthreads();
    for (int o = 128; o > 0; o >>= 1) {
        if (t < o) { s_sum[t] += s_sum[t + o]; s_sq[t] += s_sq[t + o]; }
        __syncthreads();
    }
    float mu   = s_sum[0] * (1.0f / DD);
    float var  = s_sq[0] * (1.0f / DD) - mu * mu;
    float rstd = rsqrtf(var + 1e-5f);
    float v0 = (x0 - mu) * rstd * s[t]       + bia[t];
    float v1 = (x1 - mu) * rstd * s[t + 256] + bia[t + 256];
    if (add) { v0 += add[base + t]; v1 += add[base + t + 256]; }
    if (outf) { outf[base + t] = v0; outf[base + t + 256] = v1; }
    if (outh) {
        bf16 h0, l0, h1, l1;
        split1(v0, h0, l0); split1(v1, h1, l1);
        outh[base + t] = h0;       outl[base + t] = l0;
        outh[base + t + 256] = h1; outl[base + t + 256] = l1;
    }
}

// ---------------- SwiGLU -----------------------------------------------------
__global__ void swiglu_kernel(const float* __restrict__ GU, float* __restrict__ Hf)
{
    size_t i = (size_t)blockIdx.x * 256 + threadIdx.x;
    if (i >= (size_t)MROWS * INNER) return;
    size_t row = i / INNER;
    int c = (int)(i % INNER);
    float g = GU[row * (2 * INNER) + c];
    float u = GU[row * (2 * INNER) + INNER + c];
    Hf[i] = siluf(g) * u;
}

// ---------------- depthwise conv k=3 + bias + silu -> hi/lo ------------------
__global__ void conv_kernel(const float* __restrict__ Hf, const float* __restrict__ w,
                            const float* __restrict__ bias,
                            bf16* __restrict__ outh, bf16* __restrict__ outl)
{
    size_t i = (size_t)blockIdx.x * 256 + threadIdx.x;
    if (i >= (size_t)MROWS * INNER) return;
    size_t row = i / INNER;
    int c = (int)(i % INNER);
    int n = (int)(row % NN);
    const float* wc = w + (size_t)c * CKW;
    float acc = bias[c];
    if (n > 0)      acc += wc[0] * Hf[(row - 1) * INNER + c];
    acc += wc[1] * Hf[row * INNER + c];
    if (n < NN - 1) acc += wc[2] * Hf[(row + 1) * INNER + c];
    float v = siluf(acc);
    bf16 h, l;
    split1(v, h, l);
    outh[i] = h;
    outl[i] = l;
}

// ---------------- halt head --------------------------------------------------
__global__ void halt_kernel(const float* __restrict__ Qn, const float* __restrict__ hw,
                            const float* __restrict__ hb, float* __restrict__ out)
{
    int b = blockIdx.x;
    int t = threadIdx.x;
    __shared__ float md[DD];
    for (int d = t; d < DD; d += 256) {
        float s = 0.0f;
        for (int n = 0; n < NN; n++)
            s += Qn[((size_t)(b * NN + n)) * DD + d];
        md[d] = s * (1.0f / NN);
    }
    __syncthreads();
    __shared__ float r0[256], r1[256];
    float p0 = 0.0f, p1 = 0.0f;
    for (int d = t; d < DD; d += 256) {
        p0 += md[d] * hw[d];
        p1 += md[d] * hw[DD + d];
    }
    r0[t] = p0; r1[t] = p1;
    __syncthreads();
    for (int o = 128; o > 0; o >>= 1) {
        if (t < o) { r0[t] += r0[t + o]; r1[t] += r1[t + o]; }
        __syncthreads();
    }
    if (t == 0) {
        out[b * 2 + 0] = r0[0] + hb[0];
        out[b * 2 + 1] = r1[0] + hb[1];
    }
}

// ---------------- host orchestration -----------------------------------------
static void cvt(const float* src, bf16* h, bf16* l, size_t n)
{
    int n4 = (int)(n / 4);
    cvt_kernel<<<(n4 + 255) / 256, 256>>>(src, h, l, n4);
}

extern "C" void kernel_launch(void* const* d_in, const int* in_sizes, int n_in,
                              void* d_out, int out_size)
{
    const int*   inputs       = (const int*)d_in[0];
    const float* carry_hidden = (const float*)d_in[2];
    const void*  halted       = d_in[4];
    const int*   carry_inputs = (const int*)d_in[5];
    const float* init_hidden  = (const float*)d_in[7];
    const float* emb          = (const float*)d_in[8];
    const float* pos          = (const float*)d_in[9];
    const float* in_s         = (const float*)d_in[10];
    const float* in_b         = (const float*)d_in[11];
    const float* fin_s        = (const float*)d_in[12];
    const float* fin_b        = (const float*)d_in[13];
    const float* lm_w         = (const float*)d_in[14];
    const float* halt_w       = (const float*)d_in[15];
    const float* halt_b       = (const float*)d_in[16];
    const float* dt           = (const float*)d_in[17];
    const float* W_Q          = (const float*)d_in[18];
    const float* W_K          = (const float*)d_in[19];
    const float* W_V          = (const float*)d_in[20];
    const float* W_O          = (const float*)d_in[21];
    const float* W_up         = (const float*)d_in[22];
    const float* dw_w         = (const float*)d_in[23];
    const float* dw_b         = (const float*)d_in[24];
    const float* W_down       = (const float*)d_in[25];
    const float* n1_s         = (const float*)d_in[26];
    const float* n1_b         = (const float*)d_in[27];
    const float* n2_s         = (const float*)d_in[28];
    const float* n2_b         = (const float*)d_in[29];

    // device symbol addresses
    float *X, *Q, *Qi, *Qn, *GU, *Hf;
    bf16 *Hch, *Hcl, *PQh, *PQl, *PKh, *PKl, *Vh, *Vl, *mbh, *mbl;
    bf16 *Q2h, *Q2l, *Hvh, *Hvl, *Qnh, *Qnl;
    bf16 *WQh, *WQl, *WKh, *WKl, *WVh, *WVl, *WOh, *WOl;
    bf16 *WUh, *WUl, *WDh, *WDl, *LMh, *LMl;
    cudaGetSymbolAddress((void**)&X,   g_X);
    cudaGetSymbolAddress((void**)&Q,   g_Q);
    cudaGetSymbolAddress((void**)&Qi,  g_Qi);
    cudaGetSymbolAddress((void**)&Qn,  g_Qn);
    cudaGetSymbolAddress((void**)&GU,  g_GU);
    cudaGetSymbolAddress((void**)&Hf,  g_Hf);
    cudaGetSymbolAddress((void**)&Hch, g_Hch); cudaGetSymbolAddress((void**)&Hcl, g_Hcl);
    cudaGetSymbolAddress((void**)&PQh, g_PQh); cudaGetSymbolAddress((void**)&PQl, g_PQl);
    cudaGetSymbolAddress((void**)&PKh, g_PKh); cudaGetSymbolAddress((void**)&PKl, g_PKl);
    cudaGetSymbolAddress((void**)&Vh,  g_Vh);  cudaGetSymbolAddress((void**)&Vl,  g_Vl);
    cudaGetSymbolAddress((void**)&mbh, g_mbh); cudaGetSymbolAddress((void**)&mbl, g_mbl);
    cudaGetSymbolAddress((void**)&Q2h, g_Q2h); cudaGetSymbolAddress((void**)&Q2l, g_Q2l);
    cudaGetSymbolAddress((void**)&Hvh, g_Hvh); cudaGetSymbolAddress((void**)&Hvl, g_Hvl);
    cudaGetSymbolAddress((void**)&Qnh, g_Qnh); cudaGetSymbolAddress((void**)&Qnl, g_Qnl);
    cudaGetSymbolAddress((void**)&WQh, g_WQh); cudaGetSymbolAddress((void**)&WQl, g_WQl);
    cudaGetSymbolAddress((void**)&WKh, g_WKh); cudaGetSymbolAddress((void**)&WKl, g_WKl);
    cudaGetSymbolAddress((void**)&WVh, g_WVh); cudaGetSymbolAddress((void**)&WVl, g_WVl);
    cudaGetSymbolAddress((void**)&WOh, g_WOh); cudaGetSymbolAddress((void**)&WOl, g_WOl);
    cudaGetSymbolAddress((void**)&WUh, g_WUh); cudaGetSymbolAddress((void**)&WUl, g_WUl);
    cudaGetSymbolAddress((void**)&WDh, g_WDh); cudaGetSymbolAddress((void**)&WDl, g_WDl);
    cudaGetSymbolAddress((void**)&LMh, g_LMh); cudaGetSymbolAddress((void**)&LMl, g_LMl);

    float* out = (float*)d_out;

    cudaFuncSetAttribute(attn_fused, cudaFuncAttributeMaxDynamicSharedMemorySize,
                         ATT_SMEM);

    // one-time (per launch) weight pre-split
    cvt(W_Q,    WQh, WQl, (size_t)KKB * DD * DD);
    cvt(W_K,    WKh, WKl, (size_t)KKB * DD * DD);
    cvt(W_V,    WVh, WVl, (size_t)KKB * DD * DD);
    cvt(W_O,    WOh, WOl, (size_t)KKB * DD * DD);
    cvt(W_up,   WUh, WUl, (size_t)KKB * DD * 2 * INNER);
    cvt(W_down, WDh, WDl, (size_t)KKB * INNER * DD);
    cvt(lm_w,   LMh, LMl, (size_t)VV * DD);

    init_kernel<<<MROWS, 256>>>(inputs, carry_inputs, halted, carry_hidden,
                                init_hidden, emb, pos, in_s, in_b);

    dim3 gP(DD / 128, MROWS / 128, 3);        // (4, 16, 3)
    dim3 gO(DD / 128, MROWS / 128);           // (4, 16)
    dim3 gUP(2 * INNER / 128, MROWS / 128);   // (24, 16)
    dim3 gAT(NN / 128, BHN);                  // (8, 16)

    for (int it = 0; it < TOTAL_PASSES; it++) {
        int k = it % KKB;

        ln_kernel<<<MROWS, 256>>>(Q, nullptr, Hch, Hcl,
                                  n1_s + k * DD, n1_b + k * DD, X);

        mma_proj<<<gP, 256>>>(Hch, Hcl, k);

        attn_fused<<<gAT, 256, ATT_SMEM>>>(PQh, PQl, PKh, PKl, Vh, Vl, mbh, mbl);

        mma_wo<<<gO, 256>>>(mbh, mbl, k, Qi, Q, dt);

        ln_kernel<<<MROWS, 256>>>(Qi, nullptr, Q2h, Q2l,
                                  n2_s + k * DD, n2_b + k * DD, nullptr);
        mma_up<<<gUP, 256>>>(Q2h, Q2l, k, GU);
        int tot = MROWS * INNER;
        swiglu_kernel<<<(tot + 255) / 256, 256>>>(GU, Hf);
        conv_kernel<<<(tot + 255) / 256, 256>>>(Hf, dw_w + (size_t)k * INNER * CKW,
                                                dw_b + (size_t)k * INNER, Hvh, Hvl);
        mma_down<<<gO, 256>>>(Hvh, Hvl, k, Q, Qi);
    }

    ln_kernel<<<MROWS, 256>>>(Q, Qn, Qnh, Qnl, fin_s, fin_b, nullptr);
    dim3 gLM(VV / 128, MROWS / 128);          // (250, 16)
    lm_head_mma<<<gLM, 256>>>(Qnh, Qnl, out);
    halt_kernel<<<BB, 256>>>(Qn, halt_w, halt_b, out + (size_t)MROWS * VV);
}

// round 8
// speedup vs baseline: 2.5984x; 1.2271x over previous
#include <cuda_runtime.h>
#include <cuda_bf16.h>
#include <math.h>
#include <stdint.h>

// Problem constants
#define BB    2
#define NN    1024
#define DD    512
#define HH    8
#define DH    64
#define KKB   4
#define VV    32000
#define INNER 1536
#define CKW   3
#define MROWS (BB*NN)     // 2048
#define BHN   (BB*HH)     // 16
#define TOTAL_PASSES 8

#define AMS  40    // A smem stride (bf16): 32 data + 8 pad
#define QS   72    // attention smem stride (64 + 8)

typedef __nv_bfloat16 bf16;

// ---------------- fp32 scratch ----------------------------------------------
__device__ __align__(16) float g_X  [MROWS*DD];
__device__ __align__(16) float g_Q  [MROWS*DD];
__device__ __align__(16) float g_Qi [MROWS*DD];
__device__ __align__(16) float g_Qn [MROWS*DD];
__device__ __align__(16) float g_GU [(size_t)MROWS*2*INNER];
__device__ __align__(16) float g_Hf [(size_t)MROWS*INNER];

// ---------------- bf16 hi/lo activation scratch ------------------------------
__device__ __align__(16) bf16 g_Hch [MROWS*DD], g_Hcl [MROWS*DD];
__device__ __align__(16) bf16 g_PQh [MROWS*DD], g_PQl [MROWS*DD];
__device__ __align__(16) bf16 g_PKh [MROWS*DD], g_PKl [MROWS*DD];
__device__ __align__(16) bf16 g_Vh  [MROWS*DD], g_Vl  [MROWS*DD];
__device__ __align__(16) bf16 g_mbh [MROWS*DD], g_mbl [MROWS*DD];
__device__ __align__(16) bf16 g_Q2h [MROWS*DD], g_Q2l [MROWS*DD];
__device__ __align__(16) bf16 g_Hvh [(size_t)MROWS*INNER], g_Hvl [(size_t)MROWS*INNER];
__device__ __align__(16) bf16 g_Qnh [MROWS*DD], g_Qnl [MROWS*DD];

// ---------------- bf16 hi/lo weight scratch ----------------------------------
__device__ __align__(16) bf16 g_WQh [KKB*DD*DD],   g_WQl [KKB*DD*DD];
__device__ __align__(16) bf16 g_WKh [KKB*DD*DD],   g_WKl [KKB*DD*DD];
__device__ __align__(16) bf16 g_WVh [KKB*DD*DD],   g_WVl [KKB*DD*DD];
__device__ __align__(16) bf16 g_WOh [KKB*DD*DD],   g_WOl [KKB*DD*DD];
__device__ __align__(16) bf16 g_WUh [(size_t)KKB*DD*2*INNER], g_WUl [(size_t)KKB*DD*2*INNER];
__device__ __align__(16) bf16 g_WDh [(size_t)KKB*INNER*DD],   g_WDl [(size_t)KKB*INNER*DD];
__device__ __align__(16) bf16 g_LMh [(size_t)VV*DD], g_LMl [(size_t)VV*DD];

// ---------------- helpers ----------------------------------------------------
__device__ __forceinline__ float siluf(float x) { return x / (1.0f + expf(-x)); }

__device__ __forceinline__ bool read_halted(const void* p, int b)
{
    const unsigned char* u8 = (const unsigned char*)p;
    if (u8[1] != 0) return u8[b] != 0;
    return ((const int*)p)[b] != 0;
}
__device__ __forceinline__ uint32_t smem_u32(const void* p) {
    uint32_t a;
    asm("{ .reg .u64 t; cvta.to.shared.u64 t, %1; cvt.u32.u64 %0, t; }"
        : "=r"(a) : "l"(p));
    return a;
}
__device__ __forceinline__ void ldm4(uint32_t* r, uint32_t a) {
    asm volatile("ldmatrix.sync.aligned.m8n8.x4.shared.b16 {%0,%1,%2,%3}, [%4];"
                 : "=r"(r[0]), "=r"(r[1]), "=r"(r[2]), "=r"(r[3]) : "r"(a));
}
__device__ __forceinline__ void ldm4t(uint32_t* r, uint32_t a) {
    asm volatile("ldmatrix.sync.aligned.m8n8.x4.trans.shared.b16 {%0,%1,%2,%3}, [%4];"
                 : "=r"(r[0]), "=r"(r[1]), "=r"(r[2]), "=r"(r[3]) : "r"(a));
}
__device__ __forceinline__ void mma_bf16(float* c, const uint32_t* a, const uint32_t* b) {
    asm volatile("mma.sync.aligned.m16n8k16.row.col.f32.bf16.bf16.f32 "
                 "{%0,%1,%2,%3}, {%4,%5,%6,%7}, {%8,%9}, {%0,%1,%2,%3};"
                 : "+f"(c[0]), "+f"(c[1]), "+f"(c[2]), "+f"(c[3])
                 : "r"(a[0]), "r"(a[1]), "r"(a[2]), "r"(a[3]),
                   "r"(b[0]), "r"(b[1]));
}
__device__ __forceinline__ uint32_t pack2(bf16 a, bf16 b) {
    return (uint32_t)__bfloat16_as_ushort(a) |
           ((uint32_t)__bfloat16_as_ushort(b) << 16);
}
__device__ __forceinline__ void split1(float v, bf16& h, bf16& l) {
    h = __float2bfloat16(v);
    l = __float2bfloat16(v - __bfloat162float(h));
}
__device__ __forceinline__ void cpa16(uint32_t s, const void* g) {
    asm volatile("cp.async.cg.shared.global [%0], [%1], 16;" :: "r"(s), "l"(g));
}
#define CP_COMMIT() asm volatile("cp.async.commit_group;" ::: "memory")
#define CP_WAIT0()  asm volatile("cp.async.wait_group 0;" ::: "memory")
#define CP_WAIT1()  asm volatile("cp.async.wait_group 1;" ::: "memory")

// ---------------- weight/activation converter --------------------------------
__global__ void cvt_kernel(const float* __restrict__ src, bf16* __restrict__ h,
                           bf16* __restrict__ l, int n4)
{
    int i = blockIdx.x * 256 + threadIdx.x;
    if (i >= n4) return;
    float4 v = *(const float4*)(src + (size_t)i * 4);
    bf16 h0, h1, h2, h3, l0, l1, l2, l3;
    split1(v.x, h0, l0); split1(v.y, h1, l1);
    split1(v.z, h2, l2); split1(v.w, h3, l3);
    *(uint2*)(h + (size_t)i * 4) = make_uint2(pack2(h0, h1), pack2(h2, h3));
    *(uint2*)(l + (size_t)i * 4) = make_uint2(pack2(l0, l1), pack2(l2, l3));
}

// ---------------- pipelined bf16x3 GEMM body ---------------------------------
// A hi/lo [M,K] row-major; B hi/lo [K,N] row-major (trans ldmatrix).
// BN = 128 or 64 output tile width. 2-stage cp.async pipeline.
// epi: 0 fp32, 1 hi/lo elu+1, 2 fp32 addP+alpha*acc, 3 fp32 addP+acc, 4 hi/lo
template <int BN>
__device__ __forceinline__ void stage_gemm(
    uint32_t base, int st, int kc, int tid, int m0, int n0,
    const bf16* __restrict__ Ah, const bf16* __restrict__ Al, int lda,
    const bf16* __restrict__ Bh, const bf16* __restrict__ Bl, int ldb)
{
    constexpr int BNS_ = (BN == 128) ? 136 : 72;
    constexpr uint32_t ASZ = 128 * AMS, BSZ = 32 * BNS_;
    const uint32_t oAh = 0, oAl = 2 * ASZ * 2;
    const uint32_t oBh = 4 * ASZ * 2, oBl = (4 * ASZ + 2 * BSZ) * 2;
    #pragma unroll
    for (int it2 = 0; it2 < 2; it2++) {
        int g = tid + 256 * it2;
        int row = g >> 2, c8 = (g & 3) * 8;
        size_t go = (size_t)(m0 + row) * lda + kc * 32 + c8;
        uint32_t so = (uint32_t)(st * ASZ + row * AMS + c8) * 2;
        cpa16(base + oAh + so, Ah + go);
        cpa16(base + oAl + so, Al + go);
    }
    #pragma unroll
    for (int it2 = 0; it2 < BN / 64; it2++) {
        int g = tid + 256 * it2;
        int row = g / (BN / 8), c8 = (g % (BN / 8)) * 8;
        size_t go = (size_t)(kc * 32 + row) * ldb + n0 + c8;
        uint32_t so = (uint32_t)(st * BSZ + row * BNS_ + c8) * 2;
        cpa16(base + oBh + so, Bh + go);
        cpa16(base + oBl + so, Bl + go);
    }
}

template <int BN>
__device__ __forceinline__ void gemm_pipe(
    bf16* smem,
    const bf16* __restrict__ Ah, const bf16* __restrict__ Al, int lda,
    const bf16* __restrict__ Bh, const bf16* __restrict__ Bl, int ldb,
    float* __restrict__ Cf, bf16* __restrict__ Ch, bf16* __restrict__ Cl, int ldc,
    int m0, int n0, int kch, int epi, const float* __restrict__ addP, float alpha)
{
    constexpr int BNS_ = (BN == 128) ? 136 : 72;
    constexpr int NJ = BN / 16;
    constexpr uint32_t ASZ = 128 * AMS, BSZ = 32 * BNS_;
    const uint32_t base = smem_u32(smem);
    const uint32_t oAh = 0, oAl = 2 * ASZ * 2;
    const uint32_t oBh = 4 * ASZ * 2, oBl = (4 * ASZ + 2 * BSZ) * 2;
    const int tid = threadIdx.x, lane = tid & 31, wid = tid >> 5;
    const int warp_m = wid >> 1, warp_n = wid & 1;

    float acc[2][NJ][4];
    #pragma unroll
    for (int i = 0; i < 2; i++)
        #pragma unroll
        for (int j = 0; j < NJ; j++)
            #pragma unroll
            for (int q = 0; q < 4; q++) acc[i][j][q] = 0.0f;

    stage_gemm<BN>(base, 0, 0, tid, m0, n0, Ah, Al, lda, Bh, Bl, ldb);
    CP_COMMIT();

    int st = 0;
    for (int kc = 0; kc < kch; kc++) {
        if (kc + 1 < kch) {
            stage_gemm<BN>(base, st ^ 1, kc + 1, tid, m0, n0, Ah, Al, lda, Bh, Bl, ldb);
            CP_COMMIT();
            CP_WAIT1();
        } else {
            CP_WAIT0();
        }
        __syncthreads();

        #pragma unroll
        for (int s = 0; s < 2; s++) {
            uint32_t ah[2][4], al[2][4], bh[NJ][2], bl[NJ][2];
            #pragma unroll
            for (int i = 0; i < 2; i++) {
                int r  = warp_m * 32 + i * 16 + (lane & 15);
                int kb = s * 16 + ((lane >> 4) << 3);
                uint32_t so = (uint32_t)(st * ASZ + r * AMS + kb) * 2;
                ldm4(ah[i], base + oAh + so);
                ldm4(al[i], base + oAl + so);
            }
            #pragma unroll
            for (int j2 = 0; j2 < NJ / 2; j2++) {
                int kk = s * 16 + (lane & 7) + ((lane >> 3) & 1) * 8;
                int nn = warp_n * (BN / 2) + j2 * 16 + (lane >> 4) * 8;
                uint32_t so = (uint32_t)(st * BSZ + kk * BNS_ + nn) * 2;
                uint32_t q[4];
                ldm4t(q, base + oBh + so);
                bh[2*j2][0] = q[0]; bh[2*j2][1] = q[1];
                bh[2*j2+1][0] = q[2]; bh[2*j2+1][1] = q[3];
                ldm4t(q, base + oBl + so);
                bl[2*j2][0] = q[0]; bl[2*j2][1] = q[1];
                bl[2*j2+1][0] = q[2]; bl[2*j2+1][1] = q[3];
            }
            #pragma unroll
            for (int i = 0; i < 2; i++)
                #pragma unroll
                for (int j = 0; j < NJ; j++) {
                    mma_bf16(acc[i][j], ah[i], bh[j]);
                    mma_bf16(acc[i][j], al[i], bh[j]);
                    mma_bf16(acc[i][j], ah[i], bl[j]);
                }
        }
        __syncthreads();
        st ^= 1;
    }

    #pragma unroll
    for (int i = 0; i < 2; i++) {
        int m = m0 + warp_m * 32 + i * 16 + (lane >> 2);
        #pragma unroll
        for (int j = 0; j < NJ; j++) {
            int n = n0 + warp_n * (BN / 2) + j * 8 + (lane & 3) * 2;
            float v0 = acc[i][j][0], v1 = acc[i][j][1];
            float v2 = acc[i][j][2], v3 = acc[i][j][3];
            size_t i0 = (size_t)m * ldc + n;
            size_t i1 = (size_t)(m + 8) * ldc + n;
            if (epi == 1 || epi == 4) {
                if (epi == 1) {
                    v0 = (v0 > 0.f) ? v0 + 1.f : expf(v0);
                    v1 = (v1 > 0.f) ? v1 + 1.f : expf(v1);
                    v2 = (v2 > 0.f) ? v2 + 1.f : expf(v2);
                    v3 = (v3 > 0.f) ? v3 + 1.f : expf(v3);
                }
                bf16 h0, h1, h2, h3, l0, l1, l2, l3;
                split1(v0, h0, l0); split1(v1, h1, l1);
                split1(v2, h2, l2); split1(v3, h3, l3);
                *(uint32_t*)(Ch + i0) = pack2(h0, h1);
                *(uint32_t*)(Cl + i0) = pack2(l0, l1);
                *(uint32_t*)(Ch + i1) = pack2(h2, h3);
                *(uint32_t*)(Cl + i1) = pack2(l2, l3);
            } else {
                if (epi == 2) {
                    v0 = addP[i0] + alpha * v0; v1 = addP[i0+1] + alpha * v1;
                    v2 = addP[i1] + alpha * v2; v3 = addP[i1+1] + alpha * v3;
                } else if (epi == 3) {
                    v0 += addP[i0]; v1 += addP[i0+1];
                    v2 += addP[i1]; v3 += addP[i1+1];
                }
                *(float2*)(Cf + i0) = make_float2(v0, v1);
                *(float2*)(Cf + i1) = make_float2(v2, v3);
            }
        }
    }
}

#define SM_G128 75776
#define SM_G64  59392
#define SM_LM   81920
#define ATT_SMEM 184320

// ---------------- GEMM wrappers ----------------------------------------------
__global__ void __launch_bounds__(256) mma_proj(
    const bf16* __restrict__ Ah, const bf16* __restrict__ Al, int kIdx)
{
    extern __shared__ __align__(16) bf16 dsm[];
    int z = blockIdx.z;
    size_t wo = (size_t)kIdx * DD * DD;
    const bf16* Bh = (z == 0) ? g_WQh + wo : (z == 1) ? g_WKh + wo : g_WVh + wo;
    const bf16* Bl = (z == 0) ? g_WQl + wo : (z == 1) ? g_WKl + wo : g_WVl + wo;
    bf16* Ch = (z == 0) ? g_PQh : (z == 1) ? g_PKh : g_Vh;
    bf16* Cl = (z == 0) ? g_PQl : (z == 1) ? g_PKl : g_Vl;
    gemm_pipe<128>(dsm, Ah, Al, DD, Bh, Bl, DD,
                   nullptr, Ch, Cl, DD, blockIdx.y * 128, blockIdx.x * 128,
                   DD / 32, (z < 2) ? 1 : 4, nullptr, 0.f);
}

__global__ void __launch_bounds__(256) mma_wo(
    const bf16* __restrict__ Ah, const bf16* __restrict__ Al, int kIdx,
    float* __restrict__ C, const float* __restrict__ addP,
    const float* __restrict__ dt)
{
    extern __shared__ __align__(16) bf16 dsm[];
    size_t wo = (size_t)kIdx * DD * DD;
    float d = dt[kIdx];
    float alpha = (d > 20.0f) ? d : log1pf(expf(d));
    gemm_pipe<64>(dsm, Ah, Al, DD, g_WOh + wo, g_WOl + wo, DD,
                  C, nullptr, nullptr, DD, blockIdx.y * 128, blockIdx.x * 64,
                  DD / 32, 2, addP, alpha);
}

__global__ void __launch_bounds__(256) mma_up(
    const bf16* __restrict__ Ah, const bf16* __restrict__ Al, int kIdx,
    float* __restrict__ C)
{
    extern __shared__ __align__(16) bf16 dsm[];
    size_t wo = (size_t)kIdx * DD * 2 * INNER;
    gemm_pipe<128>(dsm, Ah, Al, DD, g_WUh + wo, g_WUl + wo, 2 * INNER,
                   C, nullptr, nullptr, 2 * INNER, blockIdx.y * 128, blockIdx.x * 128,
                   DD / 32, 0, nullptr, 0.f);
}

__global__ void __launch_bounds__(256) mma_down(
    const bf16* __restrict__ Ah, const bf16* __restrict__ Al, int kIdx,
    float* __restrict__ C, const float* __restrict__ addP)
{
    extern __shared__ __align__(16) bf16 dsm[];
    size_t wo = (size_t)kIdx * INNER * DD;
    gemm_pipe<64>(dsm, Ah, Al, INNER, g_WDh + wo, g_WDl + wo, DD,
                  C, nullptr, nullptr, DD, blockIdx.y * 128, blockIdx.x * 64,
                  INNER / 32, 3, addP, 0.f);
}

// ---------------- fused flash attention (pipelined K/V) ----------------------
__device__ __forceinline__ void stage_kv(
    uint32_t base, int st, int kt, int tid, size_t rowbase,
    const bf16* __restrict__ PKh, const bf16* __restrict__ PKl,
    const bf16* __restrict__ Vh,  const bf16* __restrict__ Vl)
{
    const uint32_t QSZB = 128 * QS * 2;
    const uint32_t oKh = 2 * QSZB + st * QSZB;
    const uint32_t oKl = 4 * QSZB + st * QSZB;
    const uint32_t oVh = 6 * QSZB + st * QSZB;
    const uint32_t oVl = 8 * QSZB + st * QSZB;
    #pragma unroll
    for (int it2 = 0; it2 < 4; it2++) {
        int g = tid + 256 * it2;
        int row = g >> 3, c8 = (g & 7) * 8;
        size_t go = rowbase + (size_t)(kt * 128 + row) * DD + c8;
        uint32_t so = (uint32_t)(row * QS + c8) * 2;
        cpa16(base + oKh + so, PKh + go);
        cpa16(base + oKl + so, PKl + go);
        cpa16(base + oVh + so, Vh + go);
        cpa16(base + oVl + so, Vl + go);
    }
}

__global__ void __launch_bounds__(256) attn_fused(
    const bf16* __restrict__ PQh, const bf16* __restrict__ PQl,
    const bf16* __restrict__ PKh, const bf16* __restrict__ PKl,
    const bf16* __restrict__ Vh,  const bf16* __restrict__ Vl,
    bf16* __restrict__ Mh, bf16* __restrict__ Ml)
{
    extern __shared__ __align__(16) bf16 dsm[];
    const uint32_t base = smem_u32(dsm);
    const uint32_t QSZB = 128 * QS * 2;

    const int tid = threadIdx.x, lane = tid & 31, w = tid >> 5;
    const int bh = blockIdx.y, b = bh >> 3, h = bh & 7;
    const int q0 = blockIdx.x * 128;
    const size_t rowbase = (size_t)(b * NN) * DD + h * DH;

    // stage Q + KV(0) via cp.async
    #pragma unroll
    for (int it2 = 0; it2 < 4; it2++) {
        int g = tid + 256 * it2;
        int row = g >> 3, c8 = (g & 7) * 8;
        size_t go = rowbase + (size_t)(q0 + row) * DD + c8;
        uint32_t so = (uint32_t)(row * QS + c8) * 2;
        cpa16(base + so, PQh + go);
        cpa16(base + QSZB + so, PQl + go);
    }
    stage_kv(base, 0, 0, tid, rowbase, PKh, PKl, Vh, Vl);
    CP_COMMIT();
    CP_WAIT0();
    __syncthreads();

    // Q fragments
    uint32_t qh[4][4], ql[4][4];
    #pragma unroll
    for (int s = 0; s < 4; s++) {
        int r  = w * 16 + (lane & 15);
        int kb = s * 16 + ((lane >> 4) << 3);
        uint32_t so = (uint32_t)(r * QS + kb) * 2;
        ldm4(qh[s], base + so);
        ldm4(ql[s], base + QSZB + so);
    }

    float oacc[8][4];
    #pragma unroll
    for (int j = 0; j < 8; j++)
        #pragma unroll
        for (int q = 0; q < 4; q++) oacc[j][q] = 0.0f;
    float p0 = 0.0f, p1 = 0.0f;

    int st = 0;
    for (int kt = 0; kt < NN / 128; kt++) {
        if (kt + 1 < NN / 128) {
            stage_kv(base, st ^ 1, kt + 1, tid, rowbase, PKh, PKl, Vh, Vl);
            CP_COMMIT();
            CP_WAIT1();
        } else {
            CP_WAIT0();
        }
        __syncthreads();

        const uint32_t oKh = 2 * QSZB + st * QSZB;
        const uint32_t oKl = 4 * QSZB + st * QSZB;
        const uint32_t oVh = 6 * QSZB + st * QSZB;
        const uint32_t oVl = 8 * QSZB + st * QSZB;

        #pragma unroll
        for (int t = 0; t < 8; t++) {
            float sacc[2][4] = {};
            #pragma unroll
            for (int s = 0; s < 4; s++) {
                int r  = t * 16 + (lane & 7) + ((lane >> 4) << 3);
                int kb = s * 16 + (((lane >> 3) & 1) << 3);
                uint32_t so = (uint32_t)(r * QS + kb) * 2;
                uint32_t kh[4], kl[4];
                ldm4(kh, base + oKh + so);
                ldm4(kl, base + oKl + so);
                mma_bf16(sacc[0], qh[s], kh + 0);
                mma_bf16(sacc[0], ql[s], kh + 0);
                mma_bf16(sacc[0], qh[s], kl + 0);
                mma_bf16(sacc[1], qh[s], kh + 2);
                mma_bf16(sacc[1], ql[s], kh + 2);
                mma_bf16(sacc[1], qh[s], kl + 2);
            }
            float w2[2][4];
            #pragma unroll
            for (int f = 0; f < 2; f++)
                #pragma unroll
                for (int q = 0; q < 4; q++) {
                    float x = fmaxf(sacc[f][q], 0.0f);
                    w2[f][q] = x * x;
                }
            p0 += w2[0][0] + w2[0][1] + w2[1][0] + w2[1][1];
            p1 += w2[0][2] + w2[0][3] + w2[1][2] + w2[1][3];
            uint32_t wh[4], wl[4];
            {
                bf16 h0, h1, l0, l1;
                split1(w2[0][0], h0, l0); split1(w2[0][1], h1, l1);
                wh[0] = pack2(h0, h1); wl[0] = pack2(l0, l1);
                split1(w2[0][2], h0, l0); split1(w2[0][3], h1, l1);
                wh[1] = pack2(h0, h1); wl[1] = pack2(l0, l1);
                split1(w2[1][0], h0, l0); split1(w2[1][1], h1, l1);
                wh[2] = pack2(h0, h1); wl[2] = pack2(l0, l1);
                split1(w2[1][2], h0, l0); split1(w2[1][3], h1, l1);
                wh[3] = pack2(h0, h1); wl[3] = pack2(l0, l1);
            }
            #pragma unroll
            for (int n = 0; n < 4; n++) {
                int kk = t * 16 + (lane & 7) + ((lane >> 3) & 1) * 8;
                int nn = n * 16 + (lane >> 4) * 8;
                uint32_t so = (uint32_t)(kk * QS + nn) * 2;
                uint32_t vh[4], vl[4];
                ldm4t(vh, base + oVh + so);
                ldm4t(vl, base + oVl + so);
                mma_bf16(oacc[2*n],   wh, vh + 0);
                mma_bf16(oacc[2*n],   wl, vh + 0);
                mma_bf16(oacc[2*n],   wh, vl + 0);
                mma_bf16(oacc[2*n+1], wh, vh + 2);
                mma_bf16(oacc[2*n+1], wl, vh + 2);
                mma_bf16(oacc[2*n+1], wh, vl + 2);
            }
        }
        __syncthreads();
        st ^= 1;
    }

    p0 += __shfl_xor_sync(0xFFFFFFFFu, p0, 1);
    p0 += __shfl_xor_sync(0xFFFFFFFFu, p0, 2);
    p1 += __shfl_xor_sync(0xFFFFFFFFu, p1, 1);
    p1 += __shfl_xor_sync(0xFFFFFFFFu, p1, 2);
    float rd0 = 1.0f / (p0 + 1.0f);
    float rd1 = 1.0f / (p1 + 1.0f);

    int r0 = q0 + w * 16 + (lane >> 2);
    int r1 = r0 + 8;
    #pragma unroll
    for (int j = 0; j < 8; j++) {
        int d = j * 8 + (lane & 3) * 2;
        size_t i0 = rowbase + (size_t)r0 * DD + d;
        size_t i1 = rowbase + (size_t)r1 * DD + d;
        uint32_t vh0 = *(const uint32_t*)(Vh + i0), vl0 = *(const uint32_t*)(Vl + i0);
        uint32_t vh1 = *(const uint32_t*)(Vh + i1), vl1 = *(const uint32_t*)(Vl + i1);
        float vp00 = __bfloat162float(__ushort_as_bfloat16((unsigned short)(vh0 & 0xFFFF))) +
                     __bfloat162float(__ushort_as_bfloat16((unsigned short)(vl0 & 0xFFFF)));
        float vp01 = __bfloat162float(__ushort_as_bfloat16((unsigned short)(vh0 >> 16))) +
                     __bfloat162float(__ushort_as_bfloat16((unsigned short)(vl0 >> 16)));
        float vp10 = __bfloat162float(__ushort_as_bfloat16((unsigned short)(vh1 & 0xFFFF))) +
                     __bfloat162float(__ushort_as_bfloat16((unsigned short)(vl1 & 0xFFFF)));
        float vp11 = __bfloat162float(__ushort_as_bfloat16((unsigned short)(vh1 >> 16))) +
                     __bfloat162float(__ushort_as_bfloat16((unsigned short)(vl1 >> 16)));
        float m00 = oacc[j][0] * rd0 - vp00;
        float m01 = oacc[j][1] * rd0 - vp01;
        float m10 = oacc[j][2] * rd1 - vp10;
        float m11 = oacc[j][3] * rd1 - vp11;
        bf16 h0, h1, l0, l1;
        split1(m00, h0, l0); split1(m01, h1, l1);
        *(uint32_t*)(Mh + i0) = pack2(h0, h1);
        *(uint32_t*)(Ml + i0) = pack2(l0, l1);
        split1(m10, h0, l0); split1(m11, h1, l1);
        *(uint32_t*)(Mh + i1) = pack2(h0, h1);
        *(uint32_t*)(Ml + i1) = pack2(l0, l1);
    }
}

// ---------------- LM head (pipelined NT GEMM) --------------------------------
__device__ __forceinline__ void stage_lm(
    uint32_t base, int st, int kc, int tid, int m0, int n0,
    const bf16* __restrict__ Ah, const bf16* __restrict__ Al)
{
    constexpr uint32_t ASZ = 128 * AMS;
    const uint32_t oAh = 0, oAl = 2 * ASZ * 2;
    const uint32_t oBh = 4 * ASZ * 2, oBl = 6 * ASZ * 2;
    #pragma unroll
    for (int it2 = 0; it2 < 2; it2++) {
        int g = tid + 256 * it2;
        int row = g >> 2, c8 = (g & 3) * 8;
        uint32_t so = (uint32_t)(st * ASZ + row * AMS + c8) * 2;
        size_t ga = (size_t)(m0 + row) * DD + kc * 32 + c8;
        size_t gb = (size_t)(n0 + row) * DD + kc * 32 + c8;
        cpa16(base + oAh + so, Ah + ga);
        cpa16(base + oAl + so, Al + ga);
        cpa16(base + oBh + so, g_LMh + gb);
        cpa16(base + oBl + so, g_LMl + gb);
    }
}

__global__ void __launch_bounds__(256)
lm_head_mma(const bf16* __restrict__ Ah, const bf16* __restrict__ Al,
            float* __restrict__ C)
{
    extern __shared__ __align__(16) bf16 dsm[];
    constexpr uint32_t ASZ = 128 * AMS;
    const uint32_t base = smem_u32(dsm);
    const uint32_t oAh = 0, oAl = 2 * ASZ * 2;
    const uint32_t oBh = 4 * ASZ * 2, oBl = 6 * ASZ * 2;
    const int tid = threadIdx.x, lane = tid & 31, wid = tid >> 5;
    const int warp_m = wid >> 1, warp_n = wid & 1;
    const int m0 = blockIdx.y * 128, n0 = blockIdx.x * 128;

    float acc[2][8][4];
    #pragma unroll
    for (int i = 0; i < 2; i++)
        #pragma unroll
        for (int j = 0; j < 8; j++)
            #pragma unroll
            for (int q = 0; q < 4; q++) acc[i][j][q] = 0.0f;

    stage_lm(base, 0, 0, tid, m0, n0, Ah, Al);
    CP_COMMIT();

    int st = 0;
    for (int kc = 0; kc < 16; kc++) {
        if (kc + 1 < 16) {
            stage_lm(base, st ^ 1, kc + 1, tid, m0, n0, Ah, Al);
            CP_COMMIT();
            CP_WAIT1();
        } else {
            CP_WAIT0();
        }
        __syncthreads();

        #pragma unroll
        for (int s = 0; s < 2; s++) {
            uint32_t ah[2][4], al[2][4], bh[8][2], bl[8][2];
            #pragma unroll
            for (int i = 0; i < 2; i++) {
                int r  = warp_m * 32 + i * 16 + (lane & 15);
                int kb = s * 16 + ((lane >> 4) << 3);
                uint32_t so = (uint32_t)(st * ASZ + r * AMS + kb) * 2;
                ldm4(ah[i], base + oAh + so);
                ldm4(al[i], base + oAl + so);
            }
            #pragma unroll
            for (int j = 0; j < 4; j++) {
                int r  = warp_n * 64 + j * 16 + (lane & 7) + ((lane >> 4) << 3);
                int kb = s * 16 + (((lane >> 3) & 1) << 3);
                uint32_t so = (uint32_t)(st * ASZ + r * AMS + kb) * 2;
                uint32_t q[4];
                ldm4(q, base + oBh + so);
                bh[2*j][0] = q[0]; bh[2*j][1] = q[1];
                bh[2*j+1][0] = q[2]; bh[2*j+1][1] = q[3];
                ldm4(q, base + oBl + so);
                bl[2*j][0] = q[0]; bl[2*j][1] = q[1];
                bl[2*j+1][0] = q[2]; bl[2*j+1][1] = q[3];
            }
            #pragma unroll
            for (int i = 0; i < 2; i++)
                #pragma unroll
                for (int j = 0; j < 8; j++) {
                    mma_bf16(acc[i][j], ah[i], bh[j]);
                    mma_bf16(acc[i][j], al[i], bh[j]);
                    mma_bf16(acc[i][j], ah[i], bl[j]);
                }
        }
        __syncthreads();
        st ^= 1;
    }

    #pragma unroll
    for (int i = 0; i < 2; i++) {
        int m = m0 + warp_m * 32 + i * 16 + (lane >> 2);
        #pragma unroll
        for (int j = 0; j < 8; j++) {
            int n = n0 + warp_n * 64 + j * 8 + (lane & 3) * 2;
            *(float2*)(C + (size_t)m * VV + n) =
                make_float2(acc[i][j][0], acc[i][j][1]);
            *(float2*)(C + (size_t)(m + 8) * VV + n) =
                make_float2(acc[i][j][2], acc[i][j][3]);
        }
    }
}

// ---------------- init -------------------------------------------------------
__global__ void init_kernel(const int* __restrict__ inputs,
                            const int* __restrict__ carry_inputs,
                            const void* __restrict__ halted,
                            const float* __restrict__ carry_hidden,
                            const float* __restrict__ init_hidden,
                            const float* __restrict__ emb,
                            const float* __restrict__ pos,
                            const float* __restrict__ in_s,
                            const float* __restrict__ in_b)
{
    int r = blockIdx.x;
    int b = r / NN, n = r % NN;
    int t = threadIdx.x;
    bool h = read_halted(halted, b);
    int idx = h ? inputs[r] : carry_inputs[r];
    const float* e = emb + (size_t)idx * DD;
    const float* p = pos + (size_t)n * DD;

    float x0 = e[t]       + p[t];
    float x1 = e[t + 256] + p[t + 256];

    size_t base = (size_t)r * DD;
    g_Q[base + t]       = h ? init_hidden[t]       : carry_hidden[base + t];
    g_Q[base + t + 256] = h ? init_hidden[t + 256] : carry_hidden[base + t + 256];

    __shared__ float s_sum[256], s_sq[256];
    s_sum[t] = x0 + x1;
    s_sq[t]  = x0 * x0 + x1 * x1;
    __syncthreads();
    for (int o = 128; o > 0; o >>= 1) {
        if (t < o) { s_sum[t] += s_sum[t + o]; s_sq[t] += s_sq[t + o]; }
        __syncthreads();
    }
    float mu   = s_sum[0] * (1.0f / DD);
    float var  = s_sq[0] * (1.0f / DD) - mu * mu;
    float rstd = rsqrtf(var + 1e-5f);
    g_X[base + t]       = (x0 - mu) * rstd * in_s[t]       + in_b[t];
    g_X[base + t + 256] = (x1 - mu) * rstd * in_s[t + 256] + in_b[t + 256];
}

// ---------------- LayerNorm --------------------------------------------------
__global__ void ln_kernel(const float* __restrict__ in, float* __restrict__ outf,
                          bf16* __restrict__ outh, bf16* __restrict__ outl,
                          const float* __restrict__ s, const float* __restrict__ bia,
                          const float* __restrict__ add)
{
    int r = blockIdx.x;
    int t = threadIdx.x;
    size_t base = (size_t)r * DD;
    float x0 = in[base + t];
    float x1 = in[base + t + 256];

    __shared__ float s_sum[256], s_sq[256];
    s_sum[t] = x0 + x1;
    s_sq[t]  = x0 * x0 + x1 * x1;
    __syncthreads();
    for (int o = 128; o > 0; o >>= 1) {
        if (t < o) { s_sum[t] += s_sum[t + o]; s_sq[t] += s_sq[t + o]; }
        __syncthreads();
    }
    float mu   = s_sum[0] * (1.0f / DD);
    float var  = s_sq[0] * (1.0f / DD) - mu * mu;
    float rstd = rsqrtf(var + 1e-5f);
    float v0 = (x0 - mu) * rstd * s[t]       + bia[t];
    float v1 = (x1 - mu) * rstd * s[t + 256] + bia[t + 256];
    if (add) { v0 += add[base + t]; v1 += add[base + t + 256]; }
    if (outf) { outf[base + t] = v0; outf[base + t + 256] = v1; }
    if (outh) {
        bf16 h0, l0, h1, l1;
        split1(v0, h0, l0); split1(v1, h1, l1);
        outh[base + t] = h0;       outl[base + t] = l0;
        outh[base + t + 256] = h1; outl[base + t + 256] = l1;
    }
}

// ---------------- SwiGLU -----------------------------------------------------
__global__ void swiglu_kernel(const float* __restrict__ GU, float* __restrict__ Hf)
{
    size_t i = (size_t)blockIdx.x * 256 + threadIdx.x;
    if (i >= (size_t)MROWS * INNER) return;
    size_t row = i / INNER;
    int c = (int)(i % INNER);
    float g = GU[row * (2 * INNER) + c];
    float u = GU[row * (2 * INNER) + INNER + c];
    Hf[i] = siluf(g) * u;
}

// ---------------- depthwise conv k=3 + bias + silu -> hi/lo ------------------
__global__ void conv_kernel(const float* __restrict__ Hf, const float* __restrict__ w,
                            const float* __restrict__ bias,
                            bf16* __restrict__ outh, bf16* __restrict__ outl)
{
    size_t i = (size_t)blockIdx.x * 256 + threadIdx.x;
    if (i >= (size_t)MROWS * INNER) return;
    size_t row = i / INNER;
    int c = (int)(i % INNER);
    int n = (int)(row % NN);
    const float* wc = w + (size_t)c * CKW;
    float acc = bias[c];
    if (n > 0)      acc += wc[0] * Hf[(row - 1) * INNER + c];
    acc += wc[1] * Hf[row * INNER + c];
    if (n < NN - 1) acc += wc[2] * Hf[(row + 1) * INNER + c];
    float v = siluf(acc);
    bf16 h, l;
    split1(v, h, l);
    outh[i] = h;
    outl[i] = l;
}

// ---------------- halt head --------------------------------------------------
__global__ void halt_kernel(const float* __restrict__ Qn, const float* __restrict__ hw,
                            const float* __restrict__ hb, float* __restrict__ out)
{
    int b = blockIdx.x;
    int t = threadIdx.x;
    __shared__ float md[DD];
    for (int d = t; d < DD; d += 256) {
        float s = 0.0f;
        for (int n = 0; n < NN; n++)
            s += Qn[((size_t)(b * NN + n)) * DD + d];
        md[d] = s * (1.0f / NN);
    }
    __syncthreads();
    __shared__ float r0[256], r1[256];
    float p0 = 0.0f, p1 = 0.0f;
    for (int d = t; d < DD; d += 256) {
        p0 += md[d] * hw[d];
        p1 += md[d] * hw[DD + d];
    }
    r0[t] = p0; r1[t] = p1;
    __syncthreads();
    for (int o = 128; o > 0; o >>= 1) {
        if (t < o) { r0[t] += r0[t + o]; r1[t] += r1[t + o]; }
        __syncthreads();
    }
    if (t == 0) {
        out[b * 2 + 0] = r0[0] + hb[0];
        out[b * 2 + 1] = r1[0] + hb[1];
    }
}

// ---------------- host orchestration -----------------------------------------
static void cvt(const float* src, bf16* h, bf16* l, size_t n)
{
    int n4 = (int)(n / 4);
    cvt_kernel<<<(n4 + 255) / 256, 256>>>(src, h, l, n4);
}

extern "C" void kernel_launch(void* const* d_in, const int* in_sizes, int n_in,
                              void* d_out, int out_size)
{
    const int*   inputs       = (const int*)d_in[0];
    const float* carry_hidden = (const float*)d_in[2];
    const void*  halted       = d_in[4];
    const int*   carry_inputs = (const int*)d_in[5];
    const float* init_hidden  = (const float*)d_in[7];
    const float* emb          = (const float*)d_in[8];
    const float* pos          = (const float*)d_in[9];
    const float* in_s         = (const float*)d_in[10];
    const float* in_b         = (const float*)d_in[11];
    const float* fin_s        = (const float*)d_in[12];
    const float* fin_b        = (const float*)d_in[13];
    const float* lm_w         = (const float*)d_in[14];
    const float* halt_w       = (const float*)d_in[15];
    const float* halt_b       = (const float*)d_in[16];
    const float* dt           = (const float*)d_in[17];
    const float* W_Q          = (const float*)d_in[18];
    const float* W_K          = (const float*)d_in[19];
    const float* W_V          = (const float*)d_in[20];
    const float* W_O          = (const float*)d_in[21];
    const float* W_up         = (const float*)d_in[22];
    const float* dw_w         = (const float*)d_in[23];
    const float* dw_b         = (const float*)d_in[24];
    const float* W_down       = (const float*)d_in[25];
    const float* n1_s         = (const float*)d_in[26];
    const float* n1_b         = (const float*)d_in[27];
    const float* n2_s         = (const float*)d_in[28];
    const float* n2_b         = (const float*)d_in[29];

    float *X, *Q, *Qi, *Qn, *GU, *Hf;
    bf16 *Hch, *Hcl, *PQh, *PQl, *PKh, *PKl, *Vh, *Vl, *mbh, *mbl;
    bf16 *Q2h, *Q2l, *Hvh, *Hvl, *Qnh, *Qnl;
    bf16 *WQh, *WQl, *WKh, *WKl, *WVh, *WVl, *WOh, *WOl;
    bf16 *WUh, *WUl, *WDh, *WDl, *LMh, *LMl;
    cudaGetSymbolAddress((void**)&X,   g_X);
    cudaGetSymbolAddress((void**)&Q,   g_Q);
    cudaGetSymbolAddress((void**)&Qi,  g_Qi);
    cudaGetSymbolAddress((void**)&Qn,  g_Qn);
    cudaGetSymbolAddress((void**)&GU,  g_GU);
    cudaGetSymbolAddress((void**)&Hf,  g_Hf);
    cudaGetSymbolAddress((void**)&Hch, g_Hch); cudaGetSymbolAddress((void**)&Hcl, g_Hcl);
    cudaGetSymbolAddress((void**)&PQh, g_PQh); cudaGetSymbolAddress((void**)&PQl, g_PQl);
    cudaGetSymbolAddress((void**)&PKh, g_PKh); cudaGetSymbolAddress((void**)&PKl, g_PKl);
    cudaGetSymbolAddress((void**)&Vh,  g_Vh);  cudaGetSymbolAddress((void**)&Vl,  g_Vl);
    cudaGetSymbolAddress((void**)&mbh, g_mbh); cudaGetSymbolAddress((void**)&mbl, g_mbl);
    cudaGetSymbolAddress((void**)&Q2h, g_Q2h); cudaGetSymbolAddress((void**)&Q2l, g_Q2l);
    cudaGetSymbolAddress((void**)&Hvh, g_Hvh); cudaGetSymbolAddress((void**)&Hvl, g_Hvl);
    cudaGetSymbolAddress((void**)&Qnh, g_Qnh); cudaGetSymbolAddress((void**)&Qnl, g_Qnl);
    cudaGetSymbolAddress((void**)&WQh, g_WQh); cudaGetSymbolAddress((void**)&WQl, g_WQl);
    cudaGetSymbolAddress((void**)&WKh, g_WKh); cudaGetSymbolAddress((void**)&WKl, g_WKl);
    cudaGetSymbolAddress((void**)&WVh, g_WVh); cudaGetSymbolAddress((void**)&WVl, g_WVl);
    cudaGetSymbolAddress((void**)&WOh, g_WOh); cudaGetSymbolAddress((void**)&WOl, g_WOl);
    cudaGetSymbolAddress((void**)&WUh, g_WUh); cudaGetSymbolAddress((void**)&WUl, g_WUl);
    cudaGetSymbolAddress((void**)&WDh, g_WDh); cudaGetSymbolAddress((void**)&WDl, g_WDl);
    cudaGetSymbolAddress((void**)&LMh, g_LMh); cudaGetSymbolAddress((void**)&LMl, g_LMl);

    float* out = (float*)d_out;

    cudaFuncSetAttribute(attn_fused, cudaFuncAttributeMaxDynamicSharedMemorySize, ATT_SMEM);
    cudaFuncSetAttribute(mma_proj,   cudaFuncAttributeMaxDynamicSharedMemorySize, SM_G128);
    cudaFuncSetAttribute(mma_up,     cudaFuncAttributeMaxDynamicSharedMemorySize, SM_G128);
    cudaFuncSetAttribute(mma_wo,     cudaFuncAttributeMaxDynamicSharedMemorySize, SM_G64);
    cudaFuncSetAttribute(mma_down,   cudaFuncAttributeMaxDynamicSharedMemorySize, SM_G64);
    cudaFuncSetAttribute(lm_head_mma, cudaFuncAttributeMaxDynamicSharedMemorySize, SM_LM);

    // weight pre-split (runs in-graph every replay; deterministic)
    cvt(W_Q,    WQh, WQl, (size_t)KKB * DD * DD);
    cvt(W_K,    WKh, WKl, (size_t)KKB * DD * DD);
    cvt(W_V,    WVh, WVl, (size_t)KKB * DD * DD);
    cvt(W_O,    WOh, WOl, (size_t)KKB * DD * DD);
    cvt(W_up,   WUh, WUl, (size_t)KKB * DD * 2 * INNER);
    cvt(W_down, WDh, WDl, (size_t)KKB * INNER * DD);
    cvt(lm_w,   LMh, LMl, (size_t)VV * DD);

    init_kernel<<<MROWS, 256>>>(inputs, carry_inputs, halted, carry_hidden,
                                init_hidden, emb, pos, in_s, in_b);

    dim3 gP(DD / 128, MROWS / 128, 3);        // (4, 16, 3)
    dim3 gO64(DD / 64, MROWS / 128);          // (8, 16) = 128 CTAs
    dim3 gUP(2 * INNER / 128, MROWS / 128);   // (24, 16)
    dim3 gAT(NN / 128, BHN);                  // (8, 16)

    for (int it = 0; it < TOTAL_PASSES; it++) {
        int k = it % KKB;

        ln_kernel<<<MROWS, 256>>>(Q, nullptr, Hch, Hcl,
                                  n1_s + k * DD, n1_b + k * DD, X);

        mma_proj<<<gP, 256, SM_G128>>>(Hch, Hcl, k);

        attn_fused<<<gAT, 256, ATT_SMEM>>>(PQh, PQl, PKh, PKl, Vh, Vl, mbh, mbl);

        mma_wo<<<gO64, 256, SM_G64>>>(mbh, mbl, k, Qi, Q, dt);

        ln_kernel<<<MROWS, 256>>>(Qi, nullptr, Q2h, Q2l,
                                  n2_s + k * DD, n2_b + k * DD, nullptr);
        mma_up<<<gUP, 256, SM_G128>>>(Q2h, Q2l, k, GU);
        int tot = MROWS * INNER;
        swiglu_kernel<<<(tot + 255) / 256, 256>>>(GU, Hf);
        conv_kernel<<<(tot + 255) / 256, 256>>>(Hf, dw_w + (size_t)k * INNER * CKW,
                                                dw_b + (size_t)k * INNER, Hvh, Hvl);
        mma_down<<<gO64, 256, SM_G64>>>(Hvh, Hvl, k, Q, Qi);
    }

    ln_kernel<<<MROWS, 256>>>(Q, Qn, Qnh, Qnl, fin_s, fin_b, nullptr);
    dim3 gLM(VV / 128, MROWS / 128);          // (250, 16)
    lm_head_mma<<<gLM, 256, SM_LM>>>(Qnh, Qnl, out);
    halt_kernel<<<BB, 256>>>(Qn, halt_w, halt_b, out + (size_t)MROWS * VV);
}

// round 9
// speedup vs baseline: 2.6697x; 1.0274x over previous
#include <cuda_runtime.h>
#include <cuda_bf16.h>
#include <math.h>
#include <stdint.h>

// Problem constants
#define BB    2
#define NN    1024
#define DD    512
#define HH    8
#define DH    64
#define KKB   4
#define VV    32000
#define INNER 1536
#define CKW   3
#define MROWS (BB*NN)     // 2048
#define BHN   (BB*HH)     // 16
#define TOTAL_PASSES 8

#define AMS  40    // A smem stride (bf16): 32 data + 8 pad
#define QS   72    // attention smem stride (64 + 8)

typedef __nv_bfloat16 bf16;

// ---------------- fp32 scratch ----------------------------------------------
__device__ __align__(16) float g_X  [MROWS*DD];
__device__ __align__(16) float g_Q  [MROWS*DD];
__device__ __align__(16) float g_Qi [MROWS*DD];
__device__ __align__(16) float g_Qn [MROWS*DD];
__device__ __align__(16) float g_Hf [(size_t)MROWS*INNER];

// ---------------- bf16 hi/lo activation scratch ------------------------------
__device__ __align__(16) bf16 g_Hch [MROWS*DD], g_Hcl [MROWS*DD];
__device__ __align__(16) bf16 g_PQh [MROWS*DD], g_PQl [MROWS*DD];
__device__ __align__(16) bf16 g_PKh [MROWS*DD], g_PKl [MROWS*DD];
__device__ __align__(16) bf16 g_Vh  [MROWS*DD], g_Vl  [MROWS*DD];
__device__ __align__(16) bf16 g_mbh [MROWS*DD], g_mbl [MROWS*DD];
__device__ __align__(16) bf16 g_Q2h [MROWS*DD], g_Q2l [MROWS*DD];
__device__ __align__(16) bf16 g_Hvh [(size_t)MROWS*INNER], g_Hvl [(size_t)MROWS*INNER];
__device__ __align__(16) bf16 g_Qnh [MROWS*DD], g_Qnl [MROWS*DD];

// ---------------- bf16 hi/lo weight scratch ----------------------------------
__device__ __align__(16) bf16 g_WQh [KKB*DD*DD],   g_WQl [KKB*DD*DD];
__device__ __align__(16) bf16 g_WKh [KKB*DD*DD],   g_WKl [KKB*DD*DD];
__device__ __align__(16) bf16 g_WVh [KKB*DD*DD],   g_WVl [KKB*DD*DD];
__device__ __align__(16) bf16 g_WOh [KKB*DD*DD],   g_WOl [KKB*DD*DD];
__device__ __align__(16) bf16 g_WUh [(size_t)KKB*DD*2*INNER], g_WUl [(size_t)KKB*DD*2*INNER];
__device__ __align__(16) bf16 g_WDh [(size_t)KKB*INNER*DD],   g_WDl [(size_t)KKB*INNER*DD];
__device__ __align__(16) bf16 g_LMh [(size_t)VV*DD], g_LMl [(size_t)VV*DD];

// ---------------- helpers ----------------------------------------------------
__device__ __forceinline__ float siluf(float x) { return x / (1.0f + expf(-x)); }

__device__ __forceinline__ bool read_halted(const void* p, int b)
{
    const unsigned char* u8 = (const unsigned char*)p;
    if (u8[1] != 0) return u8[b] != 0;
    return ((const int*)p)[b] != 0;
}
__device__ __forceinline__ uint32_t smem_u32(const void* p) {
    uint32_t a;
    asm("{ .reg .u64 t; cvta.to.shared.u64 t, %1; cvt.u32.u64 %0, t; }"
        : "=r"(a) : "l"(p));
    return a;
}
__device__ __forceinline__ void ldm4(uint32_t* r, uint32_t a) {
    asm volatile("ldmatrix.sync.aligned.m8n8.x4.shared.b16 {%0,%1,%2,%3}, [%4];"
                 : "=r"(r[0]), "=r"(r[1]), "=r"(r[2]), "=r"(r[3]) : "r"(a));
}
__device__ __forceinline__ void ldm4t(uint32_t* r, uint32_t a) {
    asm volatile("ldmatrix.sync.aligned.m8n8.x4.trans.shared.b16 {%0,%1,%2,%3}, [%4];"
                 : "=r"(r[0]), "=r"(r[1]), "=r"(r[2]), "=r"(r[3]) : "r"(a));
}
__device__ __forceinline__ void mma_bf16(float* c, const uint32_t* a, const uint32_t* b) {
    asm volatile("mma.sync.aligned.m16n8k16.row.col.f32.bf16.bf16.f32 "
                 "{%0,%1,%2,%3}, {%4,%5,%6,%7}, {%8,%9}, {%0,%1,%2,%3};"
                 : "+f"(c[0]), "+f"(c[1]), "+f"(c[2]), "+f"(c[3])
                 : "r"(a[0]), "r"(a[1]), "r"(a[2]), "r"(a[3]),
                   "r"(b[0]), "r"(b[1]));
}
__device__ __forceinline__ uint32_t pack2(bf16 a, bf16 b) {
    return (uint32_t)__bfloat16_as_ushort(a) |
           ((uint32_t)__bfloat16_as_ushort(b) << 16);
}
__device__ __forceinline__ void split1(float v, bf16& h, bf16& l) {
    h = __float2bfloat16(v);
    l = __float2bfloat16(v - __bfloat162float(h));
}
__device__ __forceinline__ void cpa16(uint32_t s, const void* g) {
    asm volatile("cp.async.cg.shared.global [%0], [%1], 16;" :: "r"(s), "l"(g));
}
#define CP_COMMIT() asm volatile("cp.async.commit_group;" ::: "memory")
#define CP_WAIT0()  asm volatile("cp.async.wait_group 0;" ::: "memory")
#define CP_WAIT1()  asm volatile("cp.async.wait_group 1;" ::: "memory")

// ---------------- weight/activation converter --------------------------------
__global__ void cvt_kernel(const float* __restrict__ src, bf16* __restrict__ h,
                           bf16* __restrict__ l, int n4)
{
    int i = blockIdx.x * 256 + threadIdx.x;
    if (i >= n4) return;
    float4 v = *(const float4*)(src + (size_t)i * 4);
    bf16 h0, h1, h2, h3, l0, l1, l2, l3;
    split1(v.x, h0, l0); split1(v.y, h1, l1);
    split1(v.z, h2, l2); split1(v.w, h3, l3);
    *(uint2*)(h + (size_t)i * 4) = make_uint2(pack2(h0, h1), pack2(h2, h3));
    *(uint2*)(l + (size_t)i * 4) = make_uint2(pack2(l0, l1), pack2(l2, l3));
}

// W_up converter with G/U column interleave: dest col 2c = G_c, 2c+1 = U_c
__global__ void cvt_up_kernel(const float* __restrict__ src, bf16* __restrict__ h,
                              bf16* __restrict__ l)
{
    int gi = blockIdx.x * 256 + threadIdx.x;       // 8-dest-col groups
    int total = KKB * DD * (2 * INNER) / 8;
    if (gi >= total) return;
    int cg8 = gi % (2 * INNER / 8);                // dest col group
    int row = gi / (2 * INNER / 8);                // k*DD + d
    int cg = cg8 * 4;                              // first G/U index of the 4 pairs
    size_t rb = (size_t)row * (2 * INNER);
    float4 gsrc = *(const float4*)(src + rb + cg);
    float4 usrc = *(const float4*)(src + rb + INNER + cg);
    float gv[4] = {gsrc.x, gsrc.y, gsrc.z, gsrc.w};
    float uv[4] = {usrc.x, usrc.y, usrc.z, usrc.w};
    uint32_t hw[4], lw[4];
    #pragma unroll
    for (int q = 0; q < 4; q++) {
        bf16 gh, gl, uh, ul;
        split1(gv[q], gh, gl);
        split1(uv[q], uh, ul);
        hw[q] = pack2(gh, uh);
        lw[q] = pack2(gl, ul);
    }
    size_t db = rb + (size_t)cg8 * 8;
    *(uint4*)(h + db) = make_uint4(hw[0], hw[1], hw[2], hw[3]);
    *(uint4*)(l + db) = make_uint4(lw[0], lw[1], lw[2], lw[3]);
}

// ---------------- pipelined bf16x3 GEMM body ---------------------------------
// epi: 0 fp32, 1 hi/lo elu+1, 2 fp32 addP+alpha*acc, 3 fp32 addP+acc,
//      4 hi/lo plain, 5 fused swiglu: pairs (even=G, odd=U) -> Hf fp32 (ldc=INNER)
template <int BN>
__device__ __forceinline__ void stage_gemm(
    uint32_t base, int st, int kc, int tid, int m0, int n0,
    const bf16* __restrict__ Ah, const bf16* __restrict__ Al, int lda,
    const bf16* __restrict__ Bh, const bf16* __restrict__ Bl, int ldb)
{
    constexpr int BNS_ = (BN == 128) ? 136 : 72;
    constexpr uint32_t ASZ = 128 * AMS, BSZ = 32 * BNS_;
    const uint32_t oAh = 0, oAl = 2 * ASZ * 2;
    const uint32_t oBh = 4 * ASZ * 2, oBl = (4 * ASZ + 2 * BSZ) * 2;
    #pragma unroll
    for (int it2 = 0; it2 < 2; it2++) {
        int g = tid + 256 * it2;
        int row = g >> 2, c8 = (g & 3) * 8;
        size_t go = (size_t)(m0 + row) * lda + kc * 32 + c8;
        uint32_t so = (uint32_t)(st * ASZ + row * AMS + c8) * 2;
        cpa16(base + oAh + so, Ah + go);
        cpa16(base + oAl + so, Al + go);
    }
    #pragma unroll
    for (int it2 = 0; it2 < BN / 64; it2++) {
        int g = tid + 256 * it2;
        int row = g / (BN / 8), c8 = (g % (BN / 8)) * 8;
        size_t go = (size_t)(kc * 32 + row) * ldb + n0 + c8;
        uint32_t so = (uint32_t)(st * BSZ + row * BNS_ + c8) * 2;
        cpa16(base + oBh + so, Bh + go);
        cpa16(base + oBl + so, Bl + go);
    }
}

template <int BN>
__device__ __forceinline__ void gemm_pipe(
    bf16* smem,
    const bf16* __restrict__ Ah, const bf16* __restrict__ Al, int lda,
    const bf16* __restrict__ Bh, const bf16* __restrict__ Bl, int ldb,
    float* __restrict__ Cf, bf16* __restrict__ Ch, bf16* __restrict__ Cl, int ldc,
    int m0, int n0, int kch, int epi, const float* __restrict__ addP, float alpha)
{
    constexpr int BNS_ = (BN == 128) ? 136 : 72;
    constexpr int NJ = BN / 16;
    constexpr uint32_t ASZ = 128 * AMS, BSZ = 32 * BNS_;
    const uint32_t base = smem_u32(smem);
    const uint32_t oAh = 0, oAl = 2 * ASZ * 2;
    const uint32_t oBh = 4 * ASZ * 2, oBl = (4 * ASZ + 2 * BSZ) * 2;
    const int tid = threadIdx.x, lane = tid & 31, wid = tid >> 5;
    const int warp_m = wid >> 1, warp_n = wid & 1;

    float acc[2][NJ][4];
    #pragma unroll
    for (int i = 0; i < 2; i++)
        #pragma unroll
        for (int j = 0; j < NJ; j++)
            #pragma unroll
            for (int q = 0; q < 4; q++) acc[i][j][q] = 0.0f;

    stage_gemm<BN>(base, 0, 0, tid, m0, n0, Ah, Al, lda, Bh, Bl, ldb);
    CP_COMMIT();

    int st = 0;
    for (int kc = 0; kc < kch; kc++) {
        if (kc + 1 < kch) {
            stage_gemm<BN>(base, st ^ 1, kc + 1, tid, m0, n0, Ah, Al, lda, Bh, Bl, ldb);
            CP_COMMIT();
            CP_WAIT1();
        } else {
            CP_WAIT0();
        }
        __syncthreads();

        #pragma unroll
        for (int s = 0; s < 2; s++) {
            uint32_t ah[2][4], al[2][4], bh[NJ][2], bl[NJ][2];
            #pragma unroll
            for (int i = 0; i < 2; i++) {
                int r  = warp_m * 32 + i * 16 + (lane & 15);
                int kb = s * 16 + ((lane >> 4) << 3);
                uint32_t so = (uint32_t)(st * ASZ + r * AMS + kb) * 2;
                ldm4(ah[i], base + oAh + so);
                ldm4(al[i], base + oAl + so);
            }
            #pragma unroll
            for (int j2 = 0; j2 < NJ / 2; j2++) {
                int kk = s * 16 + (lane & 7) + ((lane >> 3) & 1) * 8;
                int nn = warp_n * (BN / 2) + j2 * 16 + (lane >> 4) * 8;
                uint32_t so = (uint32_t)(st * BSZ + kk * BNS_ + nn) * 2;
                uint32_t q[4];
                ldm4t(q, base + oBh + so);
                bh[2*j2][0] = q[0]; bh[2*j2][1] = q[1];
                bh[2*j2+1][0] = q[2]; bh[2*j2+1][1] = q[3];
                ldm4t(q, base + oBl + so);
                bl[2*j2][0] = q[0]; bl[2*j2][1] = q[1];
                bl[2*j2+1][0] = q[2]; bl[2*j2+1][1] = q[3];
            }
            #pragma unroll
            for (int i = 0; i < 2; i++)
                #pragma unroll
                for (int j = 0; j < NJ; j++) {
                    mma_bf16(acc[i][j], ah[i], bh[j]);
                    mma_bf16(acc[i][j], al[i], bh[j]);
                    mma_bf16(acc[i][j], ah[i], bl[j]);
                }
        }
        __syncthreads();
        st ^= 1;
    }

    #pragma unroll
    for (int i = 0; i < 2; i++) {
        int m = m0 + warp_m * 32 + i * 16 + (lane >> 2);
        #pragma unroll
        for (int j = 0; j < NJ; j++) {
            int n = n0 + warp_n * (BN / 2) + j * 8 + (lane & 3) * 2;
            float v0 = acc[i][j][0], v1 = acc[i][j][1];
            float v2 = acc[i][j][2], v3 = acc[i][j][3];
            if (epi == 5) {
                int col = n >> 1;   // (G,U) pair -> Hf column
                Cf[(size_t)m * INNER + col]       = siluf(v0) * v1;
                Cf[(size_t)(m + 8) * INNER + col] = siluf(v2) * v3;
                continue;
            }
            size_t i0 = (size_t)m * ldc + n;
            size_t i1 = (size_t)(m + 8) * ldc + n;
            if (epi == 1 || epi == 4) {
                if (epi == 1) {
                    v0 = (v0 > 0.f) ? v0 + 1.f : expf(v0);
                    v1 = (v1 > 0.f) ? v1 + 1.f : expf(v1);
                    v2 = (v2 > 0.f) ? v2 + 1.f : expf(v2);
                    v3 = (v3 > 0.f) ? v3 + 1.f : expf(v3);
                }
                bf16 h0, h1, h2, h3, l0, l1, l2, l3;
                split1(v0, h0, l0); split1(v1, h1, l1);
                split1(v2, h2, l2); split1(v3, h3, l3);
                *(uint32_t*)(Ch + i0) = pack2(h0, h1);
                *(uint32_t*)(Cl + i0) = pack2(l0, l1);
                *(uint32_t*)(Ch + i1) = pack2(h2, h3);
                *(uint32_t*)(Cl + i1) = pack2(l2, l3);
            } else {
                if (epi == 2) {
                    v0 = addP[i0] + alpha * v0; v1 = addP[i0+1] + alpha * v1;
                    v2 = addP[i1] + alpha * v2; v3 = addP[i1+1] + alpha * v3;
                } else if (epi == 3) {
                    v0 += addP[i0]; v1 += addP[i0+1];
                    v2 += addP[i1]; v3 += addP[i1+1];
                }
                *(float2*)(Cf + i0) = make_float2(v0, v1);
                *(float2*)(Cf + i1) = make_float2(v2, v3);
            }
        }
    }
}

#define SM_G128 75776
#define SM_G64  59392
#define SM_LM   122880
#define ATT_SMEM 184320

// ---------------- GEMM wrappers ----------------------------------------------
__global__ void __launch_bounds__(256) mma_proj(
    const bf16* __restrict__ Ah, const bf16* __restrict__ Al, int kIdx)
{
    extern __shared__ __align__(16) bf16 dsm[];
    int z = blockIdx.z;
    size_t wo = (size_t)kIdx * DD * DD;
    const bf16* Bh = (z == 0) ? g_WQh + wo : (z == 1) ? g_WKh + wo : g_WVh + wo;
    const bf16* Bl = (z == 0) ? g_WQl + wo : (z == 1) ? g_WKl + wo : g_WVl + wo;
    bf16* Ch = (z == 0) ? g_PQh : (z == 1) ? g_PKh : g_Vh;
    bf16* Cl = (z == 0) ? g_PQl : (z == 1) ? g_PKl : g_Vl;
    gemm_pipe<128>(dsm, Ah, Al, DD, Bh, Bl, DD,
                   nullptr, Ch, Cl, DD, blockIdx.y * 128, blockIdx.x * 128,
                   DD / 32, (z < 2) ? 1 : 4, nullptr, 0.f);
}

__global__ void __launch_bounds__(256) mma_wo(
    const bf16* __restrict__ Ah, const bf16* __restrict__ Al, int kIdx,
    float* __restrict__ C, const float* __restrict__ addP,
    const float* __restrict__ dt)
{
    extern __shared__ __align__(16) bf16 dsm[];
    size_t wo = (size_t)kIdx * DD * DD;
    float d = dt[kIdx];
    float alpha = (d > 20.0f) ? d : log1pf(expf(d));
    gemm_pipe<64>(dsm, Ah, Al, DD, g_WOh + wo, g_WOl + wo, DD,
                  C, nullptr, nullptr, DD, blockIdx.y * 128, blockIdx.x * 64,
                  DD / 32, 2, addP, alpha);
}

// mma_up with fused swiglu (permuted W_up; writes Hf fp32 directly)
__global__ void __launch_bounds__(256) mma_up(
    const bf16* __restrict__ Ah, const bf16* __restrict__ Al, int kIdx,
    float* __restrict__ Hf)
{
    extern __shared__ __align__(16) bf16 dsm[];
    size_t wo = (size_t)kIdx * DD * 2 * INNER;
    gemm_pipe<128>(dsm, Ah, Al, DD, g_WUh + wo, g_WUl + wo, 2 * INNER,
                   Hf, nullptr, nullptr, 2 * INNER, blockIdx.y * 128, blockIdx.x * 128,
                   DD / 32, 5, nullptr, 0.f);
}

__global__ void __launch_bounds__(256) mma_down(
    const bf16* __restrict__ Ah, const bf16* __restrict__ Al, int kIdx,
    float* __restrict__ C, const float* __restrict__ addP)
{
    extern __shared__ __align__(16) bf16 dsm[];
    size_t wo = (size_t)kIdx * INNER * DD;
    gemm_pipe<64>(dsm, Ah, Al, INNER, g_WDh + wo, g_WDl + wo, DD,
                  C, nullptr, nullptr, DD, blockIdx.y * 128, blockIdx.x * 64,
                  INNER / 32, 3, addP, 0.f);
}

// ---------------- fused flash attention (pipelined K/V) ----------------------
__device__ __forceinline__ void stage_kv(
    uint32_t base, int st, int kt, int tid, size_t rowbase,
    const bf16* __restrict__ PKh, const bf16* __restrict__ PKl,
    const bf16* __restrict__ Vh,  const bf16* __restrict__ Vl)
{
    const uint32_t QSZB = 128 * QS * 2;
    const uint32_t oKh = 2 * QSZB + st * QSZB;
    const uint32_t oKl = 4 * QSZB + st * QSZB;
    const uint32_t oVh = 6 * QSZB + st * QSZB;
    const uint32_t oVl = 8 * QSZB + st * QSZB;
    #pragma unroll
    for (int it2 = 0; it2 < 4; it2++) {
        int g = tid + 256 * it2;
        int row = g >> 3, c8 = (g & 7) * 8;
        size_t go = rowbase + (size_t)(kt * 128 + row) * DD + c8;
        uint32_t so = (uint32_t)(row * QS + c8) * 2;
        cpa16(base + oKh + so, PKh + go);
        cpa16(base + oKl + so, PKl + go);
        cpa16(base + oVh + so, Vh + go);
        cpa16(base + oVl + so, Vl + go);
    }
}

__global__ void __launch_bounds__(256) attn_fused(
    const bf16* __restrict__ PQh, const bf16* __restrict__ PQl,
    const bf16* __restrict__ PKh, const bf16* __restrict__ PKl,
    const bf16* __restrict__ Vh,  const bf16* __restrict__ Vl,
    bf16* __restrict__ Mh, bf16* __restrict__ Ml)
{
    extern __shared__ __align__(16) bf16 dsm[];
    const uint32_t base = smem_u32(dsm);
    const uint32_t QSZB = 128 * QS * 2;

    const int tid = threadIdx.x, lane = tid & 31, w = tid >> 5;
    const int bh = blockIdx.y, b = bh >> 3, h = bh & 7;
    const int q0 = blockIdx.x * 128;
    const size_t rowbase = (size_t)(b * NN) * DD + h * DH;

    #pragma unroll
    for (int it2 = 0; it2 < 4; it2++) {
        int g = tid + 256 * it2;
        int row = g >> 3, c8 = (g & 7) * 8;
        size_t go = rowbase + (size_t)(q0 + row) * DD + c8;
        uint32_t so = (uint32_t)(row * QS + c8) * 2;
        cpa16(base + so, PQh + go);
        cpa16(base + QSZB + so, PQl + go);
    }
    stage_kv(base, 0, 0, tid, rowbase, PKh, PKl, Vh, Vl);
    CP_COMMIT();
    CP_WAIT0();
    __syncthreads();

    uint32_t qh[4][4], ql[4][4];
    #pragma unroll
    for (int s = 0; s < 4; s++) {
        int r  = w * 16 + (lane & 15);
        int kb = s * 16 + ((lane >> 4) << 3);
        uint32_t so = (uint32_t)(r * QS + kb) * 2;
        ldm4(qh[s], base + so);
        ldm4(ql[s], base + QSZB + so);
    }

    float oacc[8][4];
    #pragma unroll
    for (int j = 0; j < 8; j++)
        #pragma unroll
        for (int q = 0; q < 4; q++) oacc[j][q] = 0.0f;
    float p0 = 0.0f, p1 = 0.0f;

    int st = 0;
    for (int kt = 0; kt < NN / 128; kt++) {
        if (kt + 1 < NN / 128) {
            stage_kv(base, st ^ 1, kt + 1, tid, rowbase, PKh, PKl, Vh, Vl);
            CP_COMMIT();
            CP_WAIT1();
        } else {
            CP_WAIT0();
        }
        __syncthreads();

        const uint32_t oKh = 2 * QSZB + st * QSZB;
        const uint32_t oKl = 4 * QSZB + st * QSZB;
        const uint32_t oVh = 6 * QSZB + st * QSZB;
        const uint32_t oVl = 8 * QSZB + st * QSZB;

        #pragma unroll
        for (int t = 0; t < 8; t++) {
            float sacc[2][4] = {};
            #pragma unroll
            for (int s = 0; s < 4; s++) {
                int r  = t * 16 + (lane & 7) + ((lane >> 4) << 3);
                int kb = s * 16 + (((lane >> 3) & 1) << 3);
                uint32_t so = (uint32_t)(r * QS + kb) * 2;
                uint32_t kh[4], kl[4];
                ldm4(kh, base + oKh + so);
                ldm4(kl, base + oKl + so);
                mma_bf16(sacc[0], qh[s], kh + 0);
                mma_bf16(sacc[0], ql[s], kh + 0);
                mma_bf16(sacc[0], qh[s], kl + 0);
                mma_bf16(sacc[1], qh[s], kh + 2);
                mma_bf16(sacc[1], ql[s], kh + 2);
                mma_bf16(sacc[1], qh[s], kl + 2);
            }
            float w2[2][4];
            #pragma unroll
            for (int f = 0; f < 2; f++)
                #pragma unroll
                for (int q = 0; q < 4; q++) {
                    float x = fmaxf(sacc[f][q], 0.0f);
                    w2[f][q] = x * x;
                }
            p0 += w2[0][0] + w2[0][1] + w2[1][0] + w2[1][1];
            p1 += w2[0][2] + w2[0][3] + w2[1][2] + w2[1][3];
            uint32_t wh[4], wl[4];
            {
                bf16 h0, h1, l0, l1;
                split1(w2[0][0], h0, l0); split1(w2[0][1], h1, l1);
                wh[0] = pack2(h0, h1); wl[0] = pack2(l0, l1);
                split1(w2[0][2], h0, l0); split1(w2[0][3], h1, l1);
                wh[1] = pack2(h0, h1); wl[1] = pack2(l0, l1);
                split1(w2[1][0], h0, l0); split1(w2[1][1], h1, l1);
                wh[2] = pack2(h0, h1); wl[2] = pack2(l0, l1);
                split1(w2[1][2], h0, l0); split1(w2[1][3], h1, l1);
                wh[3] = pack2(h0, h1); wl[3] = pack2(l0, l1);
            }
            #pragma unroll
            for (int n = 0; n < 4; n++) {
                int kk = t * 16 + (lane & 7) + ((lane >> 3) & 1) * 8;
                int nn = n * 16 + (lane >> 4) * 8;
                uint32_t so = (uint32_t)(kk * QS + nn) * 2;
                uint32_t vh[4], vl[4];
                ldm4t(vh, base + oVh + so);
                ldm4t(vl, base + oVl + so);
                mma_bf16(oacc[2*n],   wh, vh + 0);
                mma_bf16(oacc[2*n],   wl, vh + 0);
                mma_bf16(oacc[2*n],   wh, vl + 0);
                mma_bf16(oacc[2*n+1], wh, vh + 2);
                mma_bf16(oacc[2*n+1], wl, vh + 2);
                mma_bf16(oacc[2*n+1], wh, vl + 2);
            }
        }
        __syncthreads();
        st ^= 1;
    }

    p0 += __shfl_xor_sync(0xFFFFFFFFu, p0, 1);
    p0 += __shfl_xor_sync(0xFFFFFFFFu, p0, 2);
    p1 += __shfl_xor_sync(0xFFFFFFFFu, p1, 1);
    p1 += __shfl_xor_sync(0xFFFFFFFFu, p1, 2);
    float rd0 = 1.0f / (p0 + 1.0f);
    float rd1 = 1.0f / (p1 + 1.0f);

    int r0 = q0 + w * 16 + (lane >> 2);
    int r1 = r0 + 8;
    #pragma unroll
    for (int j = 0; j < 8; j++) {
        int d = j * 8 + (lane & 3) * 2;
        size_t i0 = rowbase + (size_t)r0 * DD + d;
        size_t i1 = rowbase + (size_t)r1 * DD + d;
        uint32_t vh0 = *(const uint32_t*)(Vh + i0), vl0 = *(const uint32_t*)(Vl + i0);
        uint32_t vh1 = *(const uint32_t*)(Vh + i1), vl1 = *(const uint32_t*)(Vl + i1);
        float vp00 = __bfloat162float(__ushort_as_bfloat16((unsigned short)(vh0 & 0xFFFF))) +
                     __bfloat162float(__ushort_as_bfloat16((unsigned short)(vl0 & 0xFFFF)));
        float vp01 = __bfloat162float(__ushort_as_bfloat16((unsigned short)(vh0 >> 16))) +
                     __bfloat162float(__ushort_as_bfloat16((unsigned short)(vl0 >> 16)));
        float vp10 = __bfloat162float(__ushort_as_bfloat16((unsigned short)(vh1 & 0xFFFF))) +
                     __bfloat162float(__ushort_as_bfloat16((unsigned short)(vl1 & 0xFFFF)));
        float vp11 = __bfloat162float(__ushort_as_bfloat16((unsigned short)(vh1 >> 16))) +
                     __bfloat162float(__ushort_as_bfloat16((unsigned short)(vl1 >> 16)));
        float m00 = oacc[j][0] * rd0 - vp00;
        float m01 = oacc[j][1] * rd0 - vp01;
        float m10 = oacc[j][2] * rd1 - vp10;
        float m11 = oacc[j][3] * rd1 - vp11;
        bf16 h0, h1, l0, l1;
        split1(m00, h0, l0); split1(m01, h1, l1);
        *(uint32_t*)(Mh + i0) = pack2(h0, h1);
        *(uint32_t*)(Ml + i0) = pack2(l0, l1);
        split1(m10, h0, l0); split1(m11, h1, l1);
        *(uint32_t*)(Mh + i1) = pack2(h0, h1);
        *(uint32_t*)(Ml + i1) = pack2(l0, l1);
    }
}

// ---------------- LM head: 256x128 tiles, 512 threads -------------------------
__device__ __forceinline__ void stage_lm(
    uint32_t base, int st, int kc, int tid, int m0, int n0,
    const bf16* __restrict__ Ah, const bf16* __restrict__ Al)
{
    constexpr uint32_t ASZ = 256 * AMS, BSZ = 128 * AMS;
    const uint32_t oAh = 0, oAl = 2 * ASZ * 2;
    const uint32_t oBh = 4 * ASZ * 2, oBl = (4 * ASZ + 2 * BSZ) * 2;
    #pragma unroll
    for (int it2 = 0; it2 < 2; it2++) {
        int g = tid + 512 * it2;                  // 1024 A-transfers
        int row = g >> 2, c8 = (g & 3) * 8;
        uint32_t so = (uint32_t)(st * ASZ + row * AMS + c8) * 2;
        size_t ga = (size_t)(m0 + row) * DD + kc * 32 + c8;
        cpa16(base + oAh + so, Ah + ga);
        cpa16(base + oAl + so, Al + ga);
    }
    {
        int g = tid;                              // 512 B-transfers
        int row = g >> 2, c8 = (g & 3) * 8;
        uint32_t so = (uint32_t)(st * BSZ + row * AMS + c8) * 2;
        size_t gb = (size_t)(n0 + row) * DD + kc * 32 + c8;
        cpa16(base + oBh + so, g_LMh + gb);
        cpa16(base + oBl + so, g_LMl + gb);
    }
}

__global__ void __launch_bounds__(512)
lm_head_mma(const bf16* __restrict__ Ah, const bf16* __restrict__ Al,
            float* __restrict__ C)
{
    extern __shared__ __align__(16) bf16 dsm[];
    constexpr uint32_t ASZ = 256 * AMS, BSZ = 128 * AMS;
    const uint32_t base = smem_u32(dsm);
    const uint32_t oAh = 0, oAl = 2 * ASZ * 2;
    const uint32_t oBh = 4 * ASZ * 2, oBl = (4 * ASZ + 2 * BSZ) * 2;
    const int tid = threadIdx.x, lane = tid & 31, wid = tid >> 5;
    const int warp_m = wid >> 1, warp_n = wid & 1;   // 8 x 2 warps
    const int m0 = blockIdx.y * 256, n0 = blockIdx.x * 128;

    float acc[2][8][4];
    #pragma unroll
    for (int i = 0; i < 2; i++)
        #pragma unroll
        for (int j = 0; j < 8; j++)
            #pragma unroll
            for (int q = 0; q < 4; q++) acc[i][j][q] = 0.0f;

    stage_lm(base, 0, 0, tid, m0, n0, Ah, Al);
    CP_COMMIT();

    int st = 0;
    for (int kc = 0; kc < 16; kc++) {
        if (kc + 1 < 16) {
            stage_lm(base, st ^ 1, kc + 1, tid, m0, n0, Ah, Al);
            CP_COMMIT();
            CP_WAIT1();
        } else {
            CP_WAIT0();
        }
        __syncthreads();

        #pragma unroll
        for (int s = 0; s < 2; s++) {
            uint32_t ah[2][4], al[2][4], bh[8][2], bl[8][2];
            #pragma unroll
            for (int i = 0; i < 2; i++) {
                int r  = warp_m * 32 + i * 16 + (lane & 15);
                int kb = s * 16 + ((lane >> 4) << 3);
                uint32_t so = (uint32_t)(st * ASZ + r * AMS + kb) * 2;
                ldm4(ah[i], base + oAh + so);
                ldm4(al[i], base + oAl + so);
            }
            #pragma unroll
            for (int j = 0; j < 4; j++) {
                int r  = warp_n * 64 + j * 16 + (lane & 7) + ((lane >> 4) << 3);
                int kb = s * 16 + (((lane >> 3) & 1) << 3);
                uint32_t so = (uint32_t)(st * BSZ + r * AMS + kb) * 2;
                uint32_t q[4];
                ldm4(q, base + oBh + so);
                bh[2*j][0] = q[0]; bh[2*j][1] = q[1];
                bh[2*j+1][0] = q[2]; bh[2*j+1][1] = q[3];
                ldm4(q, base + oBl + so);
                bl[2*j][0] = q[0]; bl[2*j][1] = q[1];
                bl[2*j+1][0] = q[2]; bl[2*j+1][1] = q[3];
            }
            #pragma unroll
            for (int i = 0; i < 2; i++)
                #pragma unroll
                for (int j = 0; j < 8; j++) {
                    mma_bf16(acc[i][j], ah[i], bh[j]);
                    mma_bf16(acc[i][j], al[i], bh[j]);
                    mma_bf16(acc[i][j], ah[i], bl[j]);
                }
        }
        __syncthreads();
        st ^= 1;
    }

    #pragma unroll
    for (int i = 0; i < 2; i++) {
        int m = m0 + warp_m * 32 + i * 16 + (lane >> 2);
        #pragma unroll
        for (int j = 0; j < 8; j++) {
            int n = n0 + warp_n * 64 + j * 8 + (lane & 3) * 2;
            *(float2*)(C + (size_t)m * VV + n) =
                make_float2(acc[i][j][0], acc[i][j][1]);
            *(float2*)(C + (size_t)(m + 8) * VV + n) =
                make_float2(acc[i][j][2], acc[i][j][3]);
        }
    }
}

// ---------------- init -------------------------------------------------------
__global__ void init_kernel(const int* __restrict__ inputs,
                            const int* __restrict__ carry_inputs,
                            const void* __restrict__ halted,
                            const float* __restrict__ carry_hidden,
                            const float* __restrict__ init_hidden,
                            const float* __restrict__ emb,
                            const float* __restrict__ pos,
                            const float* __restrict__ in_s,
                            const float* __restrict__ in_b)
{
    int r = blockIdx.x;
    int b = r / NN, n = r % NN;
    int t = threadIdx.x;
    bool h = read_halted(halted, b);
    int idx = h ? inputs[r] : carry_inputs[r];
    const float* e = emb + (size_t)idx * DD;
    const float* p = pos + (size_t)n * DD;

    float x0 = e[t]       + p[t];
    float x1 = e[t + 256] + p[t + 256];

    size_t base = (size_t)r * DD;
    g_Q[base + t]       = h ? init_hidden[t]       : carry_hidden[base + t];
    g_Q[base + t + 256] = h ? init_hidden[t + 256] : carry_hidden[base + t + 256];

    __shared__ float s_sum[256], s_sq[256];
    s_sum[t] = x0 + x1;
    s_sq[t]  = x0 * x0 + x1 * x1;
    __syncthreads();
    for (int o = 128; o > 0; o >>= 1) {
        if (t < o) { s_sum[t] += s_sum[t + o]; s_sq[t] += s_sq[t + o]; }
        __syncthreads();
    }
    float mu   = s_sum[0] * (1.0f / DD);
    float var  = s_sq[0] * (1.0f / DD) - mu * mu;
    float rstd = rsqrtf(var + 1e-5f);
    g_X[base + t]       = (x0 - mu) * rstd * in_s[t]       + in_b[t];
    g_X[base + t + 256] = (x1 - mu) * rstd * in_s[t + 256] + in_b[t + 256];
}

// ---------------- LayerNorm --------------------------------------------------
__global__ void ln_kernel(const float* __restrict__ in, float* __restrict__ outf,
                          bf16* __restrict__ outh, bf16* __restrict__ outl,
                          const float* __restrict__ s, const float* __restrict__ bia,
                          const float* __restrict__ add)
{
    int r = blockIdx.x;
    int t = threadIdx.x;
    size_t base = (size_t)r * DD;
    float x0 = in[base + t];
    float x1 = in[base + t + 256];

    __shared__ float s_sum[256], s_sq[256];
    s_sum[t] = x0 + x1;
    s_sq[t]  = x0 * x0 + x1 * x1;
    __syncthreads();
    for (int o = 128; o > 0; o >>= 1) {
        if (t < o) { s_sum[t] += s_sum[t + o]; s_sq[t] += s_sq[t + o]; }
        __syncthreads();
    }
    float mu   = s_sum[0] * (1.0f / DD);
    float var  = s_sq[0] * (1.0f / DD) - mu * mu;
    float rstd = rsqrtf(var + 1e-5f);
    float v0 = (x0 - mu) * rstd * s[t]       + bia[t];
    float v1 = (x1 - mu) * rstd * s[t + 256] + bia[t + 256];
    if (add) { v0 += add[base + t]; v1 += add[base + t + 256]; }
    if (outf) { outf[base + t] = v0; outf[base + t + 256] = v1; }
    if (outh) {
        bf16 h0, l0, h1, l1;
        split1(v0, h0, l0); split1(v1, h1, l1);
        outh[base + t] = h0;       outl[base + t] = l0;
        outh[base + t + 256] = h1; outl[base + t + 256] = l1;
    }
}

// ---------------- depthwise conv k=3 + bias + silu -> hi/lo ------------------
__global__ void conv_kernel(const float* __restrict__ Hf, const float* __restrict__ w,
                            const float* __restrict__ bias,
                            bf16* __restrict__ outh, bf16* __restrict__ outl)
{
    size_t i = (size_t)blockIdx.x * 256 + threadIdx.x;
    if (i >= (size_t)MROWS * INNER) return;
    size_t row = i / INNER;
    int c = (int)(i % INNER);
    int n = (int)(row % NN);
    const float* wc = w + (size_t)c * CKW;
    float acc = bias[c];
    if (n > 0)      acc += wc[0] * Hf[(row - 1) * INNER + c];
    acc += wc[1] * Hf[row * INNER + c];
    if (n < NN - 1) acc += wc[2] * Hf[(row + 1) * INNER + c];
    float v = siluf(acc);
    bf16 h, l;
    split1(v, h, l);
    outh[i] = h;
    outl[i] = l;
}

// ---------------- halt head --------------------------------------------------
__global__ void halt_kernel(const float* __restrict__ Qn, const float* __restrict__ hw,
                            const float* __restrict__ hb, float* __restrict__ out)
{
    int b = blockIdx.x;
    int t = threadIdx.x;
    __shared__ float md[DD];
    for (int d = t; d < DD; d += 256) {
        float s = 0.0f;
        for (int n = 0; n < NN; n++)
            s += Qn[((size_t)(b * NN + n)) * DD + d];
        md[d] = s * (1.0f / NN);
    }
    __syncthreads();
    __shared__ float r0[256], r1[256];
    float p0 = 0.0f, p1 = 0.0f;
    for (int d = t; d < DD; d += 256) {
        p0 += md[d] * hw[d];
        p1 += md[d] * hw[DD + d];
    }
    r0[t] = p0; r1[t] = p1;
    __syncthreads();
    for (int o = 128; o > 0; o >>= 1) {
        if (t < o) { r0[t] += r0[t + o]; r1[t] += r1[t + o]; }
        __syncthreads();
    }
    if (t == 0) {
        out[b * 2 + 0] = r0[0] + hb[0];
        out[b * 2 + 1] = r1[0] + hb[1];
    }
}

// ---------------- host orchestration -----------------------------------------
static void cvt(const float* src, bf16* h, bf16* l, size_t n)
{
    int n4 = (int)(n / 4);
    cvt_kernel<<<(n4 + 255) / 256, 256>>>(src, h, l, n4);
}

extern "C" void kernel_launch(void* const* d_in, const int* in_sizes, int n_in,
                              void* d_out, int out_size)
{
    const int*   inputs       = (const int*)d_in[0];
    const float* carry_hidden = (const float*)d_in[2];
    const void*  halted       = d_in[4];
    const int*   carry_inputs = (const int*)d_in[5];
    const float* init_hidden  = (const float*)d_in[7];
    const float* emb          = (const float*)d_in[8];
    const float* pos          = (const float*)d_in[9];
    const float* in_s         = (const float*)d_in[10];
    const float* in_b         = (const float*)d_in[11];
    const float* fin_s        = (const float*)d_in[12];
    const float* fin_b        = (const float*)d_in[13];
    const float* lm_w         = (const float*)d_in[14];
    const float* halt_w       = (const float*)d_in[15];
    const float* halt_b       = (const float*)d_in[16];
    const float* dt           = (const float*)d_in[17];
    const float* W_Q          = (const float*)d_in[18];
    const float* W_K          = (const float*)d_in[19];
    const float* W_V          = (const float*)d_in[20];
    const float* W_O          = (const float*)d_in[21];
    const float* W_up         = (const float*)d_in[22];
    const float* dw_w         = (const float*)d_in[23];
    const float* dw_b         = (const float*)d_in[24];
    const float* W_down       = (const float*)d_in[25];
    const float* n1_s         = (const float*)d_in[26];
    const float* n1_b         = (const float*)d_in[27];
    const float* n2_s         = (const float*)d_in[28];
    const float* n2_b         = (const float*)d_in[29];

    float *X, *Q, *Qi, *Qn, *Hf;
    bf16 *Hch, *Hcl, *PQh, *PQl, *PKh, *PKl, *Vh, *Vl, *mbh, *mbl;
    bf16 *Q2h, *Q2l, *Hvh, *Hvl, *Qnh, *Qnl;
    bf16 *WQh, *WQl, *WKh, *WKl, *WVh, *WVl, *WOh, *WOl;
    bf16 *WUh, *WUl, *WDh, *WDl, *LMh, *LMl;
    cudaGetSymbolAddress((void**)&X,   g_X);
    cudaGetSymbolAddress((void**)&Q,   g_Q);
    cudaGetSymbolAddress((void**)&Qi,  g_Qi);
    cudaGetSymbolAddress((void**)&Qn,  g_Qn);
    cudaGetSymbolAddress((void**)&Hf,  g_Hf);
    cudaGetSymbolAddress((void**)&Hch, g_Hch); cudaGetSymbolAddress((void**)&Hcl, g_Hcl);
    cudaGetSymbolAddress((void**)&PQh, g_PQh); cudaGetSymbolAddress((void**)&PQl, g_PQl);
    cudaGetSymbolAddress((void**)&PKh, g_PKh); cudaGetSymbolAddress((void**)&PKl, g_PKl);
    cudaGetSymbolAddress((void**)&Vh,  g_Vh);  cudaGetSymbolAddress((void**)&Vl,  g_Vl);
    cudaGetSymbolAddress((void**)&mbh, g_mbh); cudaGetSymbolAddress((void**)&mbl, g_mbl);
    cudaGetSymbolAddress((void**)&Q2h, g_Q2h); cudaGetSymbolAddress((void**)&Q2l, g_Q2l);
    cudaGetSymbolAddress((void**)&Hvh, g_Hvh); cudaGetSymbolAddress((void**)&Hvl, g_Hvl);
    cudaGetSymbolAddress((void**)&Qnh, g_Qnh); cudaGetSymbolAddress((void**)&Qnl, g_Qnl);
    cudaGetSymbolAddress((void**)&WQh, g_WQh); cudaGetSymbolAddress((void**)&WQl, g_WQl);
    cudaGetSymbolAddress((void**)&WKh, g_WKh); cudaGetSymbolAddress((void**)&WKl, g_WKl);
    cudaGetSymbolAddress((void**)&WVh, g_WVh); cudaGetSymbolAddress((void**)&WVl, g_WVl);
    cudaGetSymbolAddress((void**)&WOh, g_WOh); cudaGetSymbolAddress((void**)&WOl, g_WOl);
    cudaGetSymbolAddress((void**)&WUh, g_WUh); cudaGetSymbolAddress((void**)&WUl, g_WUl);
    cudaGetSymbolAddress((void**)&WDh, g_WDh); cudaGetSymbolAddress((void**)&WDl, g_WDl);
    cudaGetSymbolAddress((void**)&LMh, g_LMh); cudaGetSymbolAddress((void**)&LMl, g_LMl);

    float* out = (float*)d_out;

    cudaFuncSetAttribute(attn_fused, cudaFuncAttributeMaxDynamicSharedMemorySize, ATT_SMEM);
    cudaFuncSetAttribute(mma_proj,   cudaFuncAttributeMaxDynamicSharedMemorySize, SM_G128);
    cudaFuncSetAttribute(mma_up,     cudaFuncAttributeMaxDynamicSharedMemorySize, SM_G128);
    cudaFuncSetAttribute(mma_wo,     cudaFuncAttributeMaxDynamicSharedMemorySize, SM_G64);
    cudaFuncSetAttribute(mma_down,   cudaFuncAttributeMaxDynamicSharedMemorySize, SM_G64);
    cudaFuncSetAttribute(lm_head_mma, cudaFuncAttributeMaxDynamicSharedMemorySize, SM_LM);

    // weight pre-split (W_up permuted for fused swiglu)
    cvt(W_Q,    WQh, WQl, (size_t)KKB * DD * DD);
    cvt(W_K,    WKh, WKl, (size_t)KKB * DD * DD);
    cvt(W_V,    WVh, WVl, (size_t)KKB * DD * DD);
    cvt(W_O,    WOh, WOl, (size_t)KKB * DD * DD);
    {
        int total = KKB * DD * (2 * INNER) / 8;
        cvt_up_kernel<<<(total + 255) / 256, 256>>>(W_up, WUh, WUl);
    }
    cvt(W_down, WDh, WDl, (size_t)KKB * INNER * DD);
    cvt(lm_w,   LMh, LMl, (size_t)VV * DD);

    init_kernel<<<MROWS, 256>>>(inputs, carry_inputs, halted, carry_hidden,
                                init_hidden, emb, pos, in_s, in_b);

    dim3 gP(DD / 128, MROWS / 128, 3);        // (4, 16, 3)
    dim3 gO64(DD / 64, MROWS / 128);          // (8, 16) = 128 CTAs
    dim3 gUP(2 * INNER / 128, MROWS / 128);   // (24, 16)
    dim3 gAT(NN / 128, BHN);                  // (8, 16)

    for (int it = 0; it < TOTAL_PASSES; it++) {
        int k = it % KKB;

        ln_kernel<<<MROWS, 256>>>(Q, nullptr, Hch, Hcl,
                                  n1_s + k * DD, n1_b + k * DD, X);

        mma_proj<<<gP, 256, SM_G128>>>(Hch, Hcl, k);

        attn_fused<<<gAT, 256, ATT_SMEM>>>(PQh, PQl, PKh, PKl, Vh, Vl, mbh, mbl);

        mma_wo<<<gO64, 256, SM_G64>>>(mbh, mbl, k, Qi, Q, dt);

        ln_kernel<<<MROWS, 256>>>(Qi, nullptr, Q2h, Q2l,
                                  n2_s + k * DD, n2_b + k * DD, nullptr);
        mma_up<<<gUP, 256, SM_G128>>>(Q2h, Q2l, k, Hf);    // fused swiglu
        int tot = MROWS * INNER;
        conv_kernel<<<(tot + 255) / 256, 256>>>(Hf, dw_w + (size_t)k * INNER * CKW,
                                                dw_b + (size_t)k * INNER, Hvh, Hvl);
        mma_down<<<gO64, 256, SM_G64>>>(Hvh, Hvl, k, Q, Qi);
    }

    ln_kernel<<<MROWS, 256>>>(Q, Qn, Qnh, Qnl, fin_s, fin_b, nullptr);
    dim3 gLM(VV / 128, MROWS / 256);          // (250, 8)
    lm_head_mma<<<gLM, 512, SM_LM>>>(Qnh, Qnl, out);
    halt_kernel<<<BB, 256>>>(Qn, halt_w, halt_b, out + (size_t)MROWS * VV);
}

// round 10
// speedup vs baseline: 2.7562x; 1.0324x over previous
#include <cuda_runtime.h>
#include <cuda_bf16.h>
#include <math.h>
#include <stdint.h>

// Problem constants
#define BB    2
#define NN    1024
#define DD    512
#define HH    8
#define DH    64
#define KKB   4
#define VV    32000
#define INNER 1536
#define CKW   3
#define MROWS (BB*NN)     // 2048
#define BHN   (BB*HH)     // 16
#define TOTAL_PASSES 8

#define AMS  40    // A smem stride (bf16): 32 data + 8 pad
#define QS   72    // attention smem stride (64 + 8)

typedef __nv_bfloat16 bf16;

// ---------------- fp32 scratch ----------------------------------------------
__device__ __align__(16) float g_X  [MROWS*DD];
__device__ __align__(16) float g_Q  [MROWS*DD];
__device__ __align__(16) float g_Qi [MROWS*DD];
__device__ __align__(16) float g_Qn [MROWS*DD];
__device__ __align__(16) float g_Hf [(size_t)MROWS*INNER];

// ---------------- bf16 hi/lo activation scratch ------------------------------
__device__ __align__(16) bf16 g_Hch [MROWS*DD], g_Hcl [MROWS*DD];
__device__ __align__(16) bf16 g_PQh [MROWS*DD], g_PQl [MROWS*DD];
__device__ __align__(16) bf16 g_PKh [MROWS*DD], g_PKl [MROWS*DD];
__device__ __align__(16) bf16 g_Vh  [MROWS*DD], g_Vl  [MROWS*DD];
__device__ __align__(16) bf16 g_mbh [MROWS*DD], g_mbl [MROWS*DD];
__device__ __align__(16) bf16 g_Q2h [MROWS*DD], g_Q2l [MROWS*DD];
__device__ __align__(16) bf16 g_Hvh [(size_t)MROWS*INNER], g_Hvl [(size_t)MROWS*INNER];
__device__ __align__(16) bf16 g_Qnh [MROWS*DD], g_Qnl [MROWS*DD];

// ---------------- bf16 hi/lo weight scratch ----------------------------------
__device__ __align__(16) bf16 g_WQh [KKB*DD*DD],   g_WQl [KKB*DD*DD];
__device__ __align__(16) bf16 g_WKh [KKB*DD*DD],   g_WKl [KKB*DD*DD];
__device__ __align__(16) bf16 g_WVh [KKB*DD*DD],   g_WVl [KKB*DD*DD];
__device__ __align__(16) bf16 g_WOh [KKB*DD*DD],   g_WOl [KKB*DD*DD];
__device__ __align__(16) bf16 g_WUh [(size_t)KKB*DD*2*INNER], g_WUl [(size_t)KKB*DD*2*INNER];
__device__ __align__(16) bf16 g_WDh [(size_t)KKB*INNER*DD],   g_WDl [(size_t)KKB*INNER*DD];
__device__ __align__(16) bf16 g_LMh [(size_t)VV*DD], g_LMl [(size_t)VV*DD];

// ---------------- helpers ----------------------------------------------------
__device__ __forceinline__ float siluf(float x) { return x / (1.0f + expf(-x)); }

__device__ __forceinline__ bool read_halted(const void* p, int b)
{
    const unsigned char* u8 = (const unsigned char*)p;
    if (u8[1] != 0) return u8[b] != 0;
    return ((const int*)p)[b] != 0;
}
__device__ __forceinline__ uint32_t smem_u32(const void* p) {
    uint32_t a;
    asm("{ .reg .u64 t; cvta.to.shared.u64 t, %1; cvt.u32.u64 %0, t; }"
        : "=r"(a) : "l"(p));
    return a;
}
__device__ __forceinline__ void ldm4(uint32_t* r, uint32_t a) {
    asm volatile("ldmatrix.sync.aligned.m8n8.x4.shared.b16 {%0,%1,%2,%3}, [%4];"
                 : "=r"(r[0]), "=r"(r[1]), "=r"(r[2]), "=r"(r[3]) : "r"(a));
}
__device__ __forceinline__ void ldm4t(uint32_t* r, uint32_t a) {
    asm volatile("ldmatrix.sync.aligned.m8n8.x4.trans.shared.b16 {%0,%1,%2,%3}, [%4];"
                 : "=r"(r[0]), "=r"(r[1]), "=r"(r[2]), "=r"(r[3]) : "r"(a));
}
__device__ __forceinline__ void mma_bf16(float* c, const uint32_t* a, const uint32_t* b) {
    asm volatile("mma.sync.aligned.m16n8k16.row.col.f32.bf16.bf16.f32 "
                 "{%0,%1,%2,%3}, {%4,%5,%6,%7}, {%8,%9}, {%0,%1,%2,%3};"
                 : "+f"(c[0]), "+f"(c[1]), "+f"(c[2]), "+f"(c[3])
                 : "r"(a[0]), "r"(a[1]), "r"(a[2]), "r"(a[3]),
                   "r"(b[0]), "r"(b[1]));
}
__device__ __forceinline__ uint32_t pack2(bf16 a, bf16 b) {
    return (uint32_t)__bfloat16_as_ushort(a) |
           ((uint32_t)__bfloat16_as_ushort(b) << 16);
}
__device__ __forceinline__ void split1(float v, bf16& h, bf16& l) {
    h = __float2bfloat16(v);
    l = __float2bfloat16(v - __bfloat162float(h));
}
__device__ __forceinline__ void cpa16(uint32_t s, const void* g) {
    asm volatile("cp.async.cg.shared.global [%0], [%1], 16;" :: "r"(s), "l"(g));
}
#define CP_COMMIT() asm volatile("cp.async.commit_group;" ::: "memory")
#define CP_WAIT0()  asm volatile("cp.async.wait_group 0;" ::: "memory")
#define CP_WAIT1()  asm volatile("cp.async.wait_group 1;" ::: "memory")

// ---------------- weight/activation converter --------------------------------
__global__ void cvt_kernel(const float* __restrict__ src, bf16* __restrict__ h,
                           bf16* __restrict__ l, int n4)
{
    int i = blockIdx.x * 256 + threadIdx.x;
    if (i >= n4) return;
    float4 v = *(const float4*)(src + (size_t)i * 4);
    bf16 h0, h1, h2, h3, l0, l1, l2, l3;
    split1(v.x, h0, l0); split1(v.y, h1, l1);
    split1(v.z, h2, l2); split1(v.w, h3, l3);
    *(uint2*)(h + (size_t)i * 4) = make_uint2(pack2(h0, h1), pack2(h2, h3));
    *(uint2*)(l + (size_t)i * 4) = make_uint2(pack2(l0, l1), pack2(l2, l3));
}

// W_up converter with G/U column interleave: dest col 2c = G_c, 2c+1 = U_c
__global__ void cvt_up_kernel(const float* __restrict__ src, bf16* __restrict__ h,
                              bf16* __restrict__ l)
{
    int gi = blockIdx.x * 256 + threadIdx.x;
    int total = KKB * DD * (2 * INNER) / 8;
    if (gi >= total) return;
    int cg8 = gi % (2 * INNER / 8);
    int row = gi / (2 * INNER / 8);
    int cg = cg8 * 4;
    size_t rb = (size_t)row * (2 * INNER);
    float4 gsrc = *(const float4*)(src + rb + cg);
    float4 usrc = *(const float4*)(src + rb + INNER + cg);
    float gv[4] = {gsrc.x, gsrc.y, gsrc.z, gsrc.w};
    float uv[4] = {usrc.x, usrc.y, usrc.z, usrc.w};
    uint32_t hw[4], lw[4];
    #pragma unroll
    for (int q = 0; q < 4; q++) {
        bf16 gh, gl, uh, ul;
        split1(gv[q], gh, gl);
        split1(uv[q], uh, ul);
        hw[q] = pack2(gh, uh);
        lw[q] = pack2(gl, ul);
    }
    size_t db = rb + (size_t)cg8 * 8;
    *(uint4*)(h + db) = make_uint4(hw[0], hw[1], hw[2], hw[3]);
    *(uint4*)(l + db) = make_uint4(lw[0], lw[1], lw[2], lw[3]);
}

// ---------------- pipelined bf16x3 GEMM body ---------------------------------
template <int BN>
__device__ __forceinline__ void stage_gemm(
    uint32_t base, int st, int kc, int tid, int m0, int n0,
    const bf16* __restrict__ Ah, const bf16* __restrict__ Al, int lda,
    const bf16* __restrict__ Bh, const bf16* __restrict__ Bl, int ldb)
{
    constexpr int BNS_ = (BN == 128) ? 136 : 72;
    constexpr uint32_t ASZ = 128 * AMS, BSZ = 32 * BNS_;
    const uint32_t oAh = 0, oAl = 2 * ASZ * 2;
    const uint32_t oBh = 4 * ASZ * 2, oBl = (4 * ASZ + 2 * BSZ) * 2;
    #pragma unroll
    for (int it2 = 0; it2 < 2; it2++) {
        int g = tid + 256 * it2;
        int row = g >> 2, c8 = (g & 3) * 8;
        size_t go = (size_t)(m0 + row) * lda + kc * 32 + c8;
        uint32_t so = (uint32_t)(st * ASZ + row * AMS + c8) * 2;
        cpa16(base + oAh + so, Ah + go);
        cpa16(base + oAl + so, Al + go);
    }
    #pragma unroll
    for (int it2 = 0; it2 < BN / 64; it2++) {
        int g = tid + 256 * it2;
        int row = g / (BN / 8), c8 = (g % (BN / 8)) * 8;
        size_t go = (size_t)(kc * 32 + row) * ldb + n0 + c8;
        uint32_t so = (uint32_t)(st * BSZ + row * BNS_ + c8) * 2;
        cpa16(base + oBh + so, Bh + go);
        cpa16(base + oBl + so, Bl + go);
    }
}

// epi: 0 fp32, 1 hi/lo elu+1, 2 fp32 addP+alpha*acc, 3 fp32 addP+acc,
//      4 hi/lo plain, 5 fused swiglu
template <int BN>
__device__ __forceinline__ void gemm_pipe(
    bf16* smem,
    const bf16* __restrict__ Ah, const bf16* __restrict__ Al, int lda,
    const bf16* __restrict__ Bh, const bf16* __restrict__ Bl, int ldb,
    float* __restrict__ Cf, bf16* __restrict__ Ch, bf16* __restrict__ Cl, int ldc,
    int m0, int n0, int kch, int epi, const float* __restrict__ addP, float alpha)
{
    constexpr int BNS_ = (BN == 128) ? 136 : 72;
    constexpr int NJ = BN / 16;
    constexpr uint32_t ASZ = 128 * AMS, BSZ = 32 * BNS_;
    const uint32_t base = smem_u32(smem);
    const uint32_t oAh = 0, oAl = 2 * ASZ * 2;
    const uint32_t oBh = 4 * ASZ * 2, oBl = (4 * ASZ + 2 * BSZ) * 2;
    const int tid = threadIdx.x, lane = tid & 31, wid = tid >> 5;
    const int warp_m = wid >> 1, warp_n = wid & 1;

    float acc[2][NJ][4];
    #pragma unroll
    for (int i = 0; i < 2; i++)
        #pragma unroll
        for (int j = 0; j < NJ; j++)
            #pragma unroll
            for (int q = 0; q < 4; q++) acc[i][j][q] = 0.0f;

    stage_gemm<BN>(base, 0, 0, tid, m0, n0, Ah, Al, lda, Bh, Bl, ldb);
    CP_COMMIT();

    int st = 0;
    for (int kc = 0; kc < kch; kc++) {
        if (kc + 1 < kch) {
            stage_gemm<BN>(base, st ^ 1, kc + 1, tid, m0, n0, Ah, Al, lda, Bh, Bl, ldb);
            CP_COMMIT();
            CP_WAIT1();
        } else {
            CP_WAIT0();
        }
        __syncthreads();

        #pragma unroll
        for (int s = 0; s < 2; s++) {
            uint32_t ah[2][4], al[2][4], bh[NJ][2], bl[NJ][2];
            #pragma unroll
            for (int i = 0; i < 2; i++) {
                int r  = warp_m * 32 + i * 16 + (lane & 15);
                int kb = s * 16 + ((lane >> 4) << 3);
                uint32_t so = (uint32_t)(st * ASZ + r * AMS + kb) * 2;
                ldm4(ah[i], base + oAh + so);
                ldm4(al[i], base + oAl + so);
            }
            #pragma unroll
            for (int j2 = 0; j2 < NJ / 2; j2++) {
                int kk = s * 16 + (lane & 7) + ((lane >> 3) & 1) * 8;
                int nn = warp_n * (BN / 2) + j2 * 16 + (lane >> 4) * 8;
                uint32_t so = (uint32_t)(st * BSZ + kk * BNS_ + nn) * 2;
                uint32_t q[4];
                ldm4t(q, base + oBh + so);
                bh[2*j2][0] = q[0]; bh[2*j2][1] = q[1];
                bh[2*j2+1][0] = q[2]; bh[2*j2+1][1] = q[3];
                ldm4t(q, base + oBl + so);
                bl[2*j2][0] = q[0]; bl[2*j2][1] = q[1];
                bl[2*j2+1][0] = q[2]; bl[2*j2+1][1] = q[3];
            }
            #pragma unroll
            for (int i = 0; i < 2; i++)
                #pragma unroll
                for (int j = 0; j < NJ; j++) {
                    mma_bf16(acc[i][j], ah[i], bh[j]);
                    mma_bf16(acc[i][j], al[i], bh[j]);
                    mma_bf16(acc[i][j], ah[i], bl[j]);
                }
        }
        __syncthreads();
        st ^= 1;
    }

    #pragma unroll
    for (int i = 0; i < 2; i++) {
        int m = m0 + warp_m * 32 + i * 16 + (lane >> 2);
        #pragma unroll
        for (int j = 0; j < NJ; j++) {
            int n = n0 + warp_n * (BN / 2) + j * 8 + (lane & 3) * 2;
            float v0 = acc[i][j][0], v1 = acc[i][j][1];
            float v2 = acc[i][j][2], v3 = acc[i][j][3];
            if (epi == 5) {
                int col = n >> 1;
                Cf[(size_t)m * INNER + col]       = siluf(v0) * v1;
                Cf[(size_t)(m + 8) * INNER + col] = siluf(v2) * v3;
                continue;
            }
            size_t i0 = (size_t)m * ldc + n;
            size_t i1 = (size_t)(m + 8) * ldc + n;
            if (epi == 1 || epi == 4) {
                if (epi == 1) {
                    v0 = (v0 > 0.f) ? v0 + 1.f : expf(v0);
                    v1 = (v1 > 0.f) ? v1 + 1.f : expf(v1);
                    v2 = (v2 > 0.f) ? v2 + 1.f : expf(v2);
                    v3 = (v3 > 0.f) ? v3 + 1.f : expf(v3);
                }
                bf16 h0, h1, h2, h3, l0, l1, l2, l3;
                split1(v0, h0, l0); split1(v1, h1, l1);
                split1(v2, h2, l2); split1(v3, h3, l3);
                *(uint32_t*)(Ch + i0) = pack2(h0, h1);
                *(uint32_t*)(Cl + i0) = pack2(l0, l1);
                *(uint32_t*)(Ch + i1) = pack2(h2, h3);
                *(uint32_t*)(Cl + i1) = pack2(l2, l3);
            } else {
                if (epi == 2) {
                    v0 = addP[i0] + alpha * v0; v1 = addP[i0+1] + alpha * v1;
                    v2 = addP[i1] + alpha * v2; v3 = addP[i1+1] + alpha * v3;
                } else if (epi == 3) {
                    v0 += addP[i0]; v1 += addP[i0+1];
                    v2 += addP[i1]; v3 += addP[i1+1];
                }
                *(float2*)(Cf + i0) = make_float2(v0, v1);
                *(float2*)(Cf + i1) = make_float2(v2, v3);
            }
        }
    }
}

#define SM_G128 75776
#define SM_G64  59392
#define SM_LM   122880
#define ATT_SMEM 184320

// ---------------- GEMM wrappers (2 CTAs/SM for latency hiding) ---------------
__global__ void __launch_bounds__(256, 2) mma_proj(
    const bf16* __restrict__ Ah, const bf16* __restrict__ Al, int kIdx)
{
    extern __shared__ __align__(16) bf16 dsm[];
    int z = blockIdx.z;
    size_t wo = (size_t)kIdx * DD * DD;
    const bf16* Bh = (z == 0) ? g_WQh + wo : (z == 1) ? g_WKh + wo : g_WVh + wo;
    const bf16* Bl = (z == 0) ? g_WQl + wo : (z == 1) ? g_WKl + wo : g_WVl + wo;
    bf16* Ch = (z == 0) ? g_PQh : (z == 1) ? g_PKh : g_Vh;
    bf16* Cl = (z == 0) ? g_PQl : (z == 1) ? g_PKl : g_Vl;
    gemm_pipe<128>(dsm, Ah, Al, DD, Bh, Bl, DD,
                   nullptr, Ch, Cl, DD, blockIdx.y * 128, blockIdx.x * 128,
                   DD / 32, (z < 2) ? 1 : 4, nullptr, 0.f);
}

__global__ void __launch_bounds__(256, 2) mma_wo(
    const bf16* __restrict__ Ah, const bf16* __restrict__ Al, int kIdx,
    float* __restrict__ C, const float* __restrict__ addP,
    const float* __restrict__ dt)
{
    extern __shared__ __align__(16) bf16 dsm[];
    size_t wo = (size_t)kIdx * DD * DD;
    float d = dt[kIdx];
    float alpha = (d > 20.0f) ? d : log1pf(expf(d));
    gemm_pipe<64>(dsm, Ah, Al, DD, g_WOh + wo, g_WOl + wo, DD,
                  C, nullptr, nullptr, DD, blockIdx.y * 128, blockIdx.x * 64,
                  DD / 32, 2, addP, alpha);
}

__global__ void __launch_bounds__(256, 2) mma_up(
    const bf16* __restrict__ Ah, const bf16* __restrict__ Al, int kIdx,
    float* __restrict__ Hf)
{
    extern __shared__ __align__(16) bf16 dsm[];
    size_t wo = (size_t)kIdx * DD * 2 * INNER;
    gemm_pipe<128>(dsm, Ah, Al, DD, g_WUh + wo, g_WUl + wo, 2 * INNER,
                   Hf, nullptr, nullptr, 2 * INNER, blockIdx.y * 128, blockIdx.x * 128,
                   DD / 32, 5, nullptr, 0.f);
}

__global__ void __launch_bounds__(256, 2) mma_down(
    const bf16* __restrict__ Ah, const bf16* __restrict__ Al, int kIdx,
    float* __restrict__ C, const float* __restrict__ addP)
{
    extern __shared__ __align__(16) bf16 dsm[];
    size_t wo = (size_t)kIdx * INNER * DD;
    gemm_pipe<64>(dsm, Ah, Al, INNER, g_WDh + wo, g_WDl + wo, DD,
                  C, nullptr, nullptr, DD, blockIdx.y * 128, blockIdx.x * 64,
                  INNER / 32, 3, addP, 0.f);
}

// ---------------- fused flash attention (pipelined K/V) ----------------------
__device__ __forceinline__ void stage_kv(
    uint32_t base, int st, int kt, int tid, size_t rowbase,
    const bf16* __restrict__ PKh, const bf16* __restrict__ PKl,
    const bf16* __restrict__ Vh,  const bf16* __restrict__ Vl)
{
    const uint32_t QSZB = 128 * QS * 2;
    const uint32_t oKh = 2 * QSZB + st * QSZB;
    const uint32_t oKl = 4 * QSZB + st * QSZB;
    const uint32_t oVh = 6 * QSZB + st * QSZB;
    const uint32_t oVl = 8 * QSZB + st * QSZB;
    #pragma unroll
    for (int it2 = 0; it2 < 4; it2++) {
        int g = tid + 256 * it2;
        int row = g >> 3, c8 = (g & 7) * 8;
        size_t go = rowbase + (size_t)(kt * 128 + row) * DD + c8;
        uint32_t so = (uint32_t)(row * QS + c8) * 2;
        cpa16(base + oKh + so, PKh + go);
        cpa16(base + oKl + so, PKl + go);
        cpa16(base + oVh + so, Vh + go);
        cpa16(base + oVl + so, Vl + go);
    }
}

__global__ void __launch_bounds__(256) attn_fused(
    const bf16* __restrict__ PQh, const bf16* __restrict__ PQl,
    const bf16* __restrict__ PKh, const bf16* __restrict__ PKl,
    const bf16* __restrict__ Vh,  const bf16* __restrict__ Vl,
    bf16* __restrict__ Mh, bf16* __restrict__ Ml)
{
    extern __shared__ __align__(16) bf16 dsm[];
    const uint32_t base = smem_u32(dsm);
    const uint32_t QSZB = 128 * QS * 2;

    const int tid = threadIdx.x, lane = tid & 31, w = tid >> 5;
    const int bh = blockIdx.y, b = bh >> 3, h = bh & 7;
    const int q0 = blockIdx.x * 128;
    const size_t rowbase = (size_t)(b * NN) * DD + h * DH;

    #pragma unroll
    for (int it2 = 0; it2 < 4; it2++) {
        int g = tid + 256 * it2;
        int row = g >> 3, c8 = (g & 7) * 8;
        size_t go = rowbase + (size_t)(q0 + row) * DD + c8;
        uint32_t so = (uint32_t)(row * QS + c8) * 2;
        cpa16(base + so, PQh + go);
        cpa16(base + QSZB + so, PQl + go);
    }
    stage_kv(base, 0, 0, tid, rowbase, PKh, PKl, Vh, Vl);
    CP_COMMIT();
    CP_WAIT0();
    __syncthreads();

    uint32_t qh[4][4], ql[4][4];
    #pragma unroll
    for (int s = 0; s < 4; s++) {
        int r  = w * 16 + (lane & 15);
        int kb = s * 16 + ((lane >> 4) << 3);
        uint32_t so = (uint32_t)(r * QS + kb) * 2;
        ldm4(qh[s], base + so);
        ldm4(ql[s], base + QSZB + so);
    }

    float oacc[8][4];
    #pragma unroll
    for (int j = 0; j < 8; j++)
        #pragma unroll
        for (int q = 0; q < 4; q++) oacc[j][q] = 0.0f;
    float p0 = 0.0f, p1 = 0.0f;

    int st = 0;
    for (int kt = 0; kt < NN / 128; kt++) {
        if (kt + 1 < NN / 128) {
            stage_kv(base, st ^ 1, kt + 1, tid, rowbase, PKh, PKl, Vh, Vl);
            CP_COMMIT();
            CP_WAIT1();
        } else {
            CP_WAIT0();
        }
        __syncthreads();

        const uint32_t oKh = 2 * QSZB + st * QSZB;
        const uint32_t oKl = 4 * QSZB + st * QSZB;
        const uint32_t oVh = 6 * QSZB + st * QSZB;
        const uint32_t oVl = 8 * QSZB + st * QSZB;

        #pragma unroll
        for (int t = 0; t < 8; t++) {
            float sacc[2][4] = {};
            #pragma unroll
            for (int s = 0; s < 4; s++) {
                int r  = t * 16 + (lane & 7) + ((lane >> 4) << 3);
                int kb = s * 16 + (((lane >> 3) & 1) << 3);
                uint32_t so = (uint32_t)(r * QS + kb) * 2;
                uint32_t kh[4], kl[4];
                ldm4(kh, base + oKh + so);
                ldm4(kl, base + oKl + so);
                mma_bf16(sacc[0], qh[s], kh + 0);
                mma_bf16(sacc[0], ql[s], kh + 0);
                mma_bf16(sacc[0], qh[s], kl + 0);
                mma_bf16(sacc[1], qh[s], kh + 2);
                mma_bf16(sacc[1], ql[s], kh + 2);
                mma_bf16(sacc[1], qh[s], kl + 2);
            }
            float w2[2][4];
            #pragma unroll
            for (int f = 0; f < 2; f++)
                #pragma unroll
                for (int q = 0; q < 4; q++) {
                    float x = fmaxf(sacc[f][q], 0.0f);
                    w2[f][q] = x * x;
                }
            p0 += w2[0][0] + w2[0][1] + w2[1][0] + w2[1][1];
            p1 += w2[0][2] + w2[0][3] + w2[1][2] + w2[1][3];
            uint32_t wh[4], wl[4];
            {
                bf16 h0, h1, l0, l1;
                split1(w2[0][0], h0, l0); split1(w2[0][1], h1, l1);
                wh[0] = pack2(h0, h1); wl[0] = pack2(l0, l1);
                split1(w2[0][2], h0, l0); split1(w2[0][3], h1, l1);
                wh[1] = pack2(h0, h1); wl[1] = pack2(l0, l1);
                split1(w2[1][0], h0, l0); split1(w2[1][1], h1, l1);
                wh[2] = pack2(h0, h1); wl[2] = pack2(l0, l1);
                split1(w2[1][2], h0, l0); split1(w2[1][3], h1, l1);
                wh[3] = pack2(h0, h1); wl[3] = pack2(l0, l1);
            }
            #pragma unroll
            for (int n = 0; n < 4; n++) {
                int kk = t * 16 + (lane & 7) + ((lane >> 3) & 1) * 8;
                int nn = n * 16 + (lane >> 4) * 8;
                uint32_t so = (uint32_t)(kk * QS + nn) * 2;
                uint32_t vh[4], vl[4];
                ldm4t(vh, base + oVh + so);
                ldm4t(vl, base + oVl + so);
                mma_bf16(oacc[2*n],   wh, vh + 0);
                mma_bf16(oacc[2*n],   wl, vh + 0);
                mma_bf16(oacc[2*n],   wh, vl + 0);
                mma_bf16(oacc[2*n+1], wh, vh + 2);
                mma_bf16(oacc[2*n+1], wl, vh + 2);
                mma_bf16(oacc[2*n+1], wh, vl + 2);
            }
        }
        __syncthreads();
        st ^= 1;
    }

    p0 += __shfl_xor_sync(0xFFFFFFFFu, p0, 1);
    p0 += __shfl_xor_sync(0xFFFFFFFFu, p0, 2);
    p1 += __shfl_xor_sync(0xFFFFFFFFu, p1, 1);
    p1 += __shfl_xor_sync(0xFFFFFFFFu, p1, 2);
    float rd0 = 1.0f / (p0 + 1.0f);
    float rd1 = 1.0f / (p1 + 1.0f);

    int r0 = q0 + w * 16 + (lane >> 2);
    int r1 = r0 + 8;
    #pragma unroll
    for (int j = 0; j < 8; j++) {
        int d = j * 8 + (lane & 3) * 2;
        size_t i0 = rowbase + (size_t)r0 * DD + d;
        size_t i1 = rowbase + (size_t)r1 * DD + d;
        uint32_t vh0 = *(const uint32_t*)(Vh + i0), vl0 = *(const uint32_t*)(Vl + i0);
        uint32_t vh1 = *(const uint32_t*)(Vh + i1), vl1 = *(const uint32_t*)(Vl + i1);
        float vp00 = __bfloat162float(__ushort_as_bfloat16((unsigned short)(vh0 & 0xFFFF))) +
                     __bfloat162float(__ushort_as_bfloat16((unsigned short)(vl0 & 0xFFFF)));
        float vp01 = __bfloat162float(__ushort_as_bfloat16((unsigned short)(vh0 >> 16))) +
                     __bfloat162float(__ushort_as_bfloat16((unsigned short)(vl0 >> 16)));
        float vp10 = __bfloat162float(__ushort_as_bfloat16((unsigned short)(vh1 & 0xFFFF))) +
                     __bfloat162float(__ushort_as_bfloat16((unsigned short)(vl1 & 0xFFFF)));
        float vp11 = __bfloat162float(__ushort_as_bfloat16((unsigned short)(vh1 >> 16))) +
                     __bfloat162float(__ushort_as_bfloat16((unsigned short)(vl1 >> 16)));
        float m00 = oacc[j][0] * rd0 - vp00;
        float m01 = oacc[j][1] * rd0 - vp01;
        float m10 = oacc[j][2] * rd1 - vp10;
        float m11 = oacc[j][3] * rd1 - vp11;
        bf16 h0, h1, l0, l1;
        split1(m00, h0, l0); split1(m01, h1, l1);
        *(uint32_t*)(Mh + i0) = pack2(h0, h1);
        *(uint32_t*)(Ml + i0) = pack2(l0, l1);
        split1(m10, h0, l0); split1(m11, h1, l1);
        *(uint32_t*)(Mh + i1) = pack2(h0, h1);
        *(uint32_t*)(Ml + i1) = pack2(l0, l1);
    }
}

// ---------------- LM head: 256x128 tiles, 512 threads -------------------------
__device__ __forceinline__ void stage_lm(
    uint32_t base, int st, int kc, int tid, int m0, int n0,
    const bf16* __restrict__ Ah, const bf16* __restrict__ Al)
{
    constexpr uint32_t ASZ = 256 * AMS, BSZ = 128 * AMS;
    const uint32_t oAh = 0, oAl = 2 * ASZ * 2;
    const uint32_t oBh = 4 * ASZ * 2, oBl = (4 * ASZ + 2 * BSZ) * 2;
    #pragma unroll
    for (int it2 = 0; it2 < 2; it2++) {
        int g = tid + 512 * it2;
        int row = g >> 2, c8 = (g & 3) * 8;
        uint32_t so = (uint32_t)(st * ASZ + row * AMS + c8) * 2;
        size_t ga = (size_t)(m0 + row) * DD + kc * 32 + c8;
        cpa16(base + oAh + so, Ah + ga);
        cpa16(base + oAl + so, Al + ga);
    }
    {
        int g = tid;
        int row = g >> 2, c8 = (g & 3) * 8;
        uint32_t so = (uint32_t)(st * BSZ + row * AMS + c8) * 2;
        size_t gb = (size_t)(n0 + row) * DD + kc * 32 + c8;
        cpa16(base + oBh + so, g_LMh + gb);
        cpa16(base + oBl + so, g_LMl + gb);
    }
}

__global__ void __launch_bounds__(512)
lm_head_mma(const bf16* __restrict__ Ah, const bf16* __restrict__ Al,
            float* __restrict__ C)
{
    extern __shared__ __align__(16) bf16 dsm[];
    constexpr uint32_t ASZ = 256 * AMS, BSZ = 128 * AMS;
    const uint32_t base = smem_u32(dsm);
    const uint32_t oAh = 0, oAl = 2 * ASZ * 2;
    const uint32_t oBh = 4 * ASZ * 2, oBl = (4 * ASZ + 2 * BSZ) * 2;
    const int tid = threadIdx.x, lane = tid & 31, wid = tid >> 5;
    const int warp_m = wid >> 1, warp_n = wid & 1;
    const int m0 = blockIdx.y * 256, n0 = blockIdx.x * 128;

    float acc[2][8][4];
    #pragma unroll
    for (int i = 0; i < 2; i++)
        #pragma unroll
        for (int j = 0; j < 8; j++)
            #pragma unroll
            for (int q = 0; q < 4; q++) acc[i][j][q] = 0.0f;

    stage_lm(base, 0, 0, tid, m0, n0, Ah, Al);
    CP_COMMIT();

    int st = 0;
    for (int kc = 0; kc < 16; kc++) {
        if (kc + 1 < 16) {
            stage_lm(base, st ^ 1, kc + 1, tid, m0, n0, Ah, Al);
            CP_COMMIT();
            CP_WAIT1();
        } else {
            CP_WAIT0();
        }
        __syncthreads();

        #pragma unroll
        for (int s = 0; s < 2; s++) {
            uint32_t ah[2][4], al[2][4], bh[8][2], bl[8][2];
            #pragma unroll
            for (int i = 0; i < 2; i++) {
                int r  = warp_m * 32 + i * 16 + (lane & 15);
                int kb = s * 16 + ((lane >> 4) << 3);
                uint32_t so = (uint32_t)(st * ASZ + r * AMS + kb) * 2;
                ldm4(ah[i], base + oAh + so);
                ldm4(al[i], base + oAl + so);
            }
            #pragma unroll
            for (int j = 0; j < 4; j++) {
                int r  = warp_n * 64 + j * 16 + (lane & 7) + ((lane >> 4) << 3);
                int kb = s * 16 + (((lane >> 3) & 1) << 3);
                uint32_t so = (uint32_t)(st * BSZ + r * AMS + kb) * 2;
                uint32_t q[4];
                ldm4(q, base + oBh + so);
                bh[2*j][0] = q[0]; bh[2*j][1] = q[1];
                bh[2*j+1][0] = q[2]; bh[2*j+1][1] = q[3];
                ldm4(q, base + oBl + so);
                bl[2*j][0] = q[0]; bl[2*j][1] = q[1];
                bl[2*j+1][0] = q[2]; bl[2*j+1][1] = q[3];
            }
            #pragma unroll
            for (int i = 0; i < 2; i++)
                #pragma unroll
                for (int j = 0; j < 8; j++) {
                    mma_bf16(acc[i][j], ah[i], bh[j]);
                    mma_bf16(acc[i][j], al[i], bh[j]);
                    mma_bf16(acc[i][j], ah[i], bl[j]);
                }
        }
        __syncthreads();
        st ^= 1;
    }

    #pragma unroll
    for (int i = 0; i < 2; i++) {
        int m = m0 + warp_m * 32 + i * 16 + (lane >> 2);
        #pragma unroll
        for (int j = 0; j < 8; j++) {
            int n = n0 + warp_n * 64 + j * 8 + (lane & 3) * 2;
            *(float2*)(C + (size_t)m * VV + n) =
                make_float2(acc[i][j][0], acc[i][j][1]);
            *(float2*)(C + (size_t)(m + 8) * VV + n) =
                make_float2(acc[i][j][2], acc[i][j][3]);
        }
    }
}

// ---------------- init -------------------------------------------------------
__global__ void init_kernel(const int* __restrict__ inputs,
                            const int* __restrict__ carry_inputs,
                            const void* __restrict__ halted,
                            const float* __restrict__ carry_hidden,
                            const float* __restrict__ init_hidden,
                            const float* __restrict__ emb,
                            const float* __restrict__ pos,
                            const float* __restrict__ in_s,
                            const float* __restrict__ in_b)
{
    int r = blockIdx.x;
    int b = r / NN, n = r % NN;
    int t = threadIdx.x;
    bool h = read_halted(halted, b);
    int idx = h ? inputs[r] : carry_inputs[r];
    const float* e = emb + (size_t)idx * DD;
    const float* p = pos + (size_t)n * DD;

    float x0 = e[t]       + p[t];
    float x1 = e[t + 256] + p[t + 256];

    size_t base = (size_t)r * DD;
    g_Q[base + t]       = h ? init_hidden[t]       : carry_hidden[base + t];
    g_Q[base + t + 256] = h ? init_hidden[t + 256] : carry_hidden[base + t + 256];

    __shared__ float s_sum[256], s_sq[256];
    s_sum[t] = x0 + x1;
    s_sq[t]  = x0 * x0 + x1 * x1;
    __syncthreads();
    for (int o = 128; o > 0; o >>= 1) {
        if (t < o) { s_sum[t] += s_sum[t + o]; s_sq[t] += s_sq[t + o]; }
        __syncthreads();
    }
    float mu   = s_sum[0] * (1.0f / DD);
    float var  = s_sq[0] * (1.0f / DD) - mu * mu;
    float rstd = rsqrtf(var + 1e-5f);
    g_X[base + t]       = (x0 - mu) * rstd * in_s[t]       + in_b[t];
    g_X[base + t + 256] = (x1 - mu) * rstd * in_s[t + 256] + in_b[t + 256];
}

// ---------------- LayerNorm --------------------------------------------------
__global__ void ln_kernel(const float* __restrict__ in, float* __restrict__ outf,
                          bf16* __restrict__ outh, bf16* __restrict__ outl,
                          const float* __restrict__ s, const float* __restrict__ bia,
                          const float* __restrict__ add)
{
    int r = blockIdx.x;
    int t = threadIdx.x;
    size_t base = (size_t)r * DD;
    float x0 = in[base + t];
    float x1 = in[base + t + 256];

    __shared__ float s_sum[256], s_sq[256];
    s_sum[t] = x0 + x1;
    s_sq[t]  = x0 * x0 + x1 * x1;
    __syncthreads();
    for (int o = 128; o > 0; o >>= 1) {
        if (t < o) { s_sum[t] += s_sum[t + o]; s_sq[t] += s_sq[t + o]; }
        __syncthreads();
    }
    float mu   = s_sum[0] * (1.0f / DD);
    float var  = s_sq[0] * (1.0f / DD) - mu * mu;
    float rstd = rsqrtf(var + 1e-5f);
    float v0 = (x0 - mu) * rstd * s[t]       + bia[t];
    float v1 = (x1 - mu) * rstd * s[t + 256] + bia[t + 256];
    if (add) { v0 += add[base + t]; v1 += add[base + t + 256]; }
    if (outf) { outf[base + t] = v0; outf[base + t + 256] = v1; }
    if (outh) {
        bf16 h0, l0, h1, l1;
        split1(v0, h0, l0); split1(v1, h1, l1);
        outh[base + t] = h0;       outl[base + t] = l0;
        outh[base + t + 256] = h1; outl[base + t + 256] = l1;
    }
}

// ---------------- depthwise conv k=3 + bias + silu -> hi/lo ------------------
__global__ void conv_kernel(const float* __restrict__ Hf, const float* __restrict__ w,
                            const float* __restrict__ bias,
                            bf16* __restrict__ outh, bf16* __restrict__ outl)
{
    size_t i = (size_t)blockIdx.x * 256 + threadIdx.x;
    if (i >= (size_t)MROWS * INNER) return;
    size_t row = i / INNER;
    int c = (int)(i % INNER);
    int n = (int)(row % NN);
    const float* wc = w + (size_t)c * CKW;
    float acc = bias[c];
    if (n > 0)      acc += wc[0] * Hf[(row - 1) * INNER + c];
    acc += wc[1] * Hf[row * INNER + c];
    if (n < NN - 1) acc += wc[2] * Hf[(row + 1) * INNER + c];
    float v = siluf(acc);
    bf16 h, l;
    split1(v, h, l);
    outh[i] = h;
    outl[i] = l;
}

// ---------------- halt head --------------------------------------------------
__global__ void halt_kernel(const float* __restrict__ Qn, const float* __restrict__ hw,
                            const float* __restrict__ hb, float* __restrict__ out)
{
    int b = blockIdx.x;
    int t = threadIdx.x;
    __shared__ float md[DD];
    for (int d = t; d < DD; d += 256) {
        float s = 0.0f;
        for (int n = 0; n < NN; n++)
            s += Qn[((size_t)(b * NN + n)) * DD + d];
        md[d] = s * (1.0f / NN);
    }
    __syncthreads();
    __shared__ float r0[256], r1[256];
    float p0 = 0.0f, p1 = 0.0f;
    for (int d = t; d < DD; d += 256) {
        p0 += md[d] * hw[d];
        p1 += md[d] * hw[DD + d];
    }
    r0[t] = p0; r1[t] = p1;
    __syncthreads();
    for (int o = 128; o > 0; o >>= 1) {
        if (t < o) { r0[t] += r0[t + o]; r1[t] += r1[t + o]; }
        __syncthreads();
    }
    if (t == 0) {
        out[b * 2 + 0] = r0[0] + hb[0];
        out[b * 2 + 1] = r1[0] + hb[1];
    }
}

// ---------------- host orchestration -----------------------------------------
static void cvt(const float* src, bf16* h, bf16* l, size_t n)
{
    int n4 = (int)(n / 4);
    cvt_kernel<<<(n4 + 255) / 256, 256>>>(src, h, l, n4);
}

extern "C" void kernel_launch(void* const* d_in, const int* in_sizes, int n_in,
                              void* d_out, int out_size)
{
    const int*   inputs       = (const int*)d_in[0];
    const float* carry_hidden = (const float*)d_in[2];
    const void*  halted       = d_in[4];
    const int*   carry_inputs = (const int*)d_in[5];
    const float* init_hidden  = (const float*)d_in[7];
    const float* emb          = (const float*)d_in[8];
    const float* pos          = (const float*)d_in[9];
    const float* in_s         = (const float*)d_in[10];
    const float* in_b         = (const float*)d_in[11];
    const float* fin_s        = (const float*)d_in[12];
    const float* fin_b        = (const float*)d_in[13];
    const float* lm_w         = (const float*)d_in[14];
    const float* halt_w       = (const float*)d_in[15];
    const float* halt_b       = (const float*)d_in[16];
    const float* dt           = (const float*)d_in[17];
    const float* W_Q          = (const float*)d_in[18];
    const float* W_K          = (const float*)d_in[19];
    const float* W_V          = (const float*)d_in[20];
    const float* W_O          = (const float*)d_in[21];
    const float* W_up         = (const float*)d_in[22];
    const float* dw_w         = (const float*)d_in[23];
    const float* dw_b         = (const float*)d_in[24];
    const float* W_down       = (const float*)d_in[25];
    const float* n1_s         = (const float*)d_in[26];
    const float* n1_b         = (const float*)d_in[27];
    const float* n2_s         = (const float*)d_in[28];
    const float* n2_b         = (const float*)d_in[29];

    float *X, *Q, *Qi, *Qn, *Hf;
    bf16 *Hch, *Hcl, *PQh, *PQl, *PKh, *PKl, *Vh, *Vl, *mbh, *mbl;
    bf16 *Q2h, *Q2l, *Hvh, *Hvl, *Qnh, *Qnl;
    bf16 *WQh, *WQl, *WKh, *WKl, *WVh, *WVl, *WOh, *WOl;
    bf16 *WUh, *WUl, *WDh, *WDl, *LMh, *LMl;
    cudaGetSymbolAddress((void**)&X,   g_X);
    cudaGetSymbolAddress((void**)&Q,   g_Q);
    cudaGetSymbolAddress((void**)&Qi,  g_Qi);
    cudaGetSymbolAddress((void**)&Qn,  g_Qn);
    cudaGetSymbolAddress((void**)&Hf,  g_Hf);
    cudaGetSymbolAddress((void**)&Hch, g_Hch); cudaGetSymbolAddress((void**)&Hcl, g_Hcl);
    cudaGetSymbolAddress((void**)&PQh, g_PQh); cudaGetSymbolAddress((void**)&PQl, g_PQl);
    cudaGetSymbolAddress((void**)&PKh, g_PKh); cudaGetSymbolAddress((void**)&PKl, g_PKl);
    cudaGetSymbolAddress((void**)&Vh,  g_Vh);  cudaGetSymbolAddress((void**)&Vl,  g_Vl);
    cudaGetSymbolAddress((void**)&mbh, g_mbh); cudaGetSymbolAddress((void**)&mbl, g_mbl);
    cudaGetSymbolAddress((void**)&Q2h, g_Q2h); cudaGetSymbolAddress((void**)&Q2l, g_Q2l);
    cudaGetSymbolAddress((void**)&Hvh, g_Hvh); cudaGetSymbolAddress((void**)&Hvl, g_Hvl);
    cudaGetSymbolAddress((void**)&Qnh, g_Qnh); cudaGetSymbolAddress((void**)&Qnl, g_Qnl);
    cudaGetSymbolAddress((void**)&WQh, g_WQh); cudaGetSymbolAddress((void**)&WQl, g_WQl);
    cudaGetSymbolAddress((void**)&WKh, g_WKh); cudaGetSymbolAddress((void**)&WKl, g_WKl);
    cudaGetSymbolAddress((void**)&WVh, g_WVh); cudaGetSymbolAddress((void**)&WVl, g_WVl);
    cudaGetSymbolAddress((void**)&WOh, g_WOh); cudaGetSymbolAddress((void**)&WOl, g_WOl);
    cudaGetSymbolAddress((void**)&WUh, g_WUh); cudaGetSymbolAddress((void**)&WUl, g_WUl);
    cudaGetSymbolAddress((void**)&WDh, g_WDh); cudaGetSymbolAddress((void**)&WDl, g_WDl);
    cudaGetSymbolAddress((void**)&LMh, g_LMh); cudaGetSymbolAddress((void**)&LMl, g_LMl);

    float* out = (float*)d_out;

    cudaFuncSetAttribute(attn_fused, cudaFuncAttributeMaxDynamicSharedMemorySize, ATT_SMEM);
    cudaFuncSetAttribute(mma_proj,   cudaFuncAttributeMaxDynamicSharedMemorySize, SM_G128);
    cudaFuncSetAttribute(mma_up,     cudaFuncAttributeMaxDynamicSharedMemorySize, SM_G128);
    cudaFuncSetAttribute(mma_wo,     cudaFuncAttributeMaxDynamicSharedMemorySize, SM_G64);
    cudaFuncSetAttribute(mma_down,   cudaFuncAttributeMaxDynamicSharedMemorySize, SM_G64);
    cudaFuncSetAttribute(lm_head_mma, cudaFuncAttributeMaxDynamicSharedMemorySize, SM_LM);

    // weight pre-split (W_up permuted for fused swiglu)
    cvt(W_Q,    WQh, WQl, (size_t)KKB * DD * DD);
    cvt(W_K,    WKh, WKl, (size_t)KKB * DD * DD);
    cvt(W_V,    WVh, WVl, (size_t)KKB * DD * DD);
    cvt(W_O,    WOh, WOl, (size_t)KKB * DD * DD);
    {
        int total = KKB * DD * (2 * INNER) / 8;
        cvt_up_kernel<<<(total + 255) / 256, 256>>>(W_up, WUh, WUl);
    }
    cvt(W_down, WDh, WDl, (size_t)KKB * INNER * DD);
    cvt(lm_w,   LMh, LMl, (size_t)VV * DD);

    init_kernel<<<MROWS, 256>>>(inputs, carry_inputs, halted, carry_hidden,
                                init_hidden, emb, pos, in_s, in_b);

    dim3 gP(DD / 128, MROWS / 128, 3);        // (4, 16, 3)
    dim3 gO64(DD / 64, MROWS / 128);          // (8, 16) = 128 CTAs
    dim3 gUP(2 * INNER / 128, MROWS / 128);   // (24, 16)
    dim3 gAT(NN / 128, BHN);                  // (8, 16)

    for (int it = 0; it < TOTAL_PASSES; it++) {
        int k = it % KKB;

        ln_kernel<<<MROWS, 256>>>(Q, nullptr, Hch, Hcl,
                                  n1_s + k * DD, n1_b + k * DD, X);

        mma_proj<<<gP, 256, SM_G128>>>(Hch, Hcl, k);

        attn_fused<<<gAT, 256, ATT_SMEM>>>(PQh, PQl, PKh, PKl, Vh, Vl, mbh, mbl);

        mma_wo<<<gO64, 256, SM_G64>>>(mbh, mbl, k, Qi, Q, dt);

        ln_kernel<<<MROWS, 256>>>(Qi, nullptr, Q2h, Q2l,
                                  n2_s + k * DD, n2_b + k * DD, nullptr);
        mma_up<<<gUP, 256, SM_G128>>>(Q2h, Q2l, k, Hf);    // fused swiglu
        int tot = MROWS * INNER;
        conv_kernel<<<(tot + 255) / 256, 256>>>(Hf, dw_w + (size_t)k * INNER * CKW,
                                                dw_b + (size_t)k * INNER, Hvh, Hvl);
        mma_down<<<gO64, 256, SM_G64>>>(Hvh, Hvl, k, Q, Qi);
    }

    ln_kernel<<<MROWS, 256>>>(Q, Qn, Qnh, Qnl, fin_s, fin_b, nullptr);
    dim3 gLM(VV / 128, MROWS / 256);          // (250, 8)
    lm_head_mma<<<gLM, 512, SM_LM>>>(Qnh, Qnl, out);
    halt_kernel<<<BB, 256>>>(Qn, halt_w, halt_b, out + (size_t)MROWS * VV);
}

// round 11
// speedup vs baseline: 3.3896x; 1.2298x over previous
#include <cuda_runtime.h>
#include <cuda_bf16.h>
#include <cuda_fp16.h>
#include <math.h>
#include <stdint.h>

// Problem constants
#define BB    2
#define NN    1024
#define DD    512
#define HH    8
#define DH    64
#define KKB   4
#define VV    32000
#define INNER 1536
#define CKW   3
#define MROWS (BB*NN)     // 2048
#define BHN   (BB*HH)     // 16
#define TOTAL_PASSES 8

#define AMS  40    // A smem stride (16-bit elems): 32 data + 8 pad
#define QS   72    // attention smem stride (64 + 8)

typedef __nv_bfloat16 bf16;
typedef __half h16;

// ---------------- fp32 scratch ----------------------------------------------
__device__ __align__(16) float g_X  [MROWS*DD];
__device__ __align__(16) float g_Q  [MROWS*DD];
__device__ __align__(16) float g_Qi [MROWS*DD];
__device__ __align__(16) float g_Qn [MROWS*DD];
__device__ __align__(16) float g_Hf [(size_t)MROWS*INNER];

// ---------------- activation scratch -----------------------------------------
// fp16 hi/lo (trunk GEMM inputs)
__device__ __align__(16) h16 g_Hch [MROWS*DD], g_Hcl [MROWS*DD];
__device__ __align__(16) h16 g_mbh [MROWS*DD], g_mbl [MROWS*DD];
__device__ __align__(16) h16 g_Q2h [MROWS*DD], g_Q2l [MROWS*DD];
__device__ __align__(16) h16 g_Hvh [(size_t)MROWS*INNER], g_Hvl [(size_t)MROWS*INNER];
__device__ __align__(16) h16 g_Qnh [MROWS*DD], g_Qnl [MROWS*DD];
// bf16 hi/lo (attention inputs; bf16 range needed for W=relu(dot)^2)
__device__ __align__(16) bf16 g_PQh [MROWS*DD], g_PQl [MROWS*DD];
__device__ __align__(16) bf16 g_PKh [MROWS*DD], g_PKl [MROWS*DD];
__device__ __align__(16) bf16 g_Vh  [MROWS*DD], g_Vl  [MROWS*DD];

// ---------------- single-fp16 weight scratch ---------------------------------
__device__ __align__(16) h16 g_WQh [KKB*DD*DD];
__device__ __align__(16) h16 g_WKh [KKB*DD*DD];
__device__ __align__(16) h16 g_WVh [KKB*DD*DD];
__device__ __align__(16) h16 g_WOh [KKB*DD*DD];
__device__ __align__(16) h16 g_WUh [(size_t)KKB*DD*2*INNER];
__device__ __align__(16) h16 g_WDh [(size_t)KKB*INNER*DD];
__device__ __align__(16) h16 g_LMh [(size_t)VV*DD];

// ---------------- helpers ----------------------------------------------------
__device__ __forceinline__ float siluf(float x) { return x / (1.0f + expf(-x)); }

__device__ __forceinline__ bool read_halted(const void* p, int b)
{
    const unsigned char* u8 = (const unsigned char*)p;
    if (u8[1] != 0) return u8[b] != 0;
    return ((const int*)p)[b] != 0;
}
__device__ __forceinline__ uint32_t smem_u32(const void* p) {
    uint32_t a;
    asm("{ .reg .u64 t; cvta.to.shared.u64 t, %1; cvt.u32.u64 %0, t; }"
        : "=r"(a) : "l"(p));
    return a;
}
__device__ __forceinline__ void ldm4(uint32_t* r, uint32_t a) {
    asm volatile("ldmatrix.sync.aligned.m8n8.x4.shared.b16 {%0,%1,%2,%3}, [%4];"
                 : "=r"(r[0]), "=r"(r[1]), "=r"(r[2]), "=r"(r[3]) : "r"(a));
}
__device__ __forceinline__ void ldm4t(uint32_t* r, uint32_t a) {
    asm volatile("ldmatrix.sync.aligned.m8n8.x4.trans.shared.b16 {%0,%1,%2,%3}, [%4];"
                 : "=r"(r[0]), "=r"(r[1]), "=r"(r[2]), "=r"(r[3]) : "r"(a));
}
__device__ __forceinline__ void mma_bf16(float* c, const uint32_t* a, const uint32_t* b) {
    asm volatile("mma.sync.aligned.m16n8k16.row.col.f32.bf16.bf16.f32 "
                 "{%0,%1,%2,%3}, {%4,%5,%6,%7}, {%8,%9}, {%0,%1,%2,%3};"
                 : "+f"(c[0]), "+f"(c[1]), "+f"(c[2]), "+f"(c[3])
                 : "r"(a[0]), "r"(a[1]), "r"(a[2]), "r"(a[3]),
                   "r"(b[0]), "r"(b[1]));
}
__device__ __forceinline__ void mma_f16(float* c, const uint32_t* a, const uint32_t* b) {
    asm volatile("mma.sync.aligned.m16n8k16.row.col.f32.f16.f16.f32 "
                 "{%0,%1,%2,%3}, {%4,%5,%6,%7}, {%8,%9}, {%0,%1,%2,%3};"
                 : "+f"(c[0]), "+f"(c[1]), "+f"(c[2]), "+f"(c[3])
                 : "r"(a[0]), "r"(a[1]), "r"(a[2]), "r"(a[3]),
                   "r"(b[0]), "r"(b[1]));
}
__device__ __forceinline__ uint32_t pack2(bf16 a, bf16 b) {
    return (uint32_t)__bfloat16_as_ushort(a) |
           ((uint32_t)__bfloat16_as_ushort(b) << 16);
}
__device__ __forceinline__ uint32_t pack2h(h16 a, h16 b) {
    return (uint32_t)__half_as_ushort(a) |
           ((uint32_t)__half_as_ushort(b) << 16);
}
__device__ __forceinline__ void split1(float v, bf16& h, bf16& l) {
    h = __float2bfloat16(v);
    l = __float2bfloat16(v - __bfloat162float(h));
}
__device__ __forceinline__ void split1h(float v, h16& h, h16& l) {
    h = __float2half_rn(v);
    l = __float2half_rn(v - __half2float(h));
}
__device__ __forceinline__ void cpa16(uint32_t s, const void* g) {
    asm volatile("cp.async.cg.shared.global [%0], [%1], 16;" :: "r"(s), "l"(g));
}
#define CP_COMMIT() asm volatile("cp.async.commit_group;" ::: "memory")
#define CP_WAIT0()  asm volatile("cp.async.wait_group 0;" ::: "memory")
#define CP_WAIT1()  asm volatile("cp.async.wait_group 1;" ::: "memory")

// ---------------- converters --------------------------------------------------
// fp32 -> single fp16
__global__ void cvt_h_kernel(const float* __restrict__ src, h16* __restrict__ d, int n4)
{
    int i = blockIdx.x * 256 + threadIdx.x;
    if (i >= n4) return;
    float4 v = *(const float4*)(src + (size_t)i * 4);
    uint2 o;
    o.x = pack2h(__float2half_rn(v.x), __float2half_rn(v.y));
    o.y = pack2h(__float2half_rn(v.z), __float2half_rn(v.w));
    *(uint2*)(d + (size_t)i * 4) = o;
}

// W_up converter with G/U column interleave (single fp16)
__global__ void cvt_up_kernel(const float* __restrict__ src, h16* __restrict__ d)
{
    int gi = blockIdx.x * 256 + threadIdx.x;
    int total = KKB * DD * (2 * INNER) / 8;
    if (gi >= total) return;
    int cg8 = gi % (2 * INNER / 8);
    int row = gi / (2 * INNER / 8);
    int cg = cg8 * 4;
    size_t rb = (size_t)row * (2 * INNER);
    float4 gsrc = *(const float4*)(src + rb + cg);
    float4 usrc = *(const float4*)(src + rb + INNER + cg);
    float gv[4] = {gsrc.x, gsrc.y, gsrc.z, gsrc.w};
    float uv[4] = {usrc.x, usrc.y, usrc.z, usrc.w};
    uint32_t w[4];
    #pragma unroll
    for (int q = 0; q < 4; q++)
        w[q] = pack2h(__float2half_rn(gv[q]), __float2half_rn(uv[q]));
    size_t db = rb + (size_t)cg8 * 8;
    *(uint4*)(d + db) = make_uint4(w[0], w[1], w[2], w[3]);
}

// ---------------- pipelined fp16x2 GEMM body ---------------------------------
// A: fp16 hi/lo [M,K]; B: single fp16 [K,N] (trans ldmatrix).
// smem layout: [Ah s0 | Ah s1 | Al s0 | Al s1 | B s0 | B s1]
template <int BN>
__device__ __forceinline__ void stage_gemm(
    uint32_t base, int st, int kc, int tid, int m0, int n0,
    const h16* __restrict__ Ah, const h16* __restrict__ Al, int lda,
    const h16* __restrict__ B, int ldb)
{
    constexpr int BNS_ = (BN == 128) ? 136 : 72;
    constexpr uint32_t ASZ = 128 * AMS, BSZ = 32 * BNS_;
    const uint32_t oAh = 0, oAl = 2 * ASZ * 2, oB = 4 * ASZ * 2;
    #pragma unroll
    for (int it2 = 0; it2 < 2; it2++) {
        int g = tid + 256 * it2;
        int row = g >> 2, c8 = (g & 3) * 8;
        size_t go = (size_t)(m0 + row) * lda + kc * 32 + c8;
        uint32_t so = (uint32_t)(st * ASZ + row * AMS + c8) * 2;
        cpa16(base + oAh + so, Ah + go);
        cpa16(base + oAl + so, Al + go);
    }
    {
        // B: 32 x BN halfs = 4*BN groups of 8
        if (BN == 128) {
            #pragma unroll
            for (int it2 = 0; it2 < 2; it2++) {
                int g = tid + 256 * it2;
                int row = g >> 4, c8 = (g & 15) * 8;
                size_t go = (size_t)(kc * 32 + row) * ldb + n0 + c8;
                uint32_t so = (uint32_t)(st * BSZ + row * BNS_ + c8) * 2;
                cpa16(base + oB + so, B + go);
            }
        } else {
            int g = tid;
            int row = g >> 3, c8 = (g & 7) * 8;
            size_t go = (size_t)(kc * 32 + row) * ldb + n0 + c8;
            uint32_t so = (uint32_t)(st * BSZ + row * BNS_ + c8) * 2;
            cpa16(base + oB + so, B + go);
        }
    }
}

// epi: 0 fp32, 1 bf16 hi/lo elu+1, 2 fp32 addP+alpha*acc, 3 fp32 addP+acc,
//      4 bf16 hi/lo plain, 5 fused swiglu -> fp32 Hf
template <int BN>
__device__ __forceinline__ void gemm_pipe(
    h16* smem,
    const h16* __restrict__ Ah, const h16* __restrict__ Al, int lda,
    const h16* __restrict__ B, int ldb,
    float* __restrict__ Cf, bf16* __restrict__ Ch, bf16* __restrict__ Cl, int ldc,
    int m0, int n0, int kch, int epi, const float* __restrict__ addP, float alpha)
{
    constexpr int BNS_ = (BN == 128) ? 136 : 72;
    constexpr int NJ = BN / 16;
    constexpr uint32_t ASZ = 128 * AMS, BSZ = 32 * BNS_;
    const uint32_t base = smem_u32(smem);
    const uint32_t oAh = 0, oAl = 2 * ASZ * 2, oB = 4 * ASZ * 2;
    const int tid = threadIdx.x, lane = tid & 31, wid = tid >> 5;
    const int warp_m = wid >> 1, warp_n = wid & 1;

    float acc[2][NJ][4];
    #pragma unroll
    for (int i = 0; i < 2; i++)
        #pragma unroll
        for (int j = 0; j < NJ; j++)
            #pragma unroll
            for (int q = 0; q < 4; q++) acc[i][j][q] = 0.0f;

    stage_gemm<BN>(base, 0, 0, tid, m0, n0, Ah, Al, lda, B, ldb);
    CP_COMMIT();

    int st = 0;
    for (int kc = 0; kc < kch; kc++) {
        if (kc + 1 < kch) {
            stage_gemm<BN>(base, st ^ 1, kc + 1, tid, m0, n0, Ah, Al, lda, B, ldb);
            CP_COMMIT();
            CP_WAIT1();
        } else {
            CP_WAIT0();
        }
        __syncthreads();

        #pragma unroll
        for (int s = 0; s < 2; s++) {
            uint32_t ah[2][4], al[2][4], bh[NJ][2];
            #pragma unroll
            for (int i = 0; i < 2; i++) {
                int r  = warp_m * 32 + i * 16 + (lane & 15);
                int kb = s * 16 + ((lane >> 4) << 3);
                uint32_t so = (uint32_t)(st * ASZ + r * AMS + kb) * 2;
                ldm4(ah[i], base + oAh + so);
                ldm4(al[i], base + oAl + so);
            }
            #pragma unroll
            for (int j2 = 0; j2 < NJ / 2; j2++) {
                int kk = s * 16 + (lane & 7) + ((lane >> 3) & 1) * 8;
                int nn = warp_n * (BN / 2) + j2 * 16 + (lane >> 4) * 8;
                uint32_t so = (uint32_t)(st * BSZ + kk * BNS_ + nn) * 2;
                uint32_t q[4];
                ldm4t(q, base + oB + so);
                bh[2*j2][0] = q[0]; bh[2*j2][1] = q[1];
                bh[2*j2+1][0] = q[2]; bh[2*j2+1][1] = q[3];
            }
            #pragma unroll
            for (int i = 0; i < 2; i++)
                #pragma unroll
                for (int j = 0; j < NJ; j++) {
                    mma_f16(acc[i][j], ah[i], bh[j]);
                    mma_f16(acc[i][j], al[i], bh[j]);
                }
        }
        __syncthreads();
        st ^= 1;
    }

    #pragma unroll
    for (int i = 0; i < 2; i++) {
        int m = m0 + warp_m * 32 + i * 16 + (lane >> 2);
        #pragma unroll
        for (int j = 0; j < NJ; j++) {
            int n = n0 + warp_n * (BN / 2) + j * 8 + (lane & 3) * 2;
            float v0 = acc[i][j][0], v1 = acc[i][j][1];
            float v2 = acc[i][j][2], v3 = acc[i][j][3];
            if (epi == 5) {
                int col = n >> 1;
                Cf[(size_t)m * INNER + col]       = siluf(v0) * v1;
                Cf[(size_t)(m + 8) * INNER + col] = siluf(v2) * v3;
                continue;
            }
            size_t i0 = (size_t)m * ldc + n;
            size_t i1 = (size_t)(m + 8) * ldc + n;
            if (epi == 1 || epi == 4) {
                if (epi == 1) {
                    v0 = (v0 > 0.f) ? v0 + 1.f : expf(v0);
                    v1 = (v1 > 0.f) ? v1 + 1.f : expf(v1);
                    v2 = (v2 > 0.f) ? v2 + 1.f : expf(v2);
                    v3 = (v3 > 0.f) ? v3 + 1.f : expf(v3);
                }
                bf16 h0, h1, h2, h3, l0, l1, l2, l3;
                split1(v0, h0, l0); split1(v1, h1, l1);
                split1(v2, h2, l2); split1(v3, h3, l3);
                *(uint32_t*)(Ch + i0) = pack2(h0, h1);
                *(uint32_t*)(Cl + i0) = pack2(l0, l1);
                *(uint32_t*)(Ch + i1) = pack2(h2, h3);
                *(uint32_t*)(Cl + i1) = pack2(l2, l3);
            } else {
                if (epi == 2) {
                    v0 = addP[i0] + alpha * v0; v1 = addP[i0+1] + alpha * v1;
                    v2 = addP[i1] + alpha * v2; v3 = addP[i1+1] + alpha * v3;
                } else if (epi == 3) {
                    v0 += addP[i0]; v1 += addP[i0+1];
                    v2 += addP[i1]; v3 += addP[i1+1];
                }
                *(float2*)(Cf + i0) = make_float2(v0, v1);
                *(float2*)(Cf + i1) = make_float2(v2, v3);
            }
        }
    }
}

#define SM_G128 58368
#define SM_G64  50176
#define SM_LM   102400
#define ATT_SMEM 184320

// ---------------- GEMM wrappers (2 CTAs/SM) -----------------------------------
__global__ void __launch_bounds__(256, 2) mma_proj(
    const h16* __restrict__ Ah, const h16* __restrict__ Al, int kIdx)
{
    extern __shared__ __align__(16) h16 dsm[];
    int z = blockIdx.z;
    size_t wo = (size_t)kIdx * DD * DD;
    const h16* B = (z == 0) ? g_WQh + wo : (z == 1) ? g_WKh + wo : g_WVh + wo;
    bf16* Ch = (z == 0) ? g_PQh : (z == 1) ? g_PKh : g_Vh;
    bf16* Cl = (z == 0) ? g_PQl : (z == 1) ? g_PKl : g_Vl;
    gemm_pipe<128>(dsm, Ah, Al, DD, B, DD,
                   nullptr, Ch, Cl, DD, blockIdx.y * 128, blockIdx.x * 128,
                   DD / 32, (z < 2) ? 1 : 4, nullptr, 0.f);
}

__global__ void __launch_bounds__(256, 2) mma_wo(
    const h16* __restrict__ Ah, const h16* __restrict__ Al, int kIdx,
    float* __restrict__ C, const float* __restrict__ addP,
    const float* __restrict__ dt)
{
    extern __shared__ __align__(16) h16 dsm[];
    size_t wo = (size_t)kIdx * DD * DD;
    float d = dt[kIdx];
    float alpha = (d > 20.0f) ? d : log1pf(expf(d));
    gemm_pipe<64>(dsm, Ah, Al, DD, g_WOh + wo, DD,
                  C, nullptr, nullptr, DD, blockIdx.y * 128, blockIdx.x * 64,
                  DD / 32, 2, addP, alpha);
}

__global__ void __launch_bounds__(256, 2) mma_up(
    const h16* __restrict__ Ah, const h16* __restrict__ Al, int kIdx,
    float* __restrict__ Hf)
{
    extern __shared__ __align__(16) h16 dsm[];
    size_t wo = (size_t)kIdx * DD * 2 * INNER;
    gemm_pipe<128>(dsm, Ah, Al, DD, g_WUh + wo, 2 * INNER,
                   Hf, nullptr, nullptr, 2 * INNER, blockIdx.y * 128, blockIdx.x * 128,
                   DD / 32, 5, nullptr, 0.f);
}

__global__ void __launch_bounds__(256, 2) mma_down(
    const h16* __restrict__ Ah, const h16* __restrict__ Al, int kIdx,
    float* __restrict__ C, const float* __restrict__ addP)
{
    extern __shared__ __align__(16) h16 dsm[];
    size_t wo = (size_t)kIdx * INNER * DD;
    gemm_pipe<64>(dsm, Ah, Al, INNER, g_WDh + wo, DD,
                  C, nullptr, nullptr, DD, blockIdx.y * 128, blockIdx.x * 64,
                  INNER / 32, 3, addP, 0.f);
}

// ---------------- fused flash attention (bf16x3, pipelined K/V) ---------------
__device__ __forceinline__ void stage_kv(
    uint32_t base, int st, int kt, int tid, size_t rowbase,
    const bf16* __restrict__ PKh, const bf16* __restrict__ PKl,
    const bf16* __restrict__ Vh,  const bf16* __restrict__ Vl)
{
    const uint32_t QSZB = 128 * QS * 2;
    const uint32_t oKh = 2 * QSZB + st * QSZB;
    const uint32_t oKl = 4 * QSZB + st * QSZB;
    const uint32_t oVh = 6 * QSZB + st * QSZB;
    const uint32_t oVl = 8 * QSZB + st * QSZB;
    #pragma unroll
    for (int it2 = 0; it2 < 4; it2++) {
        int g = tid + 256 * it2;
        int row = g >> 3, c8 = (g & 7) * 8;
        size_t go = rowbase + (size_t)(kt * 128 + row) * DD + c8;
        uint32_t so = (uint32_t)(row * QS + c8) * 2;
        cpa16(base + oKh + so, PKh + go);
        cpa16(base + oKl + so, PKl + go);
        cpa16(base + oVh + so, Vh + go);
        cpa16(base + oVl + so, Vl + go);
    }
}

__global__ void __launch_bounds__(256) attn_fused(
    const bf16* __restrict__ PQh, const bf16* __restrict__ PQl,
    const bf16* __restrict__ PKh, const bf16* __restrict__ PKl,
    const bf16* __restrict__ Vh,  const bf16* __restrict__ Vl,
    h16* __restrict__ Mh, h16* __restrict__ Ml)
{
    extern __shared__ __align__(16) bf16 dsmb[];
    const uint32_t base = smem_u32(dsmb);
    const uint32_t QSZB = 128 * QS * 2;

    const int tid = threadIdx.x, lane = tid & 31, w = tid >> 5;
    const int bh = blockIdx.y, b = bh >> 3, h = bh & 7;
    const int q0 = blockIdx.x * 128;
    const size_t rowbase = (size_t)(b * NN) * DD + h * DH;

    #pragma unroll
    for (int it2 = 0; it2 < 4; it2++) {
        int g = tid + 256 * it2;
        int row = g >> 3, c8 = (g & 7) * 8;
        size_t go = rowbase + (size_t)(q0 + row) * DD + c8;
        uint32_t so = (uint32_t)(row * QS + c8) * 2;
        cpa16(base + so, PQh + go);
        cpa16(base + QSZB + so, PQl + go);
    }
    stage_kv(base, 0, 0, tid, rowbase, PKh, PKl, Vh, Vl);
    CP_COMMIT();
    CP_WAIT0();
    __syncthreads();

    uint32_t qh[4][4], ql[4][4];
    #pragma unroll
    for (int s = 0; s < 4; s++) {
        int r  = w * 16 + (lane & 15);
        int kb = s * 16 + ((lane >> 4) << 3);
        uint32_t so = (uint32_t)(r * QS + kb) * 2;
        ldm4(qh[s], base + so);
        ldm4(ql[s], base + QSZB + so);
    }

    float oacc[8][4];
    #pragma unroll
    for (int j = 0; j < 8; j++)
        #pragma unroll
        for (int q = 0; q < 4; q++) oacc[j][q] = 0.0f;
    float p0 = 0.0f, p1 = 0.0f;

    int st = 0;
    for (int kt = 0; kt < NN / 128; kt++) {
        if (kt + 1 < NN / 128) {
            stage_kv(base, st ^ 1, kt + 1, tid, rowbase, PKh, PKl, Vh, Vl);
            CP_COMMIT();
            CP_WAIT1();
        } else {
            CP_WAIT0();
        }
        __syncthreads();

        const uint32_t oKh = 2 * QSZB + st * QSZB;
        const uint32_t oKl = 4 * QSZB + st * QSZB;
        const uint32_t oVh = 6 * QSZB + st * QSZB;
        const uint32_t oVl = 8 * QSZB + st * QSZB;

        #pragma unroll
        for (int t = 0; t < 8; t++) {
            float sacc[2][4] = {};
            #pragma unroll
            for (int s = 0; s < 4; s++) {
                int r  = t * 16 + (lane & 7) + ((lane >> 4) << 3);
                int kb = s * 16 + (((lane >> 3) & 1) << 3);
                uint32_t so = (uint32_t)(r * QS + kb) * 2;
                uint32_t kh[4], kl[4];
                ldm4(kh, base + oKh + so);
                ldm4(kl, base + oKl + so);
                mma_bf16(sacc[0], qh[s], kh + 0);
                mma_bf16(sacc[0], ql[s], kh + 0);
                mma_bf16(sacc[0], qh[s], kl + 0);
                mma_bf16(sacc[1], qh[s], kh + 2);
                mma_bf16(sacc[1], ql[s], kh + 2);
                mma_bf16(sacc[1], qh[s], kl + 2);
            }
            float w2[2][4];
            #pragma unroll
            for (int f = 0; f < 2; f++)
                #pragma unroll
                for (int q = 0; q < 4; q++) {
                    float x = fmaxf(sacc[f][q], 0.0f);
                    w2[f][q] = x * x;
                }
            p0 += w2[0][0] + w2[0][1] + w2[1][0] + w2[1][1];
            p1 += w2[0][2] + w2[0][3] + w2[1][2] + w2[1][3];
            uint32_t wh[4], wl[4];
            {
                bf16 h0, h1, l0, l1;
                split1(w2[0][0], h0, l0); split1(w2[0][1], h1, l1);
                wh[0] = pack2(h0, h1); wl[0] = pack2(l0, l1);
                split1(w2[0][2], h0, l0); split1(w2[0][3], h1, l1);
                wh[1] = pack2(h0, h1); wl[1] = pack2(l0, l1);
                split1(w2[1][0], h0, l0); split1(w2[1][1], h1, l1);
                wh[2] = pack2(h0, h1); wl[2] = pack2(l0, l1);
                split1(w2[1][2], h0, l0); split1(w2[1][3], h1, l1);
                wh[3] = pack2(h0, h1); wl[3] = pack2(l0, l1);
            }
            #pragma unroll
            for (int n = 0; n < 4; n++) {
                int kk = t * 16 + (lane & 7) + ((lane >> 3) & 1) * 8;
                int nn = n * 16 + (lane >> 4) * 8;
                uint32_t so = (uint32_t)(kk * QS + nn) * 2;
                uint32_t vh[4], vl[4];
                ldm4t(vh, base + oVh + so);
                ldm4t(vl, base + oVl + so);
                mma_bf16(oacc[2*n],   wh, vh + 0);
                mma_bf16(oacc[2*n],   wl, vh + 0);
                mma_bf16(oacc[2*n],   wh, vl + 0);
                mma_bf16(oacc[2*n+1], wh, vh + 2);
                mma_bf16(oacc[2*n+1], wl, vh + 2);
                mma_bf16(oacc[2*n+1], wh, vl + 2);
            }
        }
        __syncthreads();
        st ^= 1;
    }

    p0 += __shfl_xor_sync(0xFFFFFFFFu, p0, 1);
    p0 += __shfl_xor_sync(0xFFFFFFFFu, p0, 2);
    p1 += __shfl_xor_sync(0xFFFFFFFFu, p1, 1);
    p1 += __shfl_xor_sync(0xFFFFFFFFu, p1, 2);
    float rd0 = 1.0f / (p0 + 1.0f);
    float rd1 = 1.0f / (p1 + 1.0f);

    int r0 = q0 + w * 16 + (lane >> 2);
    int r1 = r0 + 8;
    #pragma unroll
    for (int j = 0; j < 8; j++) {
        int d = j * 8 + (lane & 3) * 2;
        size_t i0 = rowbase + (size_t)r0 * DD + d;
        size_t i1 = rowbase + (size_t)r1 * DD + d;
        uint32_t vh0 = *(const uint32_t*)(Vh + i0), vl0 = *(const uint32_t*)(Vl + i0);
        uint32_t vh1 = *(const uint32_t*)(Vh + i1), vl1 = *(const uint32_t*)(Vl + i1);
        float vp00 = __bfloat162float(__ushort_as_bfloat16((unsigned short)(vh0 & 0xFFFF))) +
                     __bfloat162float(__ushort_as_bfloat16((unsigned short)(vl0 & 0xFFFF)));
        float vp01 = __bfloat162float(__ushort_as_bfloat16((unsigned short)(vh0 >> 16))) +
                     __bfloat162float(__ushort_as_bfloat16((unsigned short)(vl0 >> 16)));
        float vp10 = __bfloat162float(__ushort_as_bfloat16((unsigned short)(vh1 & 0xFFFF))) +
                     __bfloat162float(__ushort_as_bfloat16((unsigned short)(vl1 & 0xFFFF)));
        float vp11 = __bfloat162float(__ushort_as_bfloat16((unsigned short)(vh1 >> 16))) +
                     __bfloat162float(__ushort_as_bfloat16((unsigned short)(vl1 >> 16)));
        float m00 = oacc[j][0] * rd0 - vp00;
        float m01 = oacc[j][1] * rd0 - vp01;
        float m10 = oacc[j][2] * rd1 - vp10;
        float m11 = oacc[j][3] * rd1 - vp11;
        h16 h0, h1, l0, l1;
        split1h(m00, h0, l0); split1h(m01, h1, l1);
        *(uint32_t*)(Mh + i0) = pack2h(h0, h1);
        *(uint32_t*)(Ml + i0) = pack2h(l0, l1);
        split1h(m10, h0, l0); split1h(m11, h1, l1);
        *(uint32_t*)(Mh + i1) = pack2h(h0, h1);
        *(uint32_t*)(Ml + i1) = pack2h(l0, l1);
    }
}

// ---------------- LM head: 256x128 tiles, 512 threads, fp16x2 -----------------
__device__ __forceinline__ void stage_lm(
    uint32_t base, int st, int kc, int tid, int m0, int n0,
    const h16* __restrict__ Ah, const h16* __restrict__ Al)
{
    constexpr uint32_t ASZ = 256 * AMS, BSZ = 128 * AMS;
    const uint32_t oAh = 0, oAl = 2 * ASZ * 2, oB = 4 * ASZ * 2;
    #pragma unroll
    for (int it2 = 0; it2 < 2; it2++) {
        int g = tid + 512 * it2;
        int row = g >> 2, c8 = (g & 3) * 8;
        uint32_t so = (uint32_t)(st * ASZ + row * AMS + c8) * 2;
        size_t ga = (size_t)(m0 + row) * DD + kc * 32 + c8;
        cpa16(base + oAh + so, Ah + ga);
        cpa16(base + oAl + so, Al + ga);
    }
    {
        int g = tid;
        int row = g >> 2, c8 = (g & 3) * 8;
        uint32_t so = (uint32_t)(st * BSZ + row * AMS + c8) * 2;
        size_t gb = (size_t)(n0 + row) * DD + kc * 32 + c8;
        cpa16(base + oB + so, g_LMh + gb);
    }
}

__global__ void __launch_bounds__(512)
lm_head_mma(const h16* __restrict__ Ah, const h16* __restrict__ Al,
            float* __restrict__ C)
{
    extern __shared__ __align__(16) h16 dsm[];
    constexpr uint32_t ASZ = 256 * AMS, BSZ = 128 * AMS;
    const uint32_t base = smem_u32(dsm);
    const uint32_t oAh = 0, oAl = 2 * ASZ * 2, oB = 4 * ASZ * 2;
    const int tid = threadIdx.x, lane = tid & 31, wid = tid >> 5;
    const int warp_m = wid >> 1, warp_n = wid & 1;
    const int m0 = blockIdx.y * 256, n0 = blockIdx.x * 128;

    float acc[2][8][4];
    #pragma unroll
    for (int i = 0; i < 2; i++)
        #pragma unroll
        for (int j = 0; j < 8; j++)
            #pragma unroll
            for (int q = 0; q < 4; q++) acc[i][j][q] = 0.0f;

    stage_lm(base, 0, 0, tid, m0, n0, Ah, Al);
    CP_COMMIT();

    int st = 0;
    for (int kc = 0; kc < 16; kc++) {
        if (kc + 1 < 16) {
            stage_lm(base, st ^ 1, kc + 1, tid, m0, n0, Ah, Al);
            CP_COMMIT();
            CP_WAIT1();
        } else {
            CP_WAIT0();
        }
        __syncthreads();

        #pragma unroll
        for (int s = 0; s < 2; s++) {
            uint32_t ah[2][4], al[2][4], bh[8][2];
            #pragma unroll
            for (int i = 0; i < 2; i++) {
                int r  = warp_m * 32 + i * 16 + (lane & 15);
                int kb = s * 16 + ((lane >> 4) << 3);
                uint32_t so = (uint32_t)(st * ASZ + r * AMS + kb) * 2;
                ldm4(ah[i], base + oAh + so);
                ldm4(al[i], base + oAl + so);
            }
            #pragma unroll
            for (int j = 0; j < 4; j++) {
                int r  = warp_n * 64 + j * 16 + (lane & 7) + ((lane >> 4) << 3);
                int kb = s * 16 + (((lane >> 3) & 1) << 3);
                uint32_t so = (uint32_t)(st * BSZ + r * AMS + kb) * 2;
                uint32_t q[4];
                ldm4(q, base + oB + so);
                bh[2*j][0] = q[0]; bh[2*j][1] = q[1];
                bh[2*j+1][0] = q[2]; bh[2*j+1][1] = q[3];
            }
            #pragma unroll
            for (int i = 0; i < 2; i++)
                #pragma unroll
                for (int j = 0; j < 8; j++) {
                    mma_f16(acc[i][j], ah[i], bh[j]);
                    mma_f16(acc[i][j], al[i], bh[j]);
                }
        }
        __syncthreads();
        st ^= 1;
    }

    #pragma unroll
    for (int i = 0; i < 2; i++) {
        int m = m0 + warp_m * 32 + i * 16 + (lane >> 2);
        #pragma unroll
        for (int j = 0; j < 8; j++) {
            int n = n0 + warp_n * 64 + j * 8 + (lane & 3) * 2;
            *(float2*)(C + (size_t)m * VV + n) =
                make_float2(acc[i][j][0], acc[i][j][1]);
            *(float2*)(C + (size_t)(m + 8) * VV + n) =
                make_float2(acc[i][j][2], acc[i][j][3]);
        }
    }
}

// ---------------- init -------------------------------------------------------
__global__ void init_kernel(const int* __restrict__ inputs,
                            const int* __restrict__ carry_inputs,
                            const void* __restrict__ halted,
                            const float* __restrict__ carry_hidden,
                            const float* __restrict__ init_hidden,
                            const float* __restrict__ emb,
                            const float* __restrict__ pos,
                            const float* __restrict__ in_s,
                            const float* __restrict__ in_b)
{
    int r = blockIdx.x;
    int b = r / NN, n = r % NN;
    int t = threadIdx.x;
    bool h = read_halted(halted, b);
    int idx = h ? inputs[r] : carry_inputs[r];
    const float* e = emb + (size_t)idx * DD;
    const float* p = pos + (size_t)n * DD;

    float x0 = e[t]       + p[t];
    float x1 = e[t + 256] + p[t + 256];

    size_t base = (size_t)r * DD;
    g_Q[base + t]       = h ? init_hidden[t]       : carry_hidden[base + t];
    g_Q[base + t + 256] = h ? init_hidden[t + 256] : carry_hidden[base + t + 256];

    __shared__ float s_sum[256], s_sq[256];
    s_sum[t] = x0 + x1;
    s_sq[t]  = x0 * x0 + x1 * x1;
    __syncthreads();
    for (int o = 128; o > 0; o >>= 1) {
        if (t < o) { s_sum[t] += s_sum[t + o]; s_sq[t] += s_sq[t + o]; }
        __syncthreads();
    }
    float mu   = s_sum[0] * (1.0f / DD);
    float var  = s_sq[0] * (1.0f / DD) - mu * mu;
    float rstd = rsqrtf(var + 1e-5f);
    g_X[base + t]       = (x0 - mu) * rstd * in_s[t]       + in_b[t];
    g_X[base + t + 256] = (x1 - mu) * rstd * in_s[t + 256] + in_b[t + 256];
}

// ---------------- LayerNorm (fp32 in; optional fp32 out; fp16 hi/lo out) -----
__global__ void ln_kernel(const float* __restrict__ in, float* __restrict__ outf,
                          h16* __restrict__ outh, h16* __restrict__ outl,
                          const float* __restrict__ s, const float* __restrict__ bia,
                          const float* __restrict__ add)
{
    int r = blockIdx.x;
    int t = threadIdx.x;
    size_t base = (size_t)r * DD;
    float x0 = in[base + t];
    float x1 = in[base + t + 256];

    __shared__ float s_sum[256], s_sq[256];
    s_sum[t] = x0 + x1;
    s_sq[t]  = x0 * x0 + x1 * x1;
    __syncthreads();
    for (int o = 128; o > 0; o >>= 1) {
        if (t < o) { s_sum[t] += s_sum[t + o]; s_sq[t] += s_sq[t + o]; }
        __syncthreads();
    }
    float mu   = s_sum[0] * (1.0f / DD);
    float var  = s_sq[0] * (1.0f / DD) - mu * mu;
    float rstd = rsqrtf(var + 1e-5f);
    float v0 = (x0 - mu) * rstd * s[t]       + bia[t];
    float v1 = (x1 - mu) * rstd * s[t + 256] + bia[t + 256];
    if (add) { v0 += add[base + t]; v1 += add[base + t + 256]; }
    if (outf) { outf[base + t] = v0; outf[base + t + 256] = v1; }
    if (outh) {
        h16 h0, l0, h1, l1;
        split1h(v0, h0, l0); split1h(v1, h1, l1);
        outh[base + t] = h0;       outl[base + t] = l0;
        outh[base + t + 256] = h1; outl[base + t + 256] = l1;
    }
}

// ---------------- depthwise conv k=3 + bias + silu -> fp16 hi/lo --------------
__global__ void conv_kernel(const float* __restrict__ Hf, const float* __restrict__ w,
                            const float* __restrict__ bias,
                            h16* __restrict__ outh, h16* __restrict__ outl)
{
    size_t i = (size_t)blockIdx.x * 256 + threadIdx.x;
    if (i >= (size_t)MROWS * INNER) return;
    size_t row = i / INNER;
    int c = (int)(i % INNER);
    int n = (int)(row % NN);
    const float* wc = w + (size_t)c * CKW;
    float acc = bias[c];
    if (n > 0)      acc += wc[0] * Hf[(row - 1) * INNER + c];
    acc += wc[1] * Hf[row * INNER + c];
    if (n < NN - 1) acc += wc[2] * Hf[(row + 1) * INNER + c];
    float v = siluf(acc);
    h16 h, l;
    split1h(v, h, l);
    outh[i] = h;
    outl[i] = l;
}

// ---------------- halt head --------------------------------------------------
__global__ void halt_kernel(const float* __restrict__ Qn, const float* __restrict__ hw,
                            const float* __restrict__ hb, float* __restrict__ out)
{
    int b = blockIdx.x;
    int t = threadIdx.x;
    __shared__ float md[DD];
    for (int d = t; d < DD; d += 256) {
        float s = 0.0f;
        for (int n = 0; n < NN; n++)
            s += Qn[((size_t)(b * NN + n)) * DD + d];
        md[d] = s * (1.0f / NN);
    }
    __syncthreads();
    __shared__ float r0[256], r1[256];
    float p0 = 0.0f, p1 = 0.0f;
    for (int d = t; d < DD; d += 256) {
        p0 += md[d] * hw[d];
        p1 += md[d] * hw[DD + d];
    }
    r0[t] = p0; r1[t] = p1;
    __syncthreads();
    for (int o = 128; o > 0; o >>= 1) {
        if (t < o) { r0[t] += r0[t + o]; r1[t] += r1[t + o]; }
        __syncthreads();
    }
    if (t == 0) {
        out[b * 2 + 0] = r0[0] + hb[0];
        out[b * 2 + 1] = r1[0] + hb[1];
    }
}

// ---------------- host orchestration -----------------------------------------
static void cvt_h(const float* src, h16* d, size_t n)
{
    int n4 = (int)(n / 4);
    cvt_h_kernel<<<(n4 + 255) / 256, 256>>>(src, d, n4);
}

extern "C" void kernel_launch(void* const* d_in, const int* in_sizes, int n_in,
                              void* d_out, int out_size)
{
    const int*   inputs       = (const int*)d_in[0];
    const float* carry_hidden = (const float*)d_in[2];
    const void*  halted       = d_in[4];
    const int*   carry_inputs = (const int*)d_in[5];
    const float* init_hidden  = (const float*)d_in[7];
    const float* emb          = (const float*)d_in[8];
    const float* pos          = (const float*)d_in[9];
    const float* in_s         = (const float*)d_in[10];
    const float* in_b         = (const float*)d_in[11];
    const float* fin_s        = (const float*)d_in[12];
    const float* fin_b        = (const float*)d_in[13];
    const float* lm_w         = (const float*)d_in[14];
    const float* halt_w       = (const float*)d_in[15];
    const float* halt_b       = (const float*)d_in[16];
    const float* dt           = (const float*)d_in[17];
    const float* W_Q          = (const float*)d_in[18];
    const float* W_K          = (const float*)d_in[19];
    const float* W_V          = (const float*)d_in[20];
    const float* W_O          = (const float*)d_in[21];
    const float* W_up         = (const float*)d_in[22];
    const float* dw_w         = (const float*)d_in[23];
    const float* dw_b         = (const float*)d_in[24];
    const float* W_down       = (const float*)d_in[25];
    const float* n1_s         = (const float*)d_in[26];
    const float* n1_b         = (const float*)d_in[27];
    const float* n2_s         = (const float*)d_in[28];
    const float* n2_b         = (const float*)d_in[29];

    float *X, *Q, *Qi, *Qn, *Hf;
    h16 *Hch, *Hcl, *mbh, *mbl, *Q2h, *Q2l, *Hvh, *Hvl, *Qnh, *Qnl;
    bf16 *PQh, *PQl, *PKh, *PKl, *Vh, *Vl;
    h16 *WQh, *WKh, *WVh, *WOh, *WUh, *WDh, *LMh;
    cudaGetSymbolAddress((void**)&X,   g_X);
    cudaGetSymbolAddress((void**)&Q,   g_Q);
    cudaGetSymbolAddress((void**)&Qi,  g_Qi);
    cudaGetSymbolAddress((void**)&Qn,  g_Qn);
    cudaGetSymbolAddress((void**)&Hf,  g_Hf);
    cudaGetSymbolAddress((void**)&Hch, g_Hch); cudaGetSymbolAddress((void**)&Hcl, g_Hcl);
    cudaGetSymbolAddress((void**)&PQh, g_PQh); cudaGetSymbolAddress((void**)&PQl, g_PQl);
    cudaGetSymbolAddress((void**)&PKh, g_PKh); cudaGetSymbolAddress((void**)&PKl, g_PKl);
    cudaGetSymbolAddress((void**)&Vh,  g_Vh);  cudaGetSymbolAddress((void**)&Vl,  g_Vl);
    cudaGetSymbolAddress((void**)&mbh, g_mbh); cudaGetSymbolAddress((void**)&mbl, g_mbl);
    cudaGetSymbolAddress((void**)&Q2h, g_Q2h); cudaGetSymbolAddress((void**)&Q2l, g_Q2l);
    cudaGetSymbolAddress((void**)&Hvh, g_Hvh); cudaGetSymbolAddress((void**)&Hvl, g_Hvl);
    cudaGetSymbolAddress((void**)&Qnh, g_Qnh); cudaGetSymbolAddress((void**)&Qnl, g_Qnl);
    cudaGetSymbolAddress((void**)&WQh, g_WQh);
    cudaGetSymbolAddress((void**)&WKh, g_WKh);
    cudaGetSymbolAddress((void**)&WVh, g_WVh);
    cudaGetSymbolAddress((void**)&WOh, g_WOh);
    cudaGetSymbolAddress((void**)&WUh, g_WUh);
    cudaGetSymbolAddress((void**)&WDh, g_WDh);
    cudaGetSymbolAddress((void**)&LMh, g_LMh);

    float* out = (float*)d_out;

    cudaFuncSetAttribute(attn_fused, cudaFuncAttributeMaxDynamicSharedMemorySize, ATT_SMEM);
    cudaFuncSetAttribute(mma_proj,   cudaFuncAttributeMaxDynamicSharedMemorySize, SM_G128);
    cudaFuncSetAttribute(mma_up,     cudaFuncAttributeMaxDynamicSharedMemorySize, SM_G128);
    cudaFuncSetAttribute(mma_wo,     cudaFuncAttributeMaxDynamicSharedMemorySize, SM_G64);
    cudaFuncSetAttribute(mma_down,   cudaFuncAttributeMaxDynamicSharedMemorySize, SM_G64);
    cudaFuncSetAttribute(lm_head_mma, cudaFuncAttributeMaxDynamicSharedMemorySize, SM_LM);

    // weight conversion to single fp16 (W_up permuted for fused swiglu)
    cvt_h(W_Q,    WQh, (size_t)KKB * DD * DD);
    cvt_h(W_K,    WKh, (size_t)KKB * DD * DD);
    cvt_h(W_V,    WVh, (size_t)KKB * DD * DD);
    cvt_h(W_O,    WOh, (size_t)KKB * DD * DD);
    {
        int total = KKB * DD * (2 * INNER) / 8;
        cvt_up_kernel<<<(total + 255) / 256, 256>>>(W_up, WUh);
    }
    cvt_h(W_down, WDh, (size_t)KKB * INNER * DD);
    cvt_h(lm_w,   LMh, (size_t)VV * DD);

    init_kernel<<<MROWS, 256>>>(inputs, carry_inputs, halted, carry_hidden,
                                init_hidden, emb, pos, in_s, in_b);

    dim3 gP(DD / 128, MROWS / 128, 3);        // (4, 16, 3)
    dim3 gO64(DD / 64, MROWS / 128);          // (8, 16) = 128 CTAs
    dim3 gUP(2 * INNER / 128, MROWS / 128);   // (24, 16)
    dim3 gAT(NN / 128, BHN);                  // (8, 16)

    for (int it = 0; it < TOTAL_PASSES; it++) {
        int k = it % KKB;

        ln_kernel<<<MROWS, 256>>>(Q, nullptr, Hch, Hcl,
                                  n1_s + k * DD, n1_b + k * DD, X);

        mma_proj<<<gP, 256, SM_G128>>>(Hch, Hcl, k);

        attn_fused<<<gAT, 256, ATT_SMEM>>>(PQh, PQl, PKh, PKl, Vh, Vl, mbh, mbl);

        mma_wo<<<gO64, 256, SM_G64>>>(mbh, mbl, k, Qi, Q, dt);

        ln_kernel<<<MROWS, 256>>>(Qi, nullptr, Q2h, Q2l,
                                  n2_s + k * DD, n2_b + k * DD, nullptr);
        mma_up<<<gUP, 256, SM_G128>>>(Q2h, Q2l, k, Hf);    // fused swiglu
        int tot = MROWS * INNER;
        conv_kernel<<<(tot + 255) / 256, 256>>>(Hf, dw_w + (size_t)k * INNER * CKW,
                                                dw_b + (size_t)k * INNER, Hvh, Hvl);
        mma_down<<<gO64, 256, SM_G64>>>(Hvh, Hvl, k, Q, Qi);
    }

    ln_kernel<<<MROWS, 256>>>(Q, Qn, Qnh, Qnl, fin_s, fin_b, nullptr);
    dim3 gLM(VV / 128, MROWS / 256);          // (250, 8)
    lm_head_mma<<<gLM, 512, SM_LM>>>(Qnh, Qnl, out);
    halt_kernel<<<BB, 256>>>(Qn, halt_w, halt_b, out + (size_t)MROWS * VV);
}